// round 7
// baseline (speedup 1.0000x reference)
#include <cuda_runtime.h>
#include <math.h>
#include <stdint.h>

// ---------------- problem constants ----------------
#define BB 256      // batch
#define TT 128      // timesteps
#define FF 784      // input features
#define HH 1024     // hidden
#define CC 10       // classes
#define M1 (BB*TT)  // 32768 rows for the time-parallel GEMM
#define BN_EPS 1e-3f

// ---------------- scratch (device globals) ----------------
__device__ float g_feat[(size_t)M1 * HH];          // tf32-rounded feat (B,T,H)
__device__ float g_hseq[(size_t)M1 * HH];          // fp32 h (T,B,H) for logits
__device__ float g_ht  [2][(size_t)BB * HH];       // tf32-rounded h ping-pong
__device__ float g_c   [(size_t)BB * HH];
__device__ float g_wfe [(size_t)FF * HH];          // tf32-rounded W_fe
__device__ float g_wg  [(size_t)HH * 4 * HH];      // tf32-rounded kernel
__device__ float g_wrt [(size_t)HH * 4 * HH];      // tf32-rounded rec_kernel
__device__ volatile unsigned g_bar;                // grid barrier counter

// ---------------- helpers ----------------
__device__ __forceinline__ uint32_t f2tf(float f) {
    uint32_t u;
    asm("cvt.rna.tf32.f32 %0, %1;" : "=r"(u) : "f"(f));
    return u;
}

__device__ __forceinline__ void cp16(void* dst, const void* src) {
    uint32_t d = (uint32_t)__cvta_generic_to_shared(dst);
    asm volatile("cp.async.cg.shared.global [%0], [%1], 16;" :: "r"(d), "l"(src));
}
#define CP_COMMIT asm volatile("cp.async.commit_group;")
#define CP_WAITN(n) asm volatile("cp.async.wait_group %0;" :: "n"(n))

__device__ __forceinline__ void mma_tf32(float* d, const uint32_t* a, const uint32_t* b) {
    asm volatile(
        "mma.sync.aligned.m16n8k8.row.col.f32.tf32.tf32.f32 "
        "{%0,%1,%2,%3}, {%4,%5,%6,%7}, {%8,%9}, {%0,%1,%2,%3};"
        : "+f"(d[0]), "+f"(d[1]), "+f"(d[2]), "+f"(d[3])
        : "r"(a[0]), "r"(a[1]), "r"(a[2]), "r"(a[3]),
          "r"(b[0]), "r"(b[1]));
}

__global__ void init_kernel(float* __restrict__ c, int n) {
    int i = blockIdx.x * blockDim.x + threadIdx.x;
    if (i < n) c[i] = 0.0f;
    if (i == 0) g_bar = 0u;
}

// pre-round an fp32 array to tf32 precision (rna), stored as fp32 bits
__global__ void round_tf32_kernel(const float4* __restrict__ in,
                                  float4* __restrict__ out, int n4) {
    int i = blockIdx.x * blockDim.x + threadIdx.x;
    if (i < n4) {
        float4 v = in[i];
        float4 o;
        o.x = __uint_as_float(f2tf(v.x));
        o.y = __uint_as_float(f2tf(v.y));
        o.z = __uint_as_float(f2tf(v.z));
        o.w = __uint_as_float(f2tf(v.w));
        out[i] = o;
    }
}

// ---------------- tf32 tensor-core GEMM (featurizer) -------------------------
// C[M,N] = tanh(BN(tanh(A@B + bias))) stored tf32-rounded.
// B pre-rounded; A raw fp32 (CVTA: fragments converted after LDS).
template<int BM, int BN, int BK, int WM, int WN, bool CVTA>
__global__ void __launch_bounds__((BM/WM)*(BN/WN)*32)
gemm_tf32(const float* __restrict__ A, const float* __restrict__ B,
          float* __restrict__ C, int M, int N, int K,
          const float* __restrict__ p0, const float* __restrict__ p1,
          const float* __restrict__ p2, const float* __restrict__ p3,
          const float* __restrict__ p4)
{
    constexpr int WARPS_N = BN / WN;
    constexpr int THREADS = (BM/WM) * (BN/WN) * 32;
    constexpr int MI = WM / 16;
    constexpr int NI = WN / 8;
    constexpr int KS = BK / 8;
    constexpr int AST = BK + 4;
    constexpr int BST = BN + 8;
    constexpr int AQ = BM * BK / 4;
    constexpr int BQ = BK * BN / 4;

    __shared__ float As[2][BM * AST];
    __shared__ float Bs[2][BK * BST];

    const int tid  = threadIdx.x;
    const int lane = tid & 31;
    const int warp = tid >> 5;
    const int wm   = (warp / WARPS_N) * WM;
    const int wn   = (warp % WARPS_N) * WN;
    const int row0 = blockIdx.y * BM;
    const int col0 = blockIdx.x * BN;

    float acc[MI][NI][4];
#pragma unroll
    for (int mi = 0; mi < MI; mi++)
#pragma unroll
        for (int ni = 0; ni < NI; ni++)
#pragma unroll
            for (int r = 0; r < 4; r++) acc[mi][ni][r] = 0.0f;

    const int KT = K / BK;

#pragma unroll
    for (int q = tid; q < AQ; q += THREADS) {
        int r = q / (BK/4), c = (q % (BK/4)) * 4;
        cp16(&As[0][r * AST + c], A + (size_t)(row0 + r) * K + c);
    }
#pragma unroll
    for (int q = tid; q < BQ; q += THREADS) {
        int r = q / (BN/4), c = (q % (BN/4)) * 4;
        cp16(&Bs[0][r * BST + c], B + (size_t)r * N + col0 + c);
    }
    CP_COMMIT;

#pragma unroll 1
    for (int kt = 0; kt < KT; kt++) {
        const int cur = kt & 1;
        if (kt + 1 < KT) {
            const int k0 = (kt + 1) * BK;
            const int nxt = cur ^ 1;
#pragma unroll
            for (int q = tid; q < AQ; q += THREADS) {
                int r = q / (BK/4), c = (q % (BK/4)) * 4;
                cp16(&As[nxt][r * AST + c], A + (size_t)(row0 + r) * K + k0 + c);
            }
#pragma unroll
            for (int q = tid; q < BQ; q += THREADS) {
                int r = q / (BN/4), c = (q % (BN/4)) * 4;
                cp16(&Bs[nxt][r * BST + c], B + (size_t)(k0 + r) * N + col0 + c);
            }
            CP_COMMIT;
            CP_WAITN(1);
        } else {
            CP_WAITN(0);
        }
        __syncthreads();

#pragma unroll
        for (int ks = 0; ks < KS; ks++) {
            uint32_t afr[MI][4];
            uint32_t bfr[NI][2];
            const int ar = lane >> 2;
            const int ac = ks * 8 + (lane & 3);
#pragma unroll
            for (int mi = 0; mi < MI; mi++) {
                const float* base = &As[cur][(wm + mi * 16 + ar) * AST + ac];
                if (CVTA) {
                    afr[mi][0] = f2tf(base[0]);
                    afr[mi][1] = f2tf(base[8 * AST]);
                    afr[mi][2] = f2tf(base[4]);
                    afr[mi][3] = f2tf(base[8 * AST + 4]);
                } else {
                    afr[mi][0] = __float_as_uint(base[0]);
                    afr[mi][1] = __float_as_uint(base[8 * AST]);
                    afr[mi][2] = __float_as_uint(base[4]);
                    afr[mi][3] = __float_as_uint(base[8 * AST + 4]);
                }
            }
            const int bk = ks * 8 + (lane & 3);
            const int bn = lane >> 2;
#pragma unroll
            for (int ni = 0; ni < NI; ni++) {
                const float* base = &Bs[cur][bk * BST + wn + ni * 8 + bn];
                bfr[ni][0] = __float_as_uint(base[0]);
                bfr[ni][1] = __float_as_uint(base[4 * BST]);
            }
#pragma unroll
            for (int mi = 0; mi < MI; mi++)
#pragma unroll
                for (int ni = 0; ni < NI; ni++)
                    mma_tf32(acc[mi][ni], afr[mi], bfr[ni]);
        }
        __syncthreads();
    }

#pragma unroll
    for (int mi = 0; mi < MI; mi++) {
#pragma unroll
        for (int ni = 0; ni < NI; ni++) {
            const int r0 = row0 + wm + mi * 16 + (lane >> 2);
            const int c0 = col0 + wn + ni * 8 + 2 * (lane & 3);
#pragma unroll
            for (int half = 0; half < 2; half++) {
                const int rr = r0 + half * 8;
#pragma unroll
                for (int e = 0; e < 2; e++) {
                    const int nn = c0 + e;
                    float v = acc[mi][ni][half * 2 + e];
                    v = tanhf(v + p0[nn]);
                    v = (v - p3[nn]) * rsqrtf(p4[nn] + BN_EPS) * p1[nn] + p2[nn];
                    v = tanhf(v);
                    v = __uint_as_float(f2tf(v));   // pre-round for recurrence
                    C[(size_t)rr * N + nn] = v;
                }
            }
        }
    }
}

// ---------------- persistent fused LSTM: (feat_t|h_{t-1}) @ [Wg;Wr] + gates --
// 128 CTAs (jt = blockIdx.x>>2, mt = blockIdx.x&3), 256 threads.
// Per step: K=2048 GEMM (first 1024 from feat_t@Wg, next 1024 from h@Wr),
// 4-stage cp.async pipeline, gate epilogue with bias+peepholes, grid barrier.
#define FBM 64
#define FBK 32
#define FBN 128
#define FAST (FBK + 4)       // 36
#define FBST (FBN + 8)       // 136
#define FEST (FBN + 4)       // 132
#define PSTAGES 4
#define AS_SZ (FBM * FAST)   // 2304 floats
#define BS_SZ (FBK * FBST)   // 4352 floats
#define PSMEM_BYTES ((PSTAGES * (AS_SZ + BS_SZ)) * 4)   // 106496 B

__global__ void __launch_bounds__(256)
lstm_persistent(const float* __restrict__ feat,    // (B,T,H) tf32-rounded
                const float* __restrict__ Wg,      // (HH, 4HH) tf32-rounded
                const float* __restrict__ Wr,      // (HH, 4HH) tf32-rounded
                const float* __restrict__ bias,    // (4HH,)
                float* __restrict__ cst,           // (BB, HH)
                float* __restrict__ hseq,          // (TT, BB, HH) fp32
                float* __restrict__ ht0,           // ping-pong tf32 h buffers
                float* __restrict__ ht1,
                const float* __restrict__ pi, const float* __restrict__ pf,
                const float* __restrict__ po)
{
    extern __shared__ float dsm[];
    float* As = dsm;                          // [PSTAGES][AS_SZ]
    float* Bs = dsm + PSTAGES * AS_SZ;        // [PSTAGES][BS_SZ]
    float* ep = dsm;                          // epilogue alias (33792 B)

    const int tid  = threadIdx.x;
    const int lane = tid & 31;
    const int warp = tid >> 5;
    const int wm   = (warp >> 2) * 32;
    const int wn   = (warp & 3) * 32;
    const int row0 = (blockIdx.x & 3) * FBM;
    const int j0   = (blockIdx.x >> 2) * 32;

    const int j  = tid & 31;
    const int jg = j0 + j;
    const float pij = pi[jg], pfj = pf[jg], poj = po[jg];
    const float bi = bias[jg], bf = bias[HH + jg];
    const float bc = bias[2*HH + jg], bo = bias[3*HH + jg];

    constexpr int AQ = FBM * FBK / 4;   // 512 -> 2/thread
    constexpr int BQ = FBK * FBN / 4;   // 1024 -> 4/thread
    constexpr int KTFULL = 2 * HH / FBK;   // 64
    constexpr int KTHALF = HH / FBK;       // 32

#pragma unroll 1
    for (int t = 0; t < TT; t++) {
        const float* hprev = ((t - 1) & 1) ? ht1 : ht0;
        const int KTl = (t > 0) ? KTFULL : KTHALF;

        float acc[2][4][4];
#pragma unroll
        for (int mi = 0; mi < 2; mi++)
#pragma unroll
            for (int ni = 0; ni < 4; ni++)
#pragma unroll
                for (int r = 0; r < 4; r++) acc[mi][ni][r] = 0.0f;

        // ---- tile loader: kt < KTHALF -> feat/Wg, else -> h/Wr ----
        auto load_tile = [&](int st, int kt) {
#pragma unroll
            for (int qq = tid; qq < AQ; qq += 256) {
                int r = qq >> 3, c = (qq & 7) * 4;
                const float* src;
                if (kt < KTHALF)
                    src = feat + ((size_t)(row0 + r) * TT + t) * HH + kt * FBK + c;
                else
                    src = hprev + (size_t)(row0 + r) * HH + (kt - KTHALF) * FBK + c;
                cp16(&As[st * AS_SZ + r * FAST + c], src);
            }
#pragma unroll
            for (int qq = tid; qq < BQ; qq += 256) {
                int br = qq >> 5, ci = qq & 31;
                int g = ci >> 3, jj = (ci & 7) * 4;
                const float* src;
                if (kt < KTHALF)
                    src = Wg + (size_t)(kt * FBK + br) * (4*HH) + g * HH + j0 + jj;
                else
                    src = Wr + (size_t)((kt - KTHALF) * FBK + br) * (4*HH) + g * HH + j0 + jj;
                cp16(&Bs[st * BS_SZ + br * FBST + g * 32 + jj], src);
            }
        };

        // ---- prologue ----
#pragma unroll
        for (int p = 0; p < PSTAGES - 1; p++) {
            load_tile(p, p);
            CP_COMMIT;
        }

        // ---- main K loop ----
#pragma unroll 1
        for (int kt = 0; kt < KTl; kt++) {
            const int cur = kt % PSTAGES;
            CP_WAITN(PSTAGES - 2);
            __syncthreads();

            if (kt + PSTAGES - 1 < KTl)
                load_tile((kt + PSTAGES - 1) % PSTAGES, kt + PSTAGES - 1);
            CP_COMMIT;

#pragma unroll
            for (int ks = 0; ks < FBK/8; ks++) {
                uint32_t afr[2][4];
                uint32_t bfr[4][2];
                const int ar = lane >> 2;
                const int ac = ks * 8 + (lane & 3);
#pragma unroll
                for (int mi = 0; mi < 2; mi++) {
                    const float* base = &As[cur * AS_SZ + (wm + mi * 16 + ar) * FAST + ac];
                    afr[mi][0] = __float_as_uint(base[0]);
                    afr[mi][1] = __float_as_uint(base[8 * FAST]);
                    afr[mi][2] = __float_as_uint(base[4]);
                    afr[mi][3] = __float_as_uint(base[8 * FAST + 4]);
                }
                const int bk = ks * 8 + (lane & 3);
                const int bn = lane >> 2;
#pragma unroll
                for (int ni = 0; ni < 4; ni++) {
                    const float* base = &Bs[cur * BS_SZ + bk * FBST + wn + ni * 8 + bn];
                    bfr[ni][0] = __float_as_uint(base[0]);
                    bfr[ni][1] = __float_as_uint(base[4 * FBST]);
                }
#pragma unroll
                for (int mi = 0; mi < 2; mi++)
#pragma unroll
                    for (int ni = 0; ni < 4; ni++)
                        mma_tf32(acc[mi][ni], afr[mi], bfr[ni]);
            }
        }
        CP_WAITN(0);
        __syncthreads();

        // ---- dump z accumulators to smem epilogue buffer ----
#pragma unroll
        for (int mi = 0; mi < 2; mi++) {
#pragma unroll
            for (int ni = 0; ni < 4; ni++) {
                const int r0 = wm + mi * 16 + (lane >> 2);
                const int c0 = wn + ni * 8 + 2 * (lane & 3);
#pragma unroll
                for (int half = 0; half < 2; half++) {
                    ep[(r0 + half * 8) * FEST + c0]     = acc[mi][ni][half * 2];
                    ep[(r0 + half * 8) * FEST + c0 + 1] = acc[mi][ni][half * 2 + 1];
                }
            }
        }
        __syncthreads();

        // ---- gates ----
        float* hout  = hseq + (size_t)t * BB * HH;
        float* htcur = (t & 1) ? ht1 : ht0;
#pragma unroll
        for (int s = 0; s < 8; s++) {
            const int m = s * 8 + (tid >> 5);
            const int b = row0 + m;

            float zi = ep[m * FEST +       j] + bi;
            float zf = ep[m * FEST +  32 + j] + bf;
            float zc = ep[m * FEST +  64 + j] + bc;
            float zo = ep[m * FEST +  96 + j] + bo;

            float cc = cst[(size_t)b * HH + jg];
            float ig = 1.0f / (1.0f + expf(-(zi + cc * pij)));
            float fg = 1.0f / (1.0f + expf(-(zf + cc * pfj)));
            float cn = fg * cc + ig * tanhf(zc);
            float og = 1.0f / (1.0f + expf(-(zo + cn * poj)));
            float hn = og * tanhf(cn);

            cst[(size_t)b * HH + jg]   = cn;
            hout[(size_t)b * HH + jg]  = hn;
            htcur[(size_t)b * HH + jg] = __uint_as_float(f2tf(hn));
        }

        // ---- grid barrier ----
        if (t + 1 < TT) {
            __threadfence();
            __syncthreads();
            if (tid == 0) {
                atomicAdd((unsigned*)&g_bar, 1u);
                const unsigned target = 128u * (unsigned)(t + 1);
                while (g_bar < target) { }
                __threadfence();
            }
            __syncthreads();
        }
    }
}

// ---------------- final BN -> tanh -> Dense(H,10) ----------------------------
__global__ void logits_kernel(const float* __restrict__ hseq,
                              const float* __restrict__ g2, const float* __restrict__ b2,
                              const float* __restrict__ m2, const float* __restrict__ v2,
                              const float* __restrict__ Wout, float* __restrict__ out)
{
    int row = blockIdx.x;            // = t*BB + b (hseq is (T,B,H))
    int t = row / BB, b = row % BB;
    int tid = threadIdx.x;

    float a[CC];
#pragma unroll
    for (int c2 = 0; c2 < CC; c2++) a[c2] = 0.0f;

    float4 hv = *(const float4*)(hseq + (size_t)row * HH + tid * 4);
    float4 gv = *(const float4*)(g2 + tid * 4);
    float4 bv = *(const float4*)(b2 + tid * 4);
    float4 mv = *(const float4*)(m2 + tid * 4);
    float4 vv = *(const float4*)(v2 + tid * 4);

    float h4[4] = {hv.x, hv.y, hv.z, hv.w};
    float G4[4] = {gv.x, gv.y, gv.z, gv.w};
    float B4[4] = {bv.x, bv.y, bv.z, bv.w};
    float M4[4] = {mv.x, mv.y, mv.z, mv.w};
    float V4[4] = {vv.x, vv.y, vv.z, vv.w};

#pragma unroll
    for (int s = 0; s < 4; s++) {
        int k = tid * 4 + s;
        float y = tanhf((h4[s] - M4[s]) * rsqrtf(V4[s] + BN_EPS) * G4[s] + B4[s]);
        const float* wr = Wout + (size_t)k * CC;
#pragma unroll
        for (int c2 = 0; c2 < CC; c2++)
            a[c2] = fmaf(y, wr[c2], a[c2]);
    }

#pragma unroll
    for (int off = 16; off > 0; off >>= 1)
#pragma unroll
        for (int c2 = 0; c2 < CC; c2++)
            a[c2] += __shfl_down_sync(0xffffffffu, a[c2], off);

    __shared__ float sacc[CC];
    if (tid < CC) sacc[tid] = 0.0f;
    __syncthreads();
    if ((tid & 31) == 0)
#pragma unroll
        for (int c2 = 0; c2 < CC; c2++) atomicAdd(&sacc[c2], a[c2]);
    __syncthreads();
    if (tid < CC)
        out[((size_t)b * TT + t) * CC + tid] = sacc[tid];
}

// ---------------- launcher ----------------------------------------------------
extern "C" void kernel_launch(void* const* d_in, const int* in_sizes, int n_in,
                              void* d_out, int out_size)
{
    const float* x      = (const float*)d_in[0];
    const float* W_fe   = (const float*)d_in[1];
    const float* b_fe   = (const float*)d_in[2];
    const float* gamma1 = (const float*)d_in[3];
    const float* beta1  = (const float*)d_in[4];
    const float* mean1  = (const float*)d_in[5];
    const float* var1   = (const float*)d_in[6];
    const float* Wg     = (const float*)d_in[7];
    const float* Wr     = (const float*)d_in[8];
    const float* bias   = (const float*)d_in[9];
    const float* pi     = (const float*)d_in[10];
    const float* pf     = (const float*)d_in[11];
    const float* po     = (const float*)d_in[12];
    const float* gamma2 = (const float*)d_in[13];
    const float* beta2  = (const float*)d_in[14];
    const float* mean2  = (const float*)d_in[15];
    const float* var2   = (const float*)d_in[16];
    const float* W_out  = (const float*)d_in[17];
    float* out = (float*)d_out;

    float *feat, *hseq, *cbuf, *wfe, *wg, *wrt, *ht;
    cudaGetSymbolAddress((void**)&feat, g_feat);
    cudaGetSymbolAddress((void**)&hseq, g_hseq);
    cudaGetSymbolAddress((void**)&cbuf, g_c);
    cudaGetSymbolAddress((void**)&wfe,  g_wfe);
    cudaGetSymbolAddress((void**)&wg,   g_wg);
    cudaGetSymbolAddress((void**)&wrt,  g_wrt);
    cudaGetSymbolAddress((void**)&ht,   g_ht);
    float* ht0 = ht;
    float* ht1 = ht + (size_t)BB * HH;

    cudaFuncSetAttribute(lstm_persistent,
                         cudaFuncAttributeMaxDynamicSharedMemorySize, PSMEM_BYTES);

    // init cell state + barrier
    init_kernel<<<(BB*HH + 255)/256, 256>>>(cbuf, BB*HH);

    // pre-round weights to tf32 (rna), stored as fp32
    {
        int n;
        n = FF*HH/4;      round_tf32_kernel<<<(n+255)/256,256>>>((const float4*)W_fe,(float4*)wfe, n);
        n = HH*4*HH/4;    round_tf32_kernel<<<(n+255)/256,256>>>((const float4*)Wg,  (float4*)wg,  n);
        n = HH*4*HH/4;    round_tf32_kernel<<<(n+255)/256,256>>>((const float4*)Wr,  (float4*)wrt, n);
    }

    // 1) feat = tanh(BN(tanh(x @ W_fe + b_fe)))   [32768 x 1024, K=784]
    //    A = raw x (fragments cvt'd in-kernel), B = pre-rounded W_fe
    {
        dim3 grid(HH/128, M1/128);
        gemm_tf32<128,128,16,32,64,true><<<grid, 256>>>(
            x, wfe, feat, M1, HH, FF, b_fe, gamma1, beta1, mean1, var1);
    }

    // 2) fused recurrence: z_t = [feat_t | h_{t-1}] @ [Wg; Wr] + bias -> gates
    lstm_persistent<<<128, 256, PSMEM_BYTES>>>(feat, wg, wrt, bias, cbuf, hseq,
                                               ht0, ht1, pi, pf, po);

    // 3) out = tanh(BN(hseq)) @ W_out             [32768 x 10]
    logits_kernel<<<M1, 256>>>(hseq, gamma2, beta2, mean2, var2, W_out, out);
}

// round 8
// speedup vs baseline: 1.0439x; 1.0439x over previous
#include <cuda_runtime.h>
#include <math.h>
#include <stdint.h>

// ---------------- problem constants ----------------
#define BB 256      // batch
#define TT 128      // timesteps
#define FF 784      // input features
#define HH 1024     // hidden
#define CC 10       // classes
#define M1 (BB*TT)  // 32768 rows for the time-parallel GEMMs
#define BN_EPS 1e-3f

// ---------------- scratch (device globals) ----------------
__device__ float g_feat[(size_t)M1 * HH];          // tf32-rounded feat
__device__ float g_zx  [(size_t)M1 * 4 * HH];      // fp32 Zx (+bias)
__device__ float g_hseq[(size_t)M1 * HH];          // fp32 h (T,B,H) for logits
__device__ float g_ht  [2][(size_t)BB * HH];       // tf32-rounded h ping-pong
__device__ float g_c   [(size_t)BB * HH];
__device__ float g_wfe [(size_t)FF * HH];          // tf32-rounded W_fe
__device__ float g_wg  [(size_t)HH * 4 * HH];      // tf32-rounded kernel
__device__ float g_wrt [(size_t)HH * 4 * HH];      // tf32-rounded rec_kernel
__device__ volatile unsigned g_bar;                // grid barrier counter

// ---------------- helpers ----------------
__device__ __forceinline__ uint32_t f2tf(float f) {
    uint32_t u;
    asm("cvt.rna.tf32.f32 %0, %1;" : "=r"(u) : "f"(f));
    return u;
}

__device__ __forceinline__ void cp16(void* dst, const void* src) {
    uint32_t d = (uint32_t)__cvta_generic_to_shared(dst);
    asm volatile("cp.async.cg.shared.global [%0], [%1], 16;" :: "r"(d), "l"(src));
}
#define CP_COMMIT asm volatile("cp.async.commit_group;")
#define CP_WAITN(n) asm volatile("cp.async.wait_group %0;" :: "n"(n))

__device__ __forceinline__ void mma_tf32(float* d, const uint32_t* a, const uint32_t* b) {
    asm volatile(
        "mma.sync.aligned.m16n8k8.row.col.f32.tf32.tf32.f32 "
        "{%0,%1,%2,%3}, {%4,%5,%6,%7}, {%8,%9}, {%0,%1,%2,%3};"
        : "+f"(d[0]), "+f"(d[1]), "+f"(d[2]), "+f"(d[3])
        : "r"(a[0]), "r"(a[1]), "r"(a[2]), "r"(a[3]),
          "r"(b[0]), "r"(b[1]));
}

__global__ void init_kernel(float* __restrict__ c, int n) {
    int i = blockIdx.x * blockDim.x + threadIdx.x;
    if (i < n) c[i] = 0.0f;
    if (i == 0) g_bar = 0u;
}

// pre-round an fp32 array to tf32 precision (rna), stored as fp32 bits
__global__ void round_tf32_kernel(const float4* __restrict__ in,
                                  float4* __restrict__ out, int n4) {
    int i = blockIdx.x * blockDim.x + threadIdx.x;
    if (i < n4) {
        float4 v = in[i];
        float4 o;
        o.x = __uint_as_float(f2tf(v.x));
        o.y = __uint_as_float(f2tf(v.y));
        o.z = __uint_as_float(f2tf(v.z));
        o.w = __uint_as_float(f2tf(v.w));
        out[i] = o;
    }
}

// ---------------- tf32 tensor-core GEMM (time-parallel GEMMs) ----------------
// C[M,N] = epilogue(A[M,K] @ B[K,N]); B pre-rounded.
// EPI 1: feat epilogue (tanh,BN,tanh), output stored tf32-rounded
// EPI 2: +bias, output fp32
// CVTA: convert A fragments after LDS (A raw fp32)
template<int BM, int BN, int BK, int WM, int WN, int EPI, bool CVTA>
__global__ void __launch_bounds__((BM/WM)*(BN/WN)*32)
gemm_tf32(const float* __restrict__ A, const float* __restrict__ B,
          float* __restrict__ C, int M, int N, int K,
          const float* __restrict__ p0, const float* __restrict__ p1,
          const float* __restrict__ p2, const float* __restrict__ p3,
          const float* __restrict__ p4)
{
    constexpr int WARPS_N = BN / WN;
    constexpr int THREADS = (BM/WM) * (BN/WN) * 32;
    constexpr int MI = WM / 16;
    constexpr int NI = WN / 8;
    constexpr int KS = BK / 8;
    constexpr int AST = BK + 4;
    constexpr int BST = BN + 8;
    constexpr int AQ = BM * BK / 4;
    constexpr int BQ = BK * BN / 4;

    __shared__ float As[2][BM * AST];
    __shared__ float Bs[2][BK * BST];

    const int tid  = threadIdx.x;
    const int lane = tid & 31;
    const int warp = tid >> 5;
    const int wm   = (warp / WARPS_N) * WM;
    const int wn   = (warp % WARPS_N) * WN;
    const int row0 = blockIdx.y * BM;
    const int col0 = blockIdx.x * BN;

    float acc[MI][NI][4];
#pragma unroll
    for (int mi = 0; mi < MI; mi++)
#pragma unroll
        for (int ni = 0; ni < NI; ni++)
#pragma unroll
            for (int r = 0; r < 4; r++) acc[mi][ni][r] = 0.0f;

    const int KT = K / BK;

#pragma unroll
    for (int q = tid; q < AQ; q += THREADS) {
        int r = q / (BK/4), c = (q % (BK/4)) * 4;
        cp16(&As[0][r * AST + c], A + (size_t)(row0 + r) * K + c);
    }
#pragma unroll
    for (int q = tid; q < BQ; q += THREADS) {
        int r = q / (BN/4), c = (q % (BN/4)) * 4;
        cp16(&Bs[0][r * BST + c], B + (size_t)r * N + col0 + c);
    }
    CP_COMMIT;

#pragma unroll 1
    for (int kt = 0; kt < KT; kt++) {
        const int cur = kt & 1;
        if (kt + 1 < KT) {
            const int k0 = (kt + 1) * BK;
            const int nxt = cur ^ 1;
#pragma unroll
            for (int q = tid; q < AQ; q += THREADS) {
                int r = q / (BK/4), c = (q % (BK/4)) * 4;
                cp16(&As[nxt][r * AST + c], A + (size_t)(row0 + r) * K + k0 + c);
            }
#pragma unroll
            for (int q = tid; q < BQ; q += THREADS) {
                int r = q / (BN/4), c = (q % (BN/4)) * 4;
                cp16(&Bs[nxt][r * BST + c], B + (size_t)(k0 + r) * N + col0 + c);
            }
            CP_COMMIT;
            CP_WAITN(1);
        } else {
            CP_WAITN(0);
        }
        __syncthreads();

#pragma unroll
        for (int ks = 0; ks < KS; ks++) {
            uint32_t afr[MI][4];
            uint32_t bfr[NI][2];
            const int ar = lane >> 2;
            const int ac = ks * 8 + (lane & 3);
#pragma unroll
            for (int mi = 0; mi < MI; mi++) {
                const float* base = &As[cur][(wm + mi * 16 + ar) * AST + ac];
                if (CVTA) {
                    afr[mi][0] = f2tf(base[0]);
                    afr[mi][1] = f2tf(base[8 * AST]);
                    afr[mi][2] = f2tf(base[4]);
                    afr[mi][3] = f2tf(base[8 * AST + 4]);
                } else {
                    afr[mi][0] = __float_as_uint(base[0]);
                    afr[mi][1] = __float_as_uint(base[8 * AST]);
                    afr[mi][2] = __float_as_uint(base[4]);
                    afr[mi][3] = __float_as_uint(base[8 * AST + 4]);
                }
            }
            const int bk = ks * 8 + (lane & 3);
            const int bn = lane >> 2;
#pragma unroll
            for (int ni = 0; ni < NI; ni++) {
                const float* base = &Bs[cur][bk * BST + wn + ni * 8 + bn];
                bfr[ni][0] = __float_as_uint(base[0]);
                bfr[ni][1] = __float_as_uint(base[4 * BST]);
            }
#pragma unroll
            for (int mi = 0; mi < MI; mi++)
#pragma unroll
                for (int ni = 0; ni < NI; ni++)
                    mma_tf32(acc[mi][ni], afr[mi], bfr[ni]);
        }
        __syncthreads();
    }

#pragma unroll
    for (int mi = 0; mi < MI; mi++) {
#pragma unroll
        for (int ni = 0; ni < NI; ni++) {
            const int r0 = row0 + wm + mi * 16 + (lane >> 2);
            const int c0 = col0 + wn + ni * 8 + 2 * (lane & 3);
#pragma unroll
            for (int half = 0; half < 2; half++) {
                const int rr = r0 + half * 8;
#pragma unroll
                for (int e = 0; e < 2; e++) {
                    const int nn = c0 + e;
                    float v = acc[mi][ni][half * 2 + e];
                    if (EPI == 1) {
                        v = tanhf(v + p0[nn]);
                        v = (v - p3[nn]) * rsqrtf(p4[nn] + BN_EPS) * p1[nn] + p2[nn];
                        v = tanhf(v);
                        v = __uint_as_float(f2tf(v));   // pre-round for GEMM2
                    } else if (EPI == 2) {
                        v += p0[nn];
                    }
                    C[(size_t)rr * N + nn] = v;
                }
            }
        }
    }
}

// ---------------- persistent LSTM recurrence ---------------------------------
// 128 CTAs x 512 threads (16 warps: 4 warp-rows x 4 warp-cols; WM=16, WN=32).
// CTA (jt = blockIdx.x>>2, mt = blockIdx.x&3): rows [mt*64, +64), j-cols
// [jt*32, +32) across all 4 gates. Per step: 2-stage FBK=64 cp.async tf32
// GEMM Zh = h_{t-1} @ Wr (KT=16 iterations), gate epilogue, grid barrier.
#define FBM 64
#define FBK 64
#define FBN 128
#define FAST (FBK + 4)       // 68
#define FBST (FBN + 8)       // 136
#define FEST (FBN + 4)       // 132
#define AS_SZ (FBM * FAST)   // 4352 floats
#define BS_SZ (FBK * FBST)   // 8704 floats
#define PSMEM_BYTES (2 * (AS_SZ + BS_SZ) * 4)   // 104448 B

__global__ void __launch_bounds__(512)
lstm_persistent(const float* __restrict__ Wr,      // tf32-rounded (HH, 4HH)
                const float* __restrict__ Zx,      // (BB*TT, 4HH), bias included
                float* __restrict__ cst,           // (BB, HH)
                float* __restrict__ hseq,          // (TT, BB, HH) fp32
                float* __restrict__ ht0,           // ping-pong tf32 h buffers
                float* __restrict__ ht1,
                const float* __restrict__ pi, const float* __restrict__ pf,
                const float* __restrict__ po)
{
    extern __shared__ float dsm[];
    float* As = dsm;                    // [2][AS_SZ]
    float* Bs = dsm + 2 * AS_SZ;        // [2][BS_SZ]
    float* ep = dsm;                    // epilogue alias (33792 B)

    const int tid  = threadIdx.x;
    const int lane = tid & 31;
    const int warp = tid >> 5;          // 0..15
    const int wm   = (warp >> 2) * 16;  // warp row: 0,16,32,48
    const int wn   = (warp & 3) * 32;   // warp col: one gate slab
    const int row0 = (blockIdx.x & 3) * FBM;
    const int j0   = (blockIdx.x >> 2) * 32;

    const int j  = tid & 31;
    const int jg = j0 + j;
    const float pij = pi[jg], pfj = pf[jg], poj = po[jg];

    constexpr int AQ = FBM * FBK / 4;   // 1024 -> 2/thread
    constexpr int BQ = FBK * FBN / 4;   // 2048 -> 4/thread
    constexpr int KT = HH / FBK;        // 16

#pragma unroll 1
    for (int t = 0; t < TT; t++) {
        float acc[4][4];                // NI=4 gate slabs x 4 accum regs
#pragma unroll
        for (int ni = 0; ni < 4; ni++)
#pragma unroll
            for (int r = 0; r < 4; r++) acc[ni][r] = 0.0f;

        if (t > 0) {
            const float* hprev = ((t - 1) & 1) ? ht1 : ht0;

            // prologue: stage tile 0
#pragma unroll
            for (int qq = tid; qq < AQ; qq += 512) {
                int r = qq >> 4, c = (qq & 15) * 4;
                cp16(&As[r * FAST + c], hprev + (size_t)(row0 + r) * HH + c);
            }
#pragma unroll
            for (int qq = tid; qq < BQ; qq += 512) {
                int br = qq >> 5, ci = qq & 31;
                int g = ci >> 3, jj = (ci & 7) * 4;
                cp16(&Bs[br * FBST + g * 32 + jj],
                     Wr + (size_t)br * (4*HH) + g * HH + j0 + jj);
            }
            CP_COMMIT;

#pragma unroll 1
            for (int kt = 0; kt < KT; kt++) {
                const int cur = kt & 1;
                if (kt + 1 < KT) {
                    const int nxt = cur ^ 1;
                    const int k0 = (kt + 1) * FBK;
#pragma unroll
                    for (int qq = tid; qq < AQ; qq += 512) {
                        int r = qq >> 4, c = (qq & 15) * 4;
                        cp16(&As[nxt * AS_SZ + r * FAST + c],
                             hprev + (size_t)(row0 + r) * HH + k0 + c);
                    }
#pragma unroll
                    for (int qq = tid; qq < BQ; qq += 512) {
                        int br = qq >> 5, ci = qq & 31;
                        int g = ci >> 3, jj = (ci & 7) * 4;
                        cp16(&Bs[nxt * BS_SZ + br * FBST + g * 32 + jj],
                             Wr + (size_t)(k0 + br) * (4*HH) + g * HH + j0 + jj);
                    }
                    CP_COMMIT;
                    CP_WAITN(1);
                } else {
                    CP_WAITN(0);
                }
                __syncthreads();

#pragma unroll
                for (int ks = 0; ks < FBK/8; ks++) {
                    uint32_t afr[4];
                    uint32_t bfr[4][2];
                    const int ar = lane >> 2;
                    const int ac = ks * 8 + (lane & 3);
                    {
                        const float* base = &As[cur * AS_SZ + (wm + ar) * FAST + ac];
                        afr[0] = __float_as_uint(base[0]);
                        afr[1] = __float_as_uint(base[8 * FAST]);
                        afr[2] = __float_as_uint(base[4]);
                        afr[3] = __float_as_uint(base[8 * FAST + 4]);
                    }
                    const int bk = ks * 8 + (lane & 3);
                    const int bn = lane >> 2;
#pragma unroll
                    for (int ni = 0; ni < 4; ni++) {
                        const float* base = &Bs[cur * BS_SZ + bk * FBST + wn + ni * 8 + bn];
                        bfr[ni][0] = __float_as_uint(base[0]);
                        bfr[ni][1] = __float_as_uint(base[4 * FBST]);
                    }
#pragma unroll
                    for (int ni = 0; ni < 4; ni++)
                        mma_tf32(acc[ni], afr, bfr[ni]);
                }
                __syncthreads();
            }
        } else {
            __syncthreads();
        }

        // ---- dump Zh accumulators to smem epilogue buffer ----
#pragma unroll
        for (int ni = 0; ni < 4; ni++) {
            const int r0 = wm + (lane >> 2);
            const int c0 = wn + ni * 8 + 2 * (lane & 3);
#pragma unroll
            for (int half = 0; half < 2; half++) {
                ep[(r0 + half * 8) * FEST + c0]     = acc[ni][half * 2];
                ep[(r0 + half * 8) * FEST + c0 + 1] = acc[ni][half * 2 + 1];
            }
        }
        __syncthreads();

        // ---- gates: each thread handles 4 (m, j) pairs ----
        float* hout  = hseq + (size_t)t * BB * HH;
        float* htcur = (t & 1) ? ht1 : ht0;
#pragma unroll
        for (int s = 0; s < 4; s++) {
            const int m = s * 16 + (tid >> 5);   // 0..63
            const int b = row0 + m;
            const size_t zr = ((size_t)b * TT + t) * (4 * HH);

            float zi = ep[m * FEST +       j] + Zx[zr + 0*HH + jg];
            float zf = ep[m * FEST +  32 + j] + Zx[zr + 1*HH + jg];
            float zc = ep[m * FEST +  64 + j] + Zx[zr + 2*HH + jg];
            float zo = ep[m * FEST +  96 + j] + Zx[zr + 3*HH + jg];

            float cc = cst[(size_t)b * HH + jg];
            float ig = 1.0f / (1.0f + expf(-(zi + cc * pij)));
            float fg = 1.0f / (1.0f + expf(-(zf + cc * pfj)));
            float cn = fg * cc + ig * tanhf(zc);
            float og = 1.0f / (1.0f + expf(-(zo + cn * poj)));
            float hn = og * tanhf(cn);

            cst[(size_t)b * HH + jg]   = cn;
            hout[(size_t)b * HH + jg]  = hn;
            htcur[(size_t)b * HH + jg] = __uint_as_float(f2tf(hn));
        }

        // ---- grid barrier ----
        if (t + 1 < TT) {
            __threadfence();
            __syncthreads();
            if (tid == 0) {
                atomicAdd((unsigned*)&g_bar, 1u);
                const unsigned target = 128u * (unsigned)(t + 1);
                while (g_bar < target) { }
                __threadfence();
            }
            __syncthreads();
        }
    }
}

// ---------------- final BN -> tanh -> Dense(H,10) ----------------------------
__global__ void logits_kernel(const float* __restrict__ hseq,
                              const float* __restrict__ g2, const float* __restrict__ b2,
                              const float* __restrict__ m2, const float* __restrict__ v2,
                              const float* __restrict__ Wout, float* __restrict__ out)
{
    int row = blockIdx.x;            // = t*BB + b (hseq is (T,B,H))
    int t = row / BB, b = row % BB;
    int tid = threadIdx.x;

    float a[CC];
#pragma unroll
    for (int c2 = 0; c2 < CC; c2++) a[c2] = 0.0f;

    float4 hv = *(const float4*)(hseq + (size_t)row * HH + tid * 4);
    float4 gv = *(const float4*)(g2 + tid * 4);
    float4 bv = *(const float4*)(b2 + tid * 4);
    float4 mv = *(const float4*)(m2 + tid * 4);
    float4 vv = *(const float4*)(v2 + tid * 4);

    float h4[4] = {hv.x, hv.y, hv.z, hv.w};
    float G4[4] = {gv.x, gv.y, gv.z, gv.w};
    float B4[4] = {bv.x, bv.y, bv.z, bv.w};
    float M4[4] = {mv.x, mv.y, mv.z, mv.w};
    float V4[4] = {vv.x, vv.y, vv.z, vv.w};

#pragma unroll
    for (int s = 0; s < 4; s++) {
        int k = tid * 4 + s;
        float y = tanhf((h4[s] - M4[s]) * rsqrtf(V4[s] + BN_EPS) * G4[s] + B4[s]);
        const float* wr = Wout + (size_t)k * CC;
#pragma unroll
        for (int c2 = 0; c2 < CC; c2++)
            a[c2] = fmaf(y, wr[c2], a[c2]);
    }

#pragma unroll
    for (int off = 16; off > 0; off >>= 1)
#pragma unroll
        for (int c2 = 0; c2 < CC; c2++)
            a[c2] += __shfl_down_sync(0xffffffffu, a[c2], off);

    __shared__ float sacc[CC];
    if (tid < CC) sacc[tid] = 0.0f;
    __syncthreads();
    if ((tid & 31) == 0)
#pragma unroll
        for (int c2 = 0; c2 < CC; c2++) atomicAdd(&sacc[c2], a[c2]);
    __syncthreads();
    if (tid < CC)
        out[((size_t)b * TT + t) * CC + tid] = sacc[tid];
}

// ---------------- launcher ----------------------------------------------------
extern "C" void kernel_launch(void* const* d_in, const int* in_sizes, int n_in,
                              void* d_out, int out_size)
{
    const float* x      = (const float*)d_in[0];
    const float* W_fe   = (const float*)d_in[1];
    const float* b_fe   = (const float*)d_in[2];
    const float* gamma1 = (const float*)d_in[3];
    const float* beta1  = (const float*)d_in[4];
    const float* mean1  = (const float*)d_in[5];
    const float* var1   = (const float*)d_in[6];
    const float* Wg     = (const float*)d_in[7];
    const float* Wr     = (const float*)d_in[8];
    const float* bias   = (const float*)d_in[9];
    const float* pi     = (const float*)d_in[10];
    const float* pf     = (const float*)d_in[11];
    const float* po     = (const float*)d_in[12];
    const float* gamma2 = (const float*)d_in[13];
    const float* beta2  = (const float*)d_in[14];
    const float* mean2  = (const float*)d_in[15];
    const float* var2   = (const float*)d_in[16];
    const float* W_out  = (const float*)d_in[17];
    float* out = (float*)d_out;

    float *feat, *zx, *hseq, *cbuf, *wfe, *wg, *wrt, *ht;
    cudaGetSymbolAddress((void**)&feat, g_feat);
    cudaGetSymbolAddress((void**)&zx,   g_zx);
    cudaGetSymbolAddress((void**)&hseq, g_hseq);
    cudaGetSymbolAddress((void**)&cbuf, g_c);
    cudaGetSymbolAddress((void**)&wfe,  g_wfe);
    cudaGetSymbolAddress((void**)&wg,   g_wg);
    cudaGetSymbolAddress((void**)&wrt,  g_wrt);
    cudaGetSymbolAddress((void**)&ht,   g_ht);
    float* ht0 = ht;
    float* ht1 = ht + (size_t)BB * HH;

    cudaFuncSetAttribute(lstm_persistent,
                         cudaFuncAttributeMaxDynamicSharedMemorySize, PSMEM_BYTES);

    // init cell state + barrier
    init_kernel<<<(BB*HH + 255)/256, 256>>>(cbuf, BB*HH);

    // pre-round weights to tf32 (rna), stored as fp32
    {
        int n;
        n = FF*HH/4;      round_tf32_kernel<<<(n+255)/256,256>>>((const float4*)W_fe,(float4*)wfe, n);
        n = HH*4*HH/4;    round_tf32_kernel<<<(n+255)/256,256>>>((const float4*)Wg,  (float4*)wg,  n);
        n = HH*4*HH/4;    round_tf32_kernel<<<(n+255)/256,256>>>((const float4*)Wr,  (float4*)wrt, n);
    }

    // 1) feat = tanh(BN(tanh(x @ W_fe + b_fe)))   [32768 x 1024, K=784]
    {
        dim3 grid(HH/128, M1/128);
        gemm_tf32<128,128,16,32,64,1,true><<<grid, 256>>>(
            x, wfe, feat, M1, HH, FF, b_fe, gamma1, beta1, mean1, var1);
    }
    // 2) Zx = feat @ kernel + bias                [32768 x 4096, K=1024]
    {
        dim3 grid(4*HH/128, M1/128);
        gemm_tf32<128,128,16,32,64,2,false><<<grid, 256>>>(
            feat, wg, zx, M1, 4*HH, HH, bias, nullptr, nullptr, nullptr, nullptr);
    }
    // 3) recurrence: persistent kernel, grid barrier per step
    lstm_persistent<<<128, 512, PSMEM_BYTES>>>(wrt, zx, cbuf, hseq, ht0, ht1,
                                               pi, pf, po);

    // 4) out = tanh(BN(hseq)) @ W_out             [32768 x 10]
    logits_kernel<<<M1, 256>>>(hseq, gamma2, beta2, mean2, var2, W_out, out);
}

// round 9
// speedup vs baseline: 1.0578x; 1.0133x over previous
#include <cuda_runtime.h>
#include <math.h>
#include <stdint.h>

// ---------------- problem constants ----------------
#define BB 256
#define TT 128
#define FF 784
#define HH 1024
#define CC 10
#define M1 (BB*TT)
#define BN_EPS 1e-3f

// ---------------- scratch (device globals) ----------------
__device__ float g_feat[(size_t)M1 * HH];          // tf32-rounded feat
__device__ float g_zx  [(size_t)M1 * 4 * HH];      // fp32 Zx (+bias)
__device__ float g_hseq[(size_t)M1 * HH];          // fp32 h (T,B,H)
__device__ float g_ht  [2][(size_t)BB * HH];       // tf32-rounded h ping-pong
__device__ float g_wfe [(size_t)FF * HH];
__device__ float g_wg  [(size_t)HH * 4 * HH];
__device__ float g_wrt [(size_t)HH * 4 * HH];
__device__ volatile unsigned g_bar;

// ---------------- helpers ----------------
__device__ __forceinline__ uint32_t f2tf(float f) {
    uint32_t u;
    asm("cvt.rna.tf32.f32 %0, %1;" : "=r"(u) : "f"(f));
    return u;
}
__device__ __forceinline__ void cp16(void* dst, const void* src) {
    uint32_t d = (uint32_t)__cvta_generic_to_shared(dst);
    asm volatile("cp.async.cg.shared.global [%0], [%1], 16;" :: "r"(d), "l"(src));
}
#define CP_COMMIT asm volatile("cp.async.commit_group;")
#define CP_WAITN(n) asm volatile("cp.async.wait_group %0;" :: "n"(n))

__device__ __forceinline__ void mma_tf32(float* d, const uint32_t* a, const uint32_t* b) {
    asm volatile(
        "mma.sync.aligned.m16n8k8.row.col.f32.tf32.tf32.f32 "
        "{%0,%1,%2,%3}, {%4,%5,%6,%7}, {%8,%9}, {%0,%1,%2,%3};"
        : "+f"(d[0]), "+f"(d[1]), "+f"(d[2]), "+f"(d[3])
        : "r"(a[0]), "r"(a[1]), "r"(a[2]), "r"(a[3]),
          "r"(b[0]), "r"(b[1]));
}

__global__ void init_kernel() {
    if (threadIdx.x == 0 && blockIdx.x == 0) g_bar = 0u;
}

__global__ void round_tf32_kernel(const float4* __restrict__ in,
                                  float4* __restrict__ out, int n4) {
    int i = blockIdx.x * blockDim.x + threadIdx.x;
    if (i < n4) {
        float4 v = in[i];
        float4 o;
        o.x = __uint_as_float(f2tf(v.x));
        o.y = __uint_as_float(f2tf(v.y));
        o.z = __uint_as_float(f2tf(v.z));
        o.w = __uint_as_float(f2tf(v.w));
        out[i] = o;
    }
}

// ---------------- tf32 tensor-core GEMM (time-parallel) ----------------------
// BM=256, BN=128, 512 threads (16 warps, WM=64, WN=32). Dynamic smem, 2-stage.
// EPI 1: tanh,BN,tanh epilogue, output tf32-rounded.  EPI 2: +bias fp32.
// CVTA: A fragments converted to tf32 after LDS (A raw fp32).
template<int BM, int BN, int BK, int WM, int WN, int EPI, bool CVTA>
__global__ void __launch_bounds__((BM/WM)*(BN/WN)*32)
gemm_tf32(const float* __restrict__ A, const float* __restrict__ B,
          float* __restrict__ C, int M, int N, int K,
          const float* __restrict__ p0, const float* __restrict__ p1,
          const float* __restrict__ p2, const float* __restrict__ p3,
          const float* __restrict__ p4)
{
    constexpr int WARPS_N = BN / WN;
    constexpr int THREADS = (BM/WM) * (BN/WN) * 32;
    constexpr int MI = WM / 16;
    constexpr int NI = WN / 8;
    constexpr int KS = BK / 8;
    constexpr int AST = BK + 4;
    constexpr int BST = BN + 8;
    constexpr int AQ = BM * BK / 4;
    constexpr int BQ = BK * BN / 4;
    constexpr int ASZ = BM * AST;
    constexpr int BSZ = BK * BST;

    extern __shared__ float sm[];
    float* As = sm;                 // [2][ASZ]
    float* Bs = sm + 2 * ASZ;       // [2][BSZ]

    const int tid  = threadIdx.x;
    const int lane = tid & 31;
    const int warp = tid >> 5;
    const int wm   = (warp / WARPS_N) * WM;
    const int wn   = (warp % WARPS_N) * WN;
    const int row0 = blockIdx.y * BM;
    const int col0 = blockIdx.x * BN;

    float acc[MI][NI][4];
#pragma unroll
    for (int mi = 0; mi < MI; mi++)
#pragma unroll
        for (int ni = 0; ni < NI; ni++)
#pragma unroll
            for (int r = 0; r < 4; r++) acc[mi][ni][r] = 0.0f;

    const int KT = K / BK;

#pragma unroll
    for (int q = tid; q < AQ; q += THREADS) {
        int r = q / (BK/4), c = (q % (BK/4)) * 4;
        cp16(&As[r * AST + c], A + (size_t)(row0 + r) * K + c);
    }
#pragma unroll
    for (int q = tid; q < BQ; q += THREADS) {
        int r = q / (BN/4), c = (q % (BN/4)) * 4;
        cp16(&Bs[r * BST + c], B + (size_t)r * N + col0 + c);
    }
    CP_COMMIT;

#pragma unroll 1
    for (int kt = 0; kt < KT; kt++) {
        const int cur = kt & 1;
        if (kt + 1 < KT) {
            const int k0 = (kt + 1) * BK;
            const int nxt = cur ^ 1;
#pragma unroll
            for (int q = tid; q < AQ; q += THREADS) {
                int r = q / (BK/4), c = (q % (BK/4)) * 4;
                cp16(&As[nxt * ASZ + r * AST + c], A + (size_t)(row0 + r) * K + k0 + c);
            }
#pragma unroll
            for (int q = tid; q < BQ; q += THREADS) {
                int r = q / (BN/4), c = (q % (BN/4)) * 4;
                cp16(&Bs[nxt * BSZ + r * BST + c], B + (size_t)(k0 + r) * N + col0 + c);
            }
            CP_COMMIT;
            CP_WAITN(1);
        } else {
            CP_WAITN(0);
        }
        __syncthreads();

#pragma unroll
        for (int ks = 0; ks < KS; ks++) {
            uint32_t afr[MI][4];
            uint32_t bfr[NI][2];
            const int ar = lane >> 2;
            const int ac = ks * 8 + (lane & 3);
#pragma unroll
            for (int mi = 0; mi < MI; mi++) {
                const float* base = &As[cur * ASZ + (wm + mi * 16 + ar) * AST + ac];
                if (CVTA) {
                    afr[mi][0] = f2tf(base[0]);
                    afr[mi][1] = f2tf(base[8 * AST]);
                    afr[mi][2] = f2tf(base[4]);
                    afr[mi][3] = f2tf(base[8 * AST + 4]);
                } else {
                    afr[mi][0] = __float_as_uint(base[0]);
                    afr[mi][1] = __float_as_uint(base[8 * AST]);
                    afr[mi][2] = __float_as_uint(base[4]);
                    afr[mi][3] = __float_as_uint(base[8 * AST + 4]);
                }
            }
            const int bk = ks * 8 + (lane & 3);
            const int bn = lane >> 2;
#pragma unroll
            for (int ni = 0; ni < NI; ni++) {
                const float* base = &Bs[cur * BSZ + bk * BST + wn + ni * 8 + bn];
                bfr[ni][0] = __float_as_uint(base[0]);
                bfr[ni][1] = __float_as_uint(base[4 * BST]);
            }
#pragma unroll
            for (int mi = 0; mi < MI; mi++)
#pragma unroll
                for (int ni = 0; ni < NI; ni++)
                    mma_tf32(acc[mi][ni], afr[mi], bfr[ni]);
        }
        __syncthreads();
    }

#pragma unroll
    for (int mi = 0; mi < MI; mi++) {
#pragma unroll
        for (int ni = 0; ni < NI; ni++) {
            const int r0 = row0 + wm + mi * 16 + (lane >> 2);
            const int c0 = col0 + wn + ni * 8 + 2 * (lane & 3);
#pragma unroll
            for (int half = 0; half < 2; half++) {
                const int rr = r0 + half * 8;
#pragma unroll
                for (int e = 0; e < 2; e++) {
                    const int nn = c0 + e;
                    float v = acc[mi][ni][half * 2 + e];
                    if (EPI == 1) {
                        v = tanhf(v + p0[nn]);
                        v = (v - p3[nn]) * rsqrtf(p4[nn] + BN_EPS) * p1[nn] + p2[nn];
                        v = tanhf(v);
                        v = __uint_as_float(f2tf(v));
                    } else if (EPI == 2) {
                        v += p0[nn];
                    }
                    C[(size_t)rr * N + nn] = v;
                }
            }
        }
    }
}

// ---------------- persistent LSTM recurrence ---------------------------------
// 128 CTAs x 512 threads. 3-stage ring; next-step B tiles prefetched during
// epilogue+barrier; c in smem; Zx in registers at step head; ep separate.
#define FBM 64
#define FBK 64
#define FBN 128
#define FAST (FBK + 4)       // 68
#define FBST (FBN + 8)       // 136
#define FEST (FBN + 4)       // 132
#define AS_SZ (FBM * FAST)   // 4352 floats
#define BS_SZ (FBK * FBST)   // 8704 floats
#define EP_SZ (FBM * FEST)   // 8448 floats
#define C_SZ  (FBM * 32)     // 2048 floats
#define PSMEM_BYTES ((3*(AS_SZ+BS_SZ) + EP_SZ + C_SZ) * 4)   // 198656 B

__global__ void __launch_bounds__(512)
lstm_persistent(const float* __restrict__ Wr,      // tf32-rounded (HH, 4HH)
                const float* __restrict__ Zx,      // (BB*TT, 4HH), bias included
                float* __restrict__ hseq,          // (TT, BB, HH) fp32
                float* __restrict__ ht0,           // ping-pong tf32 h
                float* __restrict__ ht1,
                const float* __restrict__ pi, const float* __restrict__ pf,
                const float* __restrict__ po)
{
    extern __shared__ float dsm[];
    float* As  = dsm;                         // [3][AS_SZ]
    float* Bs  = dsm + 3 * AS_SZ;             // [3][BS_SZ]
    float* ep  = dsm + 3 * (AS_SZ + BS_SZ);   // [EP_SZ]
    float* csm = ep + EP_SZ;                  // [C_SZ]

    const int tid  = threadIdx.x;
    const int lane = tid & 31;
    const int warp = tid >> 5;
    const int wm   = (warp >> 2) * 16;
    const int wn   = (warp & 3) * 32;
    const int row0 = (blockIdx.x & 3) * FBM;
    const int j0   = (blockIdx.x >> 2) * 32;

    const int j  = tid & 31;
    const int jg = j0 + j;
    const float pij = pi[jg], pfj = pf[jg], poj = po[jg];

    // zero the smem cell state
    for (int i = tid; i < C_SZ; i += 512) csm[i] = 0.0f;
    __syncthreads();

    constexpr int AQ = FBM * FBK / 4;   // 1024 -> 2/thread
    constexpr int BQ = FBK * FBN / 4;   // 2048 -> 4/thread
    constexpr int KT = HH / FBK;        // 16

    auto load_A = [&](int st, int kt, const float* hprev) {
#pragma unroll
        for (int qq = tid; qq < AQ; qq += 512) {
            int r = qq >> 4, c = (qq & 15) * 4;
            cp16(&As[st * AS_SZ + r * FAST + c],
                 hprev + (size_t)(row0 + r) * HH + kt * FBK + c);
        }
    };
    auto load_B = [&](int st, int kt) {
#pragma unroll
        for (int qq = tid; qq < BQ; qq += 512) {
            int br = qq >> 5, ci = qq & 31;
            int g = ci >> 3, jj = (ci & 7) * 4;
            cp16(&Bs[st * BS_SZ + br * FBST + g * 32 + jj],
                 Wr + (size_t)(kt * FBK + br) * (4*HH) + g * HH + j0 + jj);
        }
    };

#pragma unroll 1
    for (int t = 0; t < TT; t++) {
        // ---- prefetch gate inputs into registers (independent of GEMM) ----
        float zxr[4][4];
#pragma unroll
        for (int s = 0; s < 4; s++) {
            const int b = row0 + s * 16 + (tid >> 5);
            const size_t zr = ((size_t)b * TT + t) * (4 * HH);
#pragma unroll
            for (int g = 0; g < 4; g++)
                zxr[s][g] = Zx[zr + g * HH + jg];
        }

        float acc[4][4];
#pragma unroll
        for (int ni = 0; ni < 4; ni++)
#pragma unroll
            for (int r = 0; r < 4; r++) acc[ni][r] = 0.0f;

        if (t > 0) {
            const float* hprev = ((t - 1) & 1) ? ht1 : ht0;
            // B tiles 0,1 already issued into Bs[0],Bs[1] at previous tail.
            load_A(0, 0, hprev);
            CP_COMMIT;                 // G0 = {B0, B1, A0}
            load_A(1, 1, hprev);
            CP_COMMIT;                 // G1 = {A1}

#pragma unroll 1
            for (int kt = 0; kt < KT; kt++) {
                const int cur = kt % 3;
                if (kt < KT - 1) { CP_WAITN(1); } else { CP_WAITN(0); }
                __syncthreads();

                if (kt + 2 < KT) {
                    const int nxt = (kt + 2) % 3;
                    load_A(nxt, kt + 2, hprev);
                    load_B(nxt, kt + 2);
                    CP_COMMIT;
                }

#pragma unroll
                for (int ks = 0; ks < FBK/8; ks++) {
                    uint32_t afr[4];
                    uint32_t bfr[4][2];
                    const int ar = lane >> 2;
                    const int ac = ks * 8 + (lane & 3);
                    {
                        const float* base = &As[cur * AS_SZ + (wm + ar) * FAST + ac];
                        afr[0] = __float_as_uint(base[0]);
                        afr[1] = __float_as_uint(base[8 * FAST]);
                        afr[2] = __float_as_uint(base[4]);
                        afr[3] = __float_as_uint(base[8 * FAST + 4]);
                    }
                    const int bk = ks * 8 + (lane & 3);
                    const int bn = lane >> 2;
#pragma unroll
                    for (int ni = 0; ni < 4; ni++) {
                        const float* base = &Bs[cur * BS_SZ + bk * FBST + wn + ni * 8 + bn];
                        bfr[ni][0] = __float_as_uint(base[0]);
                        bfr[ni][1] = __float_as_uint(base[4 * FBST]);
                    }
#pragma unroll
                    for (int ni = 0; ni < 4; ni++)
                        mma_tf32(acc[ni], afr, bfr[ni]);
                }
            }
        }
        __syncthreads();   // all MMA smem reads done

        // ---- issue next step's first two B tiles (stream during epi+barrier)
        if (t + 1 < TT) {
            load_B(0, 0);
            load_B(1, 1);
            // committed at next step head together with A0
        }

        // ---- dump accumulators to ep ----
#pragma unroll
        for (int ni = 0; ni < 4; ni++) {
            const int r0 = wm + (lane >> 2);
            const int c0 = wn + ni * 8 + 2 * (lane & 3);
#pragma unroll
            for (int half = 0; half < 2; half++) {
                ep[(r0 + half * 8) * FEST + c0]     = acc[ni][half * 2];
                ep[(r0 + half * 8) * FEST + c0 + 1] = acc[ni][half * 2 + 1];
            }
        }
        __syncthreads();

        // ---- gates ----
        float* hout  = hseq + (size_t)t * BB * HH;
        float* htcur = (t & 1) ? ht1 : ht0;
#pragma unroll
        for (int s = 0; s < 4; s++) {
            const int m = s * 16 + (tid >> 5);
            const int b = row0 + m;

            float zi = ep[m * FEST +       j] + zxr[s][0];
            float zf = ep[m * FEST +  32 + j] + zxr[s][1];
            float zc = ep[m * FEST +  64 + j] + zxr[s][2];
            float zo = ep[m * FEST +  96 + j] + zxr[s][3];

            float cc = csm[m * 32 + j];
            float ig = 1.0f / (1.0f + expf(-(zi + cc * pij)));
            float fg = 1.0f / (1.0f + expf(-(zf + cc * pfj)));
            float cn = fg * cc + ig * tanhf(zc);
            float og = 1.0f / (1.0f + expf(-(zo + cn * poj)));
            float hn = og * tanhf(cn);

            csm[m * 32 + j] = cn;
            hout[(size_t)b * HH + jg]  = hn;
            htcur[(size_t)b * HH + jg] = __uint_as_float(f2tf(hn));
        }

        // ---- grid barrier ----
        if (t + 1 < TT) {
            __threadfence();
            __syncthreads();
            if (tid == 0) {
                atomicAdd((unsigned*)&g_bar, 1u);
                const unsigned target = 128u * (unsigned)(t + 1);
                while (g_bar < target) __nanosleep(64);
                __threadfence();
            }
            __syncthreads();
        }
    }
}

// ---------------- final BN -> tanh -> Dense(H,10) ----------------------------
__global__ void logits_kernel(const float* __restrict__ hseq,
                              const float* __restrict__ g2, const float* __restrict__ b2,
                              const float* __restrict__ m2, const float* __restrict__ v2,
                              const float* __restrict__ Wout, float* __restrict__ out)
{
    int row = blockIdx.x;
    int t = row / BB, b = row % BB;
    int tid = threadIdx.x;

    float a[CC];
#pragma unroll
    for (int c2 = 0; c2 < CC; c2++) a[c2] = 0.0f;

    float4 hv = *(const float4*)(hseq + (size_t)row * HH + tid * 4);
    float4 gv = *(const float4*)(g2 + tid * 4);
    float4 bv = *(const float4*)(b2 + tid * 4);
    float4 mv = *(const float4*)(m2 + tid * 4);
    float4 vv = *(const float4*)(v2 + tid * 4);

    float h4[4] = {hv.x, hv.y, hv.z, hv.w};
    float G4[4] = {gv.x, gv.y, gv.z, gv.w};
    float B4[4] = {bv.x, bv.y, bv.z, bv.w};
    float M4[4] = {mv.x, mv.y, mv.z, mv.w};
    float V4[4] = {vv.x, vv.y, vv.z, vv.w};

#pragma unroll
    for (int s = 0; s < 4; s++) {
        int k = tid * 4 + s;
        float y = tanhf((h4[s] - M4[s]) * rsqrtf(V4[s] + BN_EPS) * G4[s] + B4[s]);
        const float* wr = Wout + (size_t)k * CC;
#pragma unroll
        for (int c2 = 0; c2 < CC; c2++)
            a[c2] = fmaf(y, wr[c2], a[c2]);
    }

#pragma unroll
    for (int off = 16; off > 0; off >>= 1)
#pragma unroll
        for (int c2 = 0; c2 < CC; c2++)
            a[c2] += __shfl_down_sync(0xffffffffu, a[c2], off);

    __shared__ float sacc[CC];
    if (tid < CC) sacc[tid] = 0.0f;
    __syncthreads();
    if ((tid & 31) == 0)
#pragma unroll
        for (int c2 = 0; c2 < CC; c2++) atomicAdd(&sacc[c2], a[c2]);
    __syncthreads();
    if (tid < CC)
        out[((size_t)b * TT + t) * CC + tid] = sacc[tid];
}

// ---------------- launcher ----------------------------------------------------
extern "C" void kernel_launch(void* const* d_in, const int* in_sizes, int n_in,
                              void* d_out, int out_size)
{
    const float* x      = (const float*)d_in[0];
    const float* W_fe   = (const float*)d_in[1];
    const float* b_fe   = (const float*)d_in[2];
    const float* gamma1 = (const float*)d_in[3];
    const float* beta1  = (const float*)d_in[4];
    const float* mean1  = (const float*)d_in[5];
    const float* var1   = (const float*)d_in[6];
    const float* Wg     = (const float*)d_in[7];
    const float* Wr     = (const float*)d_in[8];
    const float* bias   = (const float*)d_in[9];
    const float* pi     = (const float*)d_in[10];
    const float* pf     = (const float*)d_in[11];
    const float* po     = (const float*)d_in[12];
    const float* gamma2 = (const float*)d_in[13];
    const float* beta2  = (const float*)d_in[14];
    const float* mean2  = (const float*)d_in[15];
    const float* var2   = (const float*)d_in[16];
    const float* W_out  = (const float*)d_in[17];
    float* out = (float*)d_out;

    float *feat, *zx, *hseq, *wfe, *wg, *wrt, *ht;
    cudaGetSymbolAddress((void**)&feat, g_feat);
    cudaGetSymbolAddress((void**)&zx,   g_zx);
    cudaGetSymbolAddress((void**)&hseq, g_hseq);
    cudaGetSymbolAddress((void**)&wfe,  g_wfe);
    cudaGetSymbolAddress((void**)&wg,   g_wg);
    cudaGetSymbolAddress((void**)&wrt,  g_wrt);
    cudaGetSymbolAddress((void**)&ht,   g_ht);
    float* ht0 = ht;
    float* ht1 = ht + (size_t)BB * HH;

    // smem sizes
    constexpr int GEMM_SMEM = (2 * 256 * 20 + 2 * 16 * 136) * 4;  // 58368 B
    cudaFuncSetAttribute((const void*)gemm_tf32<256,128,16,64,32,1,true>,
                         cudaFuncAttributeMaxDynamicSharedMemorySize, GEMM_SMEM);
    cudaFuncSetAttribute((const void*)gemm_tf32<256,128,16,64,32,2,false>,
                         cudaFuncAttributeMaxDynamicSharedMemorySize, GEMM_SMEM);
    cudaFuncSetAttribute(lstm_persistent,
                         cudaFuncAttributeMaxDynamicSharedMemorySize, PSMEM_BYTES);

    // reset grid barrier
    init_kernel<<<1, 32>>>();

    // pre-round weights to tf32 (rna)
    {
        int n;
        n = FF*HH/4;   round_tf32_kernel<<<(n+255)/256,256>>>((const float4*)W_fe,(float4*)wfe, n);
        n = HH*4*HH/4; round_tf32_kernel<<<(n+255)/256,256>>>((const float4*)Wg,  (float4*)wg,  n);
        n = HH*4*HH/4; round_tf32_kernel<<<(n+255)/256,256>>>((const float4*)Wr,  (float4*)wrt, n);
    }

    // 1) feat = tanh(BN(tanh(x @ W_fe + b_fe)))   [32768 x 1024, K=784]
    {
        dim3 grid(HH/128, M1/256);
        gemm_tf32<256,128,16,64,32,1,true><<<grid, 512, GEMM_SMEM>>>(
            x, wfe, feat, M1, HH, FF, b_fe, gamma1, beta1, mean1, var1);
    }
    // 2) Zx = feat @ kernel + bias                [32768 x 4096, K=1024]
    {
        dim3 grid(4*HH/128, M1/256);
        gemm_tf32<256,128,16,64,32,2,false><<<grid, 512, GEMM_SMEM>>>(
            feat, wg, zx, M1, 4*HH, HH, bias, nullptr, nullptr, nullptr, nullptr);
    }
    // 3) recurrence: persistent kernel
    lstm_persistent<<<128, 512, PSMEM_BYTES>>>(wrt, zx, hseq, ht0, ht1,
                                               pi, pf, po);
    // 4) logits
    logits_kernel<<<M1, 256>>>(hseq, gamma2, beta2, mean2, var2, W_out, out);
}

// round 10
// speedup vs baseline: 1.5464x; 1.4619x over previous
#include <cuda_runtime.h>
#include <cuda_fp16.h>
#include <math.h>
#include <stdint.h>

// ---------------- problem constants ----------------
#define BB 256
#define TT 128
#define FF 784
#define HH 1024
#define CC 10
#define M1 (BB*TT)
#define BN_EPS 1e-3f

// ---------------- scratch (device globals) ----------------
__device__ __half g_feat[(size_t)M1 * HH];         // fp16 feat
__device__ float  g_zx  [(size_t)M1 * 4 * HH];     // fp32 Zx (+bias)
__device__ float  g_hseq[(size_t)M1 * HH];         // fp32 h (T,B,H)
__device__ __half g_ht  [2][(size_t)BB * HH];      // fp16 h ping-pong
__device__ float  g_wfe [(size_t)FF * HH];         // tf32-rounded W_fe
__device__ __half g_wg  [(size_t)HH * 4 * HH];     // fp16 kernel
__device__ __half g_wrt [(size_t)HH * 4 * HH];     // fp16 rec_kernel
__device__ volatile unsigned g_bar;

// ---------------- helpers ----------------
__device__ __forceinline__ uint32_t f2tf(float f) {
    uint32_t u;
    asm("cvt.rna.tf32.f32 %0, %1;" : "=r"(u) : "f"(f));
    return u;
}
__device__ __forceinline__ void cp16(void* dst, const void* src) {
    uint32_t d = (uint32_t)__cvta_generic_to_shared(dst);
    asm volatile("cp.async.cg.shared.global [%0], [%1], 16;" :: "r"(d), "l"(src));
}
#define CP_COMMIT asm volatile("cp.async.commit_group;")
#define CP_WAITN(n) asm volatile("cp.async.wait_group %0;" :: "n"(n))

__device__ __forceinline__ void mma_tf32(float* d, const uint32_t* a, const uint32_t* b) {
    asm volatile(
        "mma.sync.aligned.m16n8k8.row.col.f32.tf32.tf32.f32 "
        "{%0,%1,%2,%3}, {%4,%5,%6,%7}, {%8,%9}, {%0,%1,%2,%3};"
        : "+f"(d[0]), "+f"(d[1]), "+f"(d[2]), "+f"(d[3])
        : "r"(a[0]), "r"(a[1]), "r"(a[2]), "r"(a[3]),
          "r"(b[0]), "r"(b[1]));
}
__device__ __forceinline__ void mma_f16(float* d, const uint32_t* a, const uint32_t* b) {
    asm volatile(
        "mma.sync.aligned.m16n8k16.row.col.f32.f16.f16.f32 "
        "{%0,%1,%2,%3}, {%4,%5,%6,%7}, {%8,%9}, {%0,%1,%2,%3};"
        : "+f"(d[0]), "+f"(d[1]), "+f"(d[2]), "+f"(d[3])
        : "r"(a[0]), "r"(a[1]), "r"(a[2]), "r"(a[3]),
          "r"(b[0]), "r"(b[1]));
}
__device__ __forceinline__ void ldsm_x4(uint32_t& r0, uint32_t& r1, uint32_t& r2,
                                        uint32_t& r3, uint32_t addr) {
    asm volatile("ldmatrix.sync.aligned.m8n8.x4.shared.b16 {%0,%1,%2,%3}, [%4];"
        : "=r"(r0), "=r"(r1), "=r"(r2), "=r"(r3) : "r"(addr));
}
__device__ __forceinline__ void ldsm_x2t(uint32_t& r0, uint32_t& r1, uint32_t addr) {
    asm volatile("ldmatrix.sync.aligned.m8n8.x2.trans.shared.b16 {%0,%1}, [%2];"
        : "=r"(r0), "=r"(r1) : "r"(addr));
}

__global__ void init_kernel() {
    if (threadIdx.x == 0 && blockIdx.x == 0) g_bar = 0u;
}
__global__ void round_tf32_kernel(const float4* __restrict__ in,
                                  float4* __restrict__ out, int n4) {
    int i = blockIdx.x * blockDim.x + threadIdx.x;
    if (i < n4) {
        float4 v = in[i];
        float4 o;
        o.x = __uint_as_float(f2tf(v.x));
        o.y = __uint_as_float(f2tf(v.y));
        o.z = __uint_as_float(f2tf(v.z));
        o.w = __uint_as_float(f2tf(v.w));
        out[i] = o;
    }
}
__global__ void f32_to_f16_kernel(const float2* __restrict__ in,
                                  __half2* __restrict__ out, int n2) {
    int i = blockIdx.x * blockDim.x + threadIdx.x;
    if (i < n2) {
        float2 v = in[i];
        out[i] = __floats2half2_rn(v.x, v.y);
    }
}

// ---------------- tf32 GEMM 1 (featurizer): x fp32 -> feat fp16 --------------
// BM=256 BN=128 BK=16, 512 threads (WM=64, WN=32). tanh,BN,tanh epilogue.
__global__ void __launch_bounds__(512)
gemm1_tf32(const float* __restrict__ A, const float* __restrict__ B,
           __half* __restrict__ C, int M, int N, int K,
           const float* __restrict__ p0, const float* __restrict__ p1,
           const float* __restrict__ p2, const float* __restrict__ p3,
           const float* __restrict__ p4)
{
    constexpr int BM = 256, BN = 128, BK = 16, WM = 64, WN = 32;
    constexpr int MI = WM/16, NI = WN/8, KS = BK/8;
    constexpr int AST = BK + 4, BST = BN + 8;
    constexpr int AQ = BM*BK/4, BQ = BK*BN/4;
    constexpr int ASZ = BM*AST, BSZ = BK*BST;

    extern __shared__ float sm[];
    float* As = sm;
    float* Bs = sm + 2*ASZ;

    const int tid = threadIdx.x, lane = tid & 31, warp = tid >> 5;
    const int wm = (warp / (BN/WN)) * WM, wn = (warp % (BN/WN)) * WN;
    const int row0 = blockIdx.y * BM, col0 = blockIdx.x * BN;

    float acc[MI][NI][4];
#pragma unroll
    for (int mi = 0; mi < MI; mi++)
#pragma unroll
        for (int ni = 0; ni < NI; ni++)
#pragma unroll
            for (int r = 0; r < 4; r++) acc[mi][ni][r] = 0.0f;

    const int KT = K / BK;
#pragma unroll
    for (int q = tid; q < AQ; q += 512) {
        int r = q / (BK/4), c = (q % (BK/4)) * 4;
        cp16(&As[r*AST + c], A + (size_t)(row0 + r)*K + c);
    }
#pragma unroll
    for (int q = tid; q < BQ; q += 512) {
        int r = q / (BN/4), c = (q % (BN/4)) * 4;
        cp16(&Bs[r*BST + c], B + (size_t)r*N + col0 + c);
    }
    CP_COMMIT;

#pragma unroll 1
    for (int kt = 0; kt < KT; kt++) {
        const int cur = kt & 1;
        if (kt + 1 < KT) {
            const int k0 = (kt + 1)*BK, nxt = cur ^ 1;
#pragma unroll
            for (int q = tid; q < AQ; q += 512) {
                int r = q / (BK/4), c = (q % (BK/4)) * 4;
                cp16(&As[nxt*ASZ + r*AST + c], A + (size_t)(row0 + r)*K + k0 + c);
            }
#pragma unroll
            for (int q = tid; q < BQ; q += 512) {
                int r = q / (BN/4), c = (q % (BN/4)) * 4;
                cp16(&Bs[nxt*BSZ + r*BST + c], B + (size_t)(k0 + r)*N + col0 + c);
            }
            CP_COMMIT;
            CP_WAITN(1);
        } else {
            CP_WAITN(0);
        }
        __syncthreads();

#pragma unroll
        for (int ks = 0; ks < KS; ks++) {
            uint32_t afr[MI][4], bfr[NI][2];
            const int ar = lane >> 2, ac = ks*8 + (lane & 3);
#pragma unroll
            for (int mi = 0; mi < MI; mi++) {
                const float* base = &As[cur*ASZ + (wm + mi*16 + ar)*AST + ac];
                afr[mi][0] = f2tf(base[0]);
                afr[mi][1] = f2tf(base[8*AST]);
                afr[mi][2] = f2tf(base[4]);
                afr[mi][3] = f2tf(base[8*AST + 4]);
            }
            const int bk = ks*8 + (lane & 3), bn = lane >> 2;
#pragma unroll
            for (int ni = 0; ni < NI; ni++) {
                const float* base = &Bs[cur*BSZ + bk*BST + wn + ni*8 + bn];
                bfr[ni][0] = __float_as_uint(base[0]);
                bfr[ni][1] = __float_as_uint(base[4*BST]);
            }
#pragma unroll
            for (int mi = 0; mi < MI; mi++)
#pragma unroll
                for (int ni = 0; ni < NI; ni++)
                    mma_tf32(acc[mi][ni], afr[mi], bfr[ni]);
        }
        __syncthreads();
    }

#pragma unroll
    for (int mi = 0; mi < MI; mi++)
#pragma unroll
        for (int ni = 0; ni < NI; ni++) {
            const int r0 = row0 + wm + mi*16 + (lane >> 2);
            const int c0 = col0 + wn + ni*8 + 2*(lane & 3);
#pragma unroll
            for (int half = 0; half < 2; half++) {
                const int rr = r0 + half*8;
#pragma unroll
                for (int e = 0; e < 2; e++) {
                    const int nn = c0 + e;
                    float v = acc[mi][ni][half*2 + e];
                    v = tanhf(v + p0[nn]);
                    v = (v - p3[nn]) * rsqrtf(p4[nn] + BN_EPS) * p1[nn] + p2[nn];
                    v = tanhf(v);
                    C[(size_t)rr*N + nn] = __float2half(v);
                }
            }
        }
}

// ---------------- fp16 GEMM 2: Zx = feat @ Wg + bias -------------------------
// BM=256 BN=128 BK=32, 512 threads (WM=64, WN=32), ldmatrix + m16n8k16.
__global__ void __launch_bounds__(512)
gemm2_f16(const __half* __restrict__ A, const __half* __restrict__ B,
          float* __restrict__ C, int M, int N, int K,
          const float* __restrict__ bias)
{
    constexpr int BM = 256, BN = 128, BK = 32, WM = 64, WN = 32;
    constexpr int MI = WM/16, NI = WN/8, KS = BK/16;
    constexpr int ASTH = BK + 8;     // 40 halves (80B = 20 words: conflict-free LDSM)
    constexpr int BSTH = BN + 8;     // 136 halves (272B = 68 words: conflict-free)
    constexpr int ASZH = BM*ASTH, BSZH = BK*BSTH;
    constexpr int AQ8 = BM*BK/8, BQ8 = BK*BN/8;

    extern __shared__ __half smh[];
    __half* As = smh;
    __half* Bs = smh + 2*ASZH;
    const uint32_t As_u = (uint32_t)__cvta_generic_to_shared(As);
    const uint32_t Bs_u = (uint32_t)__cvta_generic_to_shared(Bs);

    const int tid = threadIdx.x, lane = tid & 31, warp = tid >> 5;
    const int wm = (warp / (BN/WN)) * WM, wn = (warp % (BN/WN)) * WN;
    const int row0 = blockIdx.y * BM, col0 = blockIdx.x * BN;

    float acc[MI][NI][4];
#pragma unroll
    for (int mi = 0; mi < MI; mi++)
#pragma unroll
        for (int ni = 0; ni < NI; ni++)
#pragma unroll
            for (int r = 0; r < 4; r++) acc[mi][ni][r] = 0.0f;

    const int KT = K / BK;
#pragma unroll
    for (int q = tid; q < AQ8; q += 512) {
        int r = q >> 2, c = (q & 3) * 8;
        cp16(&As[r*ASTH + c], A + (size_t)(row0 + r)*K + c);
    }
#pragma unroll
    for (int q = tid; q < BQ8; q += 512) {
        int r = q >> 4, c = (q & 15) * 8;
        cp16(&Bs[r*BSTH + c], B + (size_t)r*N + col0 + c);
    }
    CP_COMMIT;

    // per-lane ldmatrix address pieces
    const int a_m = (lane & 7) + ((lane >> 3) & 1) * 8;   // row within m16
    const int a_k = (lane >> 4) * 8;                      // k offset within k16
    const int b_k = (lane & 15);                          // row within k16

#pragma unroll 1
    for (int kt = 0; kt < KT; kt++) {
        const int cur = kt & 1;
        if (kt + 1 < KT) {
            const int k0 = (kt + 1)*BK, nxt = cur ^ 1;
#pragma unroll
            for (int q = tid; q < AQ8; q += 512) {
                int r = q >> 2, c = (q & 3) * 8;
                cp16(&As[nxt*ASZH + r*ASTH + c], A + (size_t)(row0 + r)*K + k0 + c);
            }
#pragma unroll
            for (int q = tid; q < BQ8; q += 512) {
                int r = q >> 4, c = (q & 15) * 8;
                cp16(&Bs[nxt*BSZH + r*BSTH + c], B + (size_t)(k0 + r)*N + col0 + c);
            }
            CP_COMMIT;
            CP_WAITN(1);
        } else {
            CP_WAITN(0);
        }
        __syncthreads();

#pragma unroll
        for (int ks = 0; ks < KS; ks++) {
            uint32_t afr[MI][4], bfr[NI][2];
#pragma unroll
            for (int mi = 0; mi < MI; mi++) {
                uint32_t addr = As_u + (uint32_t)((cur*ASZH + (wm + mi*16 + a_m)*ASTH
                                                   + ks*16 + a_k) * 2);
                ldsm_x4(afr[mi][0], afr[mi][1], afr[mi][2], afr[mi][3], addr);
            }
#pragma unroll
            for (int ni = 0; ni < NI; ni++) {
                uint32_t addr = Bs_u + (uint32_t)((cur*BSZH + (ks*16 + b_k)*BSTH
                                                   + wn + ni*8) * 2);
                ldsm_x2t(bfr[ni][0], bfr[ni][1], addr);
            }
#pragma unroll
            for (int mi = 0; mi < MI; mi++)
#pragma unroll
                for (int ni = 0; ni < NI; ni++)
                    mma_f16(acc[mi][ni], afr[mi], bfr[ni]);
        }
        __syncthreads();
    }

#pragma unroll
    for (int mi = 0; mi < MI; mi++)
#pragma unroll
        for (int ni = 0; ni < NI; ni++) {
            const int r0 = row0 + wm + mi*16 + (lane >> 2);
            const int c0 = col0 + wn + ni*8 + 2*(lane & 3);
#pragma unroll
            for (int half = 0; half < 2; half++) {
                const int rr = r0 + half*8;
#pragma unroll
                for (int e = 0; e < 2; e++) {
                    const int nn = c0 + e;
                    C[(size_t)rr*N + nn] = acc[mi][ni][half*2 + e] + bias[nn];
                }
            }
        }
}

// ---------------- persistent fp16 LSTM recurrence ----------------------------
#define FBM 64
#define FBK 64
#define FBN 128
#define FASTH (FBK + 8)      // 72 halves (144B = 36 words: conflict-free LDSM)
#define FBSTH (FBN + 8)      // 136 halves
#define FEST (FBN + 4)       // 132 floats
#define AS_SZH (FBM * FASTH) // 4608 halves (9216 B)
#define BS_SZH (FBK * FBSTH) // 8704 halves (17408 B)
#define EP_SZ (FBM * FEST)   // floats
#define C_SZ  (FBM * 32)
#define PSMEM_BYTES (3*(AS_SZH + BS_SZH)*2 + (EP_SZ + C_SZ)*4)  // 121856 B

__global__ void __launch_bounds__(512)
lstm_persistent(const __half* __restrict__ Wr,     // fp16 (HH, 4HH)
                const float* __restrict__ Zx,      // (BB*TT, 4HH) fp32 (+bias)
                float* __restrict__ hseq,
                __half* __restrict__ ht0, __half* __restrict__ ht1,
                const float* __restrict__ pi, const float* __restrict__ pf,
                const float* __restrict__ po)
{
    extern __shared__ __half dsh[];
    __half* As = dsh;                              // [3][AS_SZH]
    __half* Bs = dsh + 3*AS_SZH;                   // [3][BS_SZH]
    float*  ep  = (float*)(dsh + 3*(AS_SZH + BS_SZH));
    float*  csm = ep + EP_SZ;
    const uint32_t As_u = (uint32_t)__cvta_generic_to_shared(As);
    const uint32_t Bs_u = (uint32_t)__cvta_generic_to_shared(Bs);

    const int tid = threadIdx.x, lane = tid & 31, warp = tid >> 5;
    const int wm = (warp >> 2) * 16;      // 0,16,32,48
    const int wn = (warp & 3) * 32;       // gate slab
    const int row0 = (blockIdx.x & 3) * FBM;
    const int j0   = (blockIdx.x >> 2) * 32;

    const int j = tid & 31, jg = j0 + j;
    const float pij = pi[jg], pfj = pf[jg], poj = po[jg];

    for (int i = tid; i < C_SZ; i += 512) csm[i] = 0.0f;
    __syncthreads();

    constexpr int AQ8 = FBM*FBK/8;   // 512 -> 1/thread
    constexpr int BQ8 = FBK*FBN/8;   // 1024 -> 2/thread
    constexpr int KT = HH / FBK;     // 16

    auto load_A = [&](int st, int kt, const __half* hprev) {
#pragma unroll
        for (int q = tid; q < AQ8; q += 512) {
            int r = q >> 3, c = (q & 7) * 8;
            cp16(&As[st*AS_SZH + r*FASTH + c],
                 hprev + (size_t)(row0 + r)*HH + kt*FBK + c);
        }
    };
    auto load_B = [&](int st, int kt) {
#pragma unroll
        for (int q = tid; q < BQ8; q += 512) {
            int br = q >> 4, ci = q & 15;
            int g = ci >> 2, jj = (ci & 3) * 8;
            cp16(&Bs[st*BS_SZH + br*FBSTH + g*32 + jj],
                 Wr + (size_t)(kt*FBK + br)*(4*HH) + g*HH + j0 + jj);
        }
    };

    const int a_m = (lane & 7) + ((lane >> 3) & 1) * 8;
    const int a_k = (lane >> 4) * 8;
    const int b_k = (lane & 15);

#pragma unroll 1
    for (int t = 0; t < TT; t++) {
        // prefetch gate inputs into registers
        float zxr[4][4];
#pragma unroll
        for (int s = 0; s < 4; s++) {
            const int b = row0 + s*16 + (tid >> 5);
            const size_t zr = ((size_t)b*TT + t) * (4*HH);
#pragma unroll
            for (int g = 0; g < 4; g++)
                zxr[s][g] = Zx[zr + g*HH + jg];
        }

        float acc[4][4];
#pragma unroll
        for (int ni = 0; ni < 4; ni++)
#pragma unroll
            for (int r = 0; r < 4; r++) acc[ni][r] = 0.0f;

        if (t > 0) {
            const __half* hprev = ((t - 1) & 1) ? ht1 : ht0;
            load_A(0, 0, hprev);
            CP_COMMIT;              // {B0, B1 (from tail), A0}
            load_A(1, 1, hprev);
            CP_COMMIT;              // {A1}

#pragma unroll 1
            for (int kt = 0; kt < KT; kt++) {
                const int cur = kt % 3;
                if (kt < KT - 1) { CP_WAITN(1); } else { CP_WAITN(0); }
                __syncthreads();

                if (kt + 2 < KT) {
                    const int nxt = (kt + 2) % 3;
                    load_A(nxt, kt + 2, hprev);
                    load_B(nxt, kt + 2);
                    CP_COMMIT;
                }

#pragma unroll
                for (int ks = 0; ks < FBK/16; ks++) {
                    uint32_t afr[4], bfr[4][2];
                    {
                        uint32_t addr = As_u + (uint32_t)((cur*AS_SZH
                                          + (wm + a_m)*FASTH + ks*16 + a_k) * 2);
                        ldsm_x4(afr[0], afr[1], afr[2], afr[3], addr);
                    }
#pragma unroll
                    for (int ni = 0; ni < 4; ni++) {
                        uint32_t addr = Bs_u + (uint32_t)((cur*BS_SZH
                                          + (ks*16 + b_k)*FBSTH + wn + ni*8) * 2);
                        ldsm_x2t(bfr[ni][0], bfr[ni][1], addr);
                    }
#pragma unroll
                    for (int ni = 0; ni < 4; ni++)
                        mma_f16(acc[ni], afr, bfr[ni]);
                }
            }
        }
        __syncthreads();

        // prefetch next step's first two B tiles (committed at next step head)
        if (t + 1 < TT) {
            load_B(0, 0);
            load_B(1, 1);
        }

        // dump accumulators to ep
#pragma unroll
        for (int ni = 0; ni < 4; ni++) {
            const int r0 = wm + (lane >> 2);
            const int c0 = wn + ni*8 + 2*(lane & 3);
#pragma unroll
            for (int half = 0; half < 2; half++) {
                ep[(r0 + half*8)*FEST + c0]     = acc[ni][half*2];
                ep[(r0 + half*8)*FEST + c0 + 1] = acc[ni][half*2 + 1];
            }
        }
        __syncthreads();

        // gates
        float* hout  = hseq + (size_t)t*BB*HH;
        __half* htcur = (t & 1) ? ht1 : ht0;
#pragma unroll
        for (int s = 0; s < 4; s++) {
            const int m = s*16 + (tid >> 5);
            const int b = row0 + m;

            float zi = ep[m*FEST +       j] + zxr[s][0];
            float zf = ep[m*FEST +  32 + j] + zxr[s][1];
            float zc = ep[m*FEST +  64 + j] + zxr[s][2];
            float zo = ep[m*FEST +  96 + j] + zxr[s][3];

            float cc = csm[m*32 + j];
            float ig = 1.0f / (1.0f + expf(-(zi + cc*pij)));
            float fg = 1.0f / (1.0f + expf(-(zf + cc*pfj)));
            float cn = fg*cc + ig*tanhf(zc);
            float og = 1.0f / (1.0f + expf(-(zo + cn*poj)));
            float hn = og*tanhf(cn);

            csm[m*32 + j] = cn;
            hout[(size_t)b*HH + jg]  = hn;
            htcur[(size_t)b*HH + jg] = __float2half(hn);
        }

        // grid barrier
        if (t + 1 < TT) {
            __threadfence();
            __syncthreads();
            if (tid == 0) {
                atomicAdd((unsigned*)&g_bar, 1u);
                const unsigned target = 128u * (unsigned)(t + 1);
                while (g_bar < target) __nanosleep(64);
                __threadfence();
            }
            __syncthreads();
        }
    }
}

// ---------------- final BN -> tanh -> Dense(H,10) ----------------------------
__global__ void logits_kernel(const float* __restrict__ hseq,
                              const float* __restrict__ g2, const float* __restrict__ b2,
                              const float* __restrict__ m2, const float* __restrict__ v2,
                              const float* __restrict__ Wout, float* __restrict__ out)
{
    int row = blockIdx.x;
    int t = row / BB, b = row % BB;
    int tid = threadIdx.x;

    float a[CC];
#pragma unroll
    for (int c2 = 0; c2 < CC; c2++) a[c2] = 0.0f;

    float4 hv = *(const float4*)(hseq + (size_t)row*HH + tid*4);
    float4 gv = *(const float4*)(g2 + tid*4);
    float4 bv = *(const float4*)(b2 + tid*4);
    float4 mv = *(const float4*)(m2 + tid*4);
    float4 vv = *(const float4*)(v2 + tid*4);

    float h4[4] = {hv.x, hv.y, hv.z, hv.w};
    float G4[4] = {gv.x, gv.y, gv.z, gv.w};
    float B4[4] = {bv.x, bv.y, bv.z, bv.w};
    float M4[4] = {mv.x, mv.y, mv.z, mv.w};
    float V4[4] = {vv.x, vv.y, vv.z, vv.w};

#pragma unroll
    for (int s = 0; s < 4; s++) {
        int k = tid*4 + s;
        float y = tanhf((h4[s] - M4[s]) * rsqrtf(V4[s] + BN_EPS) * G4[s] + B4[s]);
        const float* wr = Wout + (size_t)k*CC;
#pragma unroll
        for (int c2 = 0; c2 < CC; c2++)
            a[c2] = fmaf(y, wr[c2], a[c2]);
    }

#pragma unroll
    for (int off = 16; off > 0; off >>= 1)
#pragma unroll
        for (int c2 = 0; c2 < CC; c2++)
            a[c2] += __shfl_down_sync(0xffffffffu, a[c2], off);

    __shared__ float sacc[CC];
    if (tid < CC) sacc[tid] = 0.0f;
    __syncthreads();
    if ((tid & 31) == 0)
#pragma unroll
        for (int c2 = 0; c2 < CC; c2++) atomicAdd(&sacc[c2], a[c2]);
    __syncthreads();
    if (tid < CC)
        out[((size_t)b*TT + t)*CC + tid] = sacc[tid];
}

// ---------------- launcher ----------------------------------------------------
extern "C" void kernel_launch(void* const* d_in, const int* in_sizes, int n_in,
                              void* d_out, int out_size)
{
    const float* x      = (const float*)d_in[0];
    const float* W_fe   = (const float*)d_in[1];
    const float* b_fe   = (const float*)d_in[2];
    const float* gamma1 = (const float*)d_in[3];
    const float* beta1  = (const float*)d_in[4];
    const float* mean1  = (const float*)d_in[5];
    const float* var1   = (const float*)d_in[6];
    const float* Wg     = (const float*)d_in[7];
    const float* Wr     = (const float*)d_in[8];
    const float* bias   = (const float*)d_in[9];
    const float* pi     = (const float*)d_in[10];
    const float* pf     = (const float*)d_in[11];
    const float* po     = (const float*)d_in[12];
    const float* gamma2 = (const float*)d_in[13];
    const float* beta2  = (const float*)d_in[14];
    const float* mean2  = (const float*)d_in[15];
    const float* var2   = (const float*)d_in[16];
    const float* W_out  = (const float*)d_in[17];
    float* out = (float*)d_out;

    __half *feat, *wg, *wrt, *ht;
    float *zx, *hseq, *wfe;
    cudaGetSymbolAddress((void**)&feat, g_feat);
    cudaGetSymbolAddress((void**)&zx,   g_zx);
    cudaGetSymbolAddress((void**)&hseq, g_hseq);
    cudaGetSymbolAddress((void**)&wfe,  g_wfe);
    cudaGetSymbolAddress((void**)&wg,   g_wg);
    cudaGetSymbolAddress((void**)&wrt,  g_wrt);
    cudaGetSymbolAddress((void**)&ht,   g_ht);
    __half* ht0 = ht;
    __half* ht1 = ht + (size_t)BB * HH;

    constexpr int G1_SMEM = (2*256*20 + 2*16*136) * 4;            // 58368 B
    constexpr int G2_SMEM = (2*256*40 + 2*32*136) * 2;            // 58368 B
    cudaFuncSetAttribute(gemm1_tf32, cudaFuncAttributeMaxDynamicSharedMemorySize, G1_SMEM);
    cudaFuncSetAttribute(gemm2_f16,  cudaFuncAttributeMaxDynamicSharedMemorySize, G2_SMEM);
    cudaFuncSetAttribute(lstm_persistent,
                         cudaFuncAttributeMaxDynamicSharedMemorySize, PSMEM_BYTES);

    init_kernel<<<1, 32>>>();

    // preprocess weights
    {
        int n = FF*HH/4;
        round_tf32_kernel<<<(n+255)/256, 256>>>((const float4*)W_fe, (float4*)wfe, n);
        int n2 = HH*4*HH/2;
        f32_to_f16_kernel<<<(n2+255)/256, 256>>>((const float2*)Wg, (__half2*)wg, n2);
        f32_to_f16_kernel<<<(n2+255)/256, 256>>>((const float2*)Wr, (__half2*)wrt, n2);
    }

    // 1) feat (fp16) = tanh(BN(tanh(x @ W_fe + b_fe)))
    {
        dim3 grid(HH/128, M1/256);
        gemm1_tf32<<<grid, 512, G1_SMEM>>>(x, wfe, feat, M1, HH, FF,
                                           b_fe, gamma1, beta1, mean1, var1);
    }
    // 2) Zx = feat @ Wg + bias  (fp16 operands, fp32 out)
    {
        dim3 grid(4*HH/128, M1/256);
        gemm2_f16<<<grid, 512, G2_SMEM>>>(feat, wg, zx, M1, 4*HH, HH, bias);
    }
    // 3) recurrence (fp16 operands)
    lstm_persistent<<<128, 512, PSMEM_BYTES>>>(wrt, zx, hseq, ht0, ht1, pi, pf, po);
    // 4) logits
    logits_kernel<<<M1, 256>>>(hseq, gamma2, beta2, mean2, var2, W_out, out);
}

// round 11
// speedup vs baseline: 1.6726x; 1.0816x over previous
#include <cuda_runtime.h>
#include <cuda_fp16.h>
#include <math.h>
#include <stdint.h>

// ---------------- problem constants ----------------
#define BB 256
#define TT 128
#define FF 784
#define HH 1024
#define CC 10
#define M1 (BB*TT)
#define BN_EPS 1e-3f

// ---------------- scratch (device globals) ----------------
__device__ __half g_feat[(size_t)M1 * HH];         // fp16 feat
__device__ float  g_zx  [(size_t)M1 * 4 * HH];     // fp32 Zx (+bias)
__device__ float  g_hseq[(size_t)M1 * HH];         // fp32 h (T,B,H)
__device__ __half g_ht  [2][(size_t)BB * HH];      // fp16 h ping-pong
__device__ float  g_wfe [(size_t)FF * HH];         // tf32-rounded W_fe
__device__ __half g_wg  [(size_t)HH * 4 * HH];     // fp16 kernel
__device__ __half g_wrt [(size_t)HH * 4 * HH];     // fp16 rec_kernel
__device__ volatile unsigned g_bar;

// ---------------- helpers ----------------
__device__ __forceinline__ uint32_t f2tf(float f) {
    uint32_t u;
    asm("cvt.rna.tf32.f32 %0, %1;" : "=r"(u) : "f"(f));
    return u;
}
__device__ __forceinline__ void cp16(void* dst, const void* src) {
    uint32_t d = (uint32_t)__cvta_generic_to_shared(dst);
    asm volatile("cp.async.cg.shared.global [%0], [%1], 16;" :: "r"(d), "l"(src));
}
#define CP_COMMIT asm volatile("cp.async.commit_group;")
#define CP_WAITN(n) asm volatile("cp.async.wait_group %0;" :: "n"(n))

__device__ __forceinline__ void mma_tf32(float* d, const uint32_t* a, const uint32_t* b) {
    asm volatile(
        "mma.sync.aligned.m16n8k8.row.col.f32.tf32.tf32.f32 "
        "{%0,%1,%2,%3}, {%4,%5,%6,%7}, {%8,%9}, {%0,%1,%2,%3};"
        : "+f"(d[0]), "+f"(d[1]), "+f"(d[2]), "+f"(d[3])
        : "r"(a[0]), "r"(a[1]), "r"(a[2]), "r"(a[3]),
          "r"(b[0]), "r"(b[1]));
}
__device__ __forceinline__ void mma_f16(float* d, const uint32_t* a, const uint32_t* b) {
    asm volatile(
        "mma.sync.aligned.m16n8k16.row.col.f32.f16.f16.f32 "
        "{%0,%1,%2,%3}, {%4,%5,%6,%7}, {%8,%9}, {%0,%1,%2,%3};"
        : "+f"(d[0]), "+f"(d[1]), "+f"(d[2]), "+f"(d[3])
        : "r"(a[0]), "r"(a[1]), "r"(a[2]), "r"(a[3]),
          "r"(b[0]), "r"(b[1]));
}
__device__ __forceinline__ void ldsm_x4(uint32_t& r0, uint32_t& r1, uint32_t& r2,
                                        uint32_t& r3, uint32_t addr) {
    asm volatile("ldmatrix.sync.aligned.m8n8.x4.shared.b16 {%0,%1,%2,%3}, [%4];"
        : "=r"(r0), "=r"(r1), "=r"(r2), "=r"(r3) : "r"(addr));
}
__device__ __forceinline__ void ldsm_x2t(uint32_t& r0, uint32_t& r1, uint32_t addr) {
    asm volatile("ldmatrix.sync.aligned.m8n8.x2.trans.shared.b16 {%0,%1}, [%2];"
        : "=r"(r0), "=r"(r1) : "r"(addr));
}

__global__ void init_kernel() {
    if (threadIdx.x == 0 && blockIdx.x == 0) g_bar = 0u;
}
__global__ void round_tf32_kernel(const float4* __restrict__ in,
                                  float4* __restrict__ out, int n4) {
    int i = blockIdx.x * blockDim.x + threadIdx.x;
    if (i < n4) {
        float4 v = in[i];
        float4 o;
        o.x = __uint_as_float(f2tf(v.x));
        o.y = __uint_as_float(f2tf(v.y));
        o.z = __uint_as_float(f2tf(v.z));
        o.w = __uint_as_float(f2tf(v.w));
        out[i] = o;
    }
}
__global__ void f32_to_f16_kernel(const float2* __restrict__ in,
                                  __half2* __restrict__ out, int n2) {
    int i = blockIdx.x * blockDim.x + threadIdx.x;
    if (i < n2) {
        float2 v = in[i];
        out[i] = __floats2half2_rn(v.x, v.y);
    }
}

// ---------------- tf32 GEMM 1 (featurizer): x fp32 -> feat fp16 --------------
__global__ void __launch_bounds__(512)
gemm1_tf32(const float* __restrict__ A, const float* __restrict__ B,
           __half* __restrict__ C, int M, int N, int K,
           const float* __restrict__ p0, const float* __restrict__ p1,
           const float* __restrict__ p2, const float* __restrict__ p3,
           const float* __restrict__ p4)
{
    constexpr int BM = 256, BN = 128, BK = 16, WM = 64, WN = 32;
    constexpr int MI = WM/16, NI = WN/8, KS = BK/8;
    constexpr int AST = BK + 4, BST = BN + 8;
    constexpr int AQ = BM*BK/4, BQ = BK*BN/4;
    constexpr int ASZ = BM*AST, BSZ = BK*BST;

    extern __shared__ float sm[];
    float* As = sm;
    float* Bs = sm + 2*ASZ;

    const int tid = threadIdx.x, lane = tid & 31, warp = tid >> 5;
    const int wm = (warp / (BN/WN)) * WM, wn = (warp % (BN/WN)) * WN;
    const int row0 = blockIdx.y * BM, col0 = blockIdx.x * BN;

    float acc[MI][NI][4];
#pragma unroll
    for (int mi = 0; mi < MI; mi++)
#pragma unroll
        for (int ni = 0; ni < NI; ni++)
#pragma unroll
            for (int r = 0; r < 4; r++) acc[mi][ni][r] = 0.0f;

    const int KT = K / BK;
#pragma unroll
    for (int q = tid; q < AQ; q += 512) {
        int r = q / (BK/4), c = (q % (BK/4)) * 4;
        cp16(&As[r*AST + c], A + (size_t)(row0 + r)*K + c);
    }
#pragma unroll
    for (int q = tid; q < BQ; q += 512) {
        int r = q / (BN/4), c = (q % (BN/4)) * 4;
        cp16(&Bs[r*BST + c], B + (size_t)r*N + col0 + c);
    }
    CP_COMMIT;

#pragma unroll 1
    for (int kt = 0; kt < KT; kt++) {
        const int cur = kt & 1;
        if (kt + 1 < KT) {
            const int k0 = (kt + 1)*BK, nxt = cur ^ 1;
#pragma unroll
            for (int q = tid; q < AQ; q += 512) {
                int r = q / (BK/4), c = (q % (BK/4)) * 4;
                cp16(&As[nxt*ASZ + r*AST + c], A + (size_t)(row0 + r)*K + k0 + c);
            }
#pragma unroll
            for (int q = tid; q < BQ; q += 512) {
                int r = q / (BN/4), c = (q % (BN/4)) * 4;
                cp16(&Bs[nxt*BSZ + r*BST + c], B + (size_t)(k0 + r)*N + col0 + c);
            }
            CP_COMMIT;
            CP_WAITN(1);
        } else {
            CP_WAITN(0);
        }
        __syncthreads();

#pragma unroll
        for (int ks = 0; ks < KS; ks++) {
            uint32_t afr[MI][4], bfr[NI][2];
            const int ar = lane >> 2, ac = ks*8 + (lane & 3);
#pragma unroll
            for (int mi = 0; mi < MI; mi++) {
                const float* base = &As[cur*ASZ + (wm + mi*16 + ar)*AST + ac];
                afr[mi][0] = f2tf(base[0]);
                afr[mi][1] = f2tf(base[8*AST]);
                afr[mi][2] = f2tf(base[4]);
                afr[mi][3] = f2tf(base[8*AST + 4]);
            }
            const int bk = ks*8 + (lane & 3), bn = lane >> 2;
#pragma unroll
            for (int ni = 0; ni < NI; ni++) {
                const float* base = &Bs[cur*BSZ + bk*BST + wn + ni*8 + bn];
                bfr[ni][0] = __float_as_uint(base[0]);
                bfr[ni][1] = __float_as_uint(base[4*BST]);
            }
#pragma unroll
            for (int mi = 0; mi < MI; mi++)
#pragma unroll
                for (int ni = 0; ni < NI; ni++)
                    mma_tf32(acc[mi][ni], afr[mi], bfr[ni]);
        }
        __syncthreads();
    }

#pragma unroll
    for (int mi = 0; mi < MI; mi++)
#pragma unroll
        for (int ni = 0; ni < NI; ni++) {
            const int r0 = row0 + wm + mi*16 + (lane >> 2);
            const int c0 = col0 + wn + ni*8 + 2*(lane & 3);
#pragma unroll
            for (int half = 0; half < 2; half++) {
                const int rr = r0 + half*8;
#pragma unroll
                for (int e = 0; e < 2; e++) {
                    const int nn = c0 + e;
                    float v = acc[mi][ni][half*2 + e];
                    v = tanhf(v + p0[nn]);
                    v = (v - p3[nn]) * rsqrtf(p4[nn] + BN_EPS) * p1[nn] + p2[nn];
                    v = tanhf(v);
                    C[(size_t)rr*N + nn] = __float2half(v);
                }
            }
        }
}

// ---------------- fp16 GEMM 2: Zx = feat @ Wg + bias -------------------------
__global__ void __launch_bounds__(512)
gemm2_f16(const __half* __restrict__ A, const __half* __restrict__ B,
          float* __restrict__ C, int M, int N, int K,
          const float* __restrict__ bias)
{
    constexpr int BM = 256, BN = 128, BK = 32, WM = 64, WN = 32;
    constexpr int MI = WM/16, NI = WN/8, KS = BK/16;
    constexpr int ASTH = BK + 8;
    constexpr int BSTH = BN + 8;
    constexpr int ASZH = BM*ASTH, BSZH = BK*BSTH;
    constexpr int AQ8 = BM*BK/8, BQ8 = BK*BN/8;

    extern __shared__ __half smh[];
    __half* As = smh;
    __half* Bs = smh + 2*ASZH;
    const uint32_t As_u = (uint32_t)__cvta_generic_to_shared(As);
    const uint32_t Bs_u = (uint32_t)__cvta_generic_to_shared(Bs);

    const int tid = threadIdx.x, lane = tid & 31, warp = tid >> 5;
    const int wm = (warp / (BN/WN)) * WM, wn = (warp % (BN/WN)) * WN;
    const int row0 = blockIdx.y * BM, col0 = blockIdx.x * BN;

    float acc[MI][NI][4];
#pragma unroll
    for (int mi = 0; mi < MI; mi++)
#pragma unroll
        for (int ni = 0; ni < NI; ni++)
#pragma unroll
            for (int r = 0; r < 4; r++) acc[mi][ni][r] = 0.0f;

    const int KT = K / BK;
#pragma unroll
    for (int q = tid; q < AQ8; q += 512) {
        int r = q >> 2, c = (q & 3) * 8;
        cp16(&As[r*ASTH + c], A + (size_t)(row0 + r)*K + c);
    }
#pragma unroll
    for (int q = tid; q < BQ8; q += 512) {
        int r = q >> 4, c = (q & 15) * 8;
        cp16(&Bs[r*BSTH + c], B + (size_t)r*N + col0 + c);
    }
    CP_COMMIT;

    const int a_m = (lane & 7) + ((lane >> 3) & 1) * 8;
    const int a_k = (lane >> 4) * 8;
    const int b_k = (lane & 15);

#pragma unroll 1
    for (int kt = 0; kt < KT; kt++) {
        const int cur = kt & 1;
        if (kt + 1 < KT) {
            const int k0 = (kt + 1)*BK, nxt = cur ^ 1;
#pragma unroll
            for (int q = tid; q < AQ8; q += 512) {
                int r = q >> 2, c = (q & 3) * 8;
                cp16(&As[nxt*ASZH + r*ASTH + c], A + (size_t)(row0 + r)*K + k0 + c);
            }
#pragma unroll
            for (int q = tid; q < BQ8; q += 512) {
                int r = q >> 4, c = (q & 15) * 8;
                cp16(&Bs[nxt*BSZH + r*BSTH + c], B + (size_t)(k0 + r)*N + col0 + c);
            }
            CP_COMMIT;
            CP_WAITN(1);
        } else {
            CP_WAITN(0);
        }
        __syncthreads();

#pragma unroll
        for (int ks = 0; ks < KS; ks++) {
            uint32_t afr[MI][4], bfr[NI][2];
#pragma unroll
            for (int mi = 0; mi < MI; mi++) {
                uint32_t addr = As_u + (uint32_t)((cur*ASZH + (wm + mi*16 + a_m)*ASTH
                                                   + ks*16 + a_k) * 2);
                ldsm_x4(afr[mi][0], afr[mi][1], afr[mi][2], afr[mi][3], addr);
            }
#pragma unroll
            for (int ni = 0; ni < NI; ni++) {
                uint32_t addr = Bs_u + (uint32_t)((cur*BSZH + (ks*16 + b_k)*BSTH
                                                   + wn + ni*8) * 2);
                ldsm_x2t(bfr[ni][0], bfr[ni][1], addr);
            }
#pragma unroll
            for (int mi = 0; mi < MI; mi++)
#pragma unroll
                for (int ni = 0; ni < NI; ni++)
                    mma_f16(acc[mi][ni], afr[mi], bfr[ni]);
        }
        __syncthreads();
    }

#pragma unroll
    for (int mi = 0; mi < MI; mi++)
#pragma unroll
        for (int ni = 0; ni < NI; ni++) {
            const int r0 = row0 + wm + mi*16 + (lane >> 2);
            const int c0 = col0 + wn + ni*8 + 2*(lane & 3);
#pragma unroll
            for (int half = 0; half < 2; half++) {
                const int rr = r0 + half*8;
#pragma unroll
                for (int e = 0; e < 2; e++) {
                    const int nn = c0 + e;
                    C[(size_t)rr*N + nn] = acc[mi][ni][half*2 + e] + bias[nn];
                }
            }
        }
}

// ---------------- persistent fp16 LSTM recurrence, weights smem-resident -----
// 128 CTAs x 512 threads. CTA: mt = bid & 1 -> rows [mt*128, +128);
// jt = bid >> 1 -> j-cols [jt*16, +16) across all 4 gates (64 B-cols).
// B slab (1024 x 64 fp16) loaded ONCE into smem; per step only A streams.
// 16 warps = 8 m-rows x 2 n-cols (WM=16, WN=32).
#define FBM 128
#define FBK 64
#define FCOLS 64             // 4 gates x 16 j
#define FASTH (FBK + 8)      // 72 halves: conflict-free ldsm
#define FBSTH (FCOLS + 8)    // 72 halves
#define FEPST (FCOLS + 4)    // 68 floats, ep row stride
#define AS_SZH (FBM * FASTH)         // 9216 halves / stage
#define B_SZH  (HH * FBSTH)          // 73728 halves (147456 B)
#define EP_SZ  (FBM * FEPST)         // 8704 floats (34816 B) - aliases A stages
#define C_SZ   (FBM * 16)            // 2048 floats
#define PSMEM_BYTES (2*AS_SZH*2 + B_SZH*2 + C_SZ*4)   // 36864+147456+8192 = 192512

__global__ void __launch_bounds__(512)
lstm_persistent(const __half* __restrict__ Wr,     // fp16 (HH, 4HH)
                const float* __restrict__ Zx,      // (BB*TT, 4HH) fp32 (+bias)
                float* __restrict__ hseq,
                __half* __restrict__ ht0, __half* __restrict__ ht1,
                const float* __restrict__ pi, const float* __restrict__ pf,
                const float* __restrict__ po)
{
    extern __shared__ __half dsh[];
    __half* As   = dsh;                       // [2][AS_SZH]
    __half* Bres = dsh + 2*AS_SZH;            // [B_SZH]  (persistent)
    float*  csm  = (float*)(dsh + 2*AS_SZH + B_SZH);   // [C_SZ]
    float*  ep   = (float*)dsh;               // aliases A stages (safe: see below)
    const uint32_t As_u = (uint32_t)__cvta_generic_to_shared(As);
    const uint32_t Bs_u = (uint32_t)__cvta_generic_to_shared(Bres);

    const int tid = threadIdx.x, lane = tid & 31, warp = tid >> 5;
    const int wm = (warp >> 1) * 16;          // 0..112
    const int wn = (warp & 1) * 32;           // 0 or 32
    const int row0 = (blockIdx.x & 1) * FBM;
    const int j0   = (blockIdx.x >> 1) * 16;

    const int j = tid & 15, jg = j0 + j;
    const int mrow = tid >> 4;                // 0..31
    const float pij = pi[jg], pfj = pf[jg], poj = po[jg];

    // ---- one-time: load the whole B slab (Wr columns for this CTA) ----
    for (int i = tid; i < C_SZ; i += 512) csm[i] = 0.0f;
    {
        constexpr int BQ8 = HH * FCOLS / 8;   // 8192 -> 16/thread
#pragma unroll
        for (int q = tid; q < BQ8; q += 512) {
            int k = q >> 3, ci = q & 7;
            int g = ci >> 1, jj8 = (ci & 1) * 8;
            cp16(&Bres[k*FBSTH + g*16 + jj8],
                 Wr + (size_t)k*(4*HH) + g*HH + j0 + jj8);
        }
        CP_COMMIT;
        CP_WAITN(0);
    }
    __syncthreads();

    constexpr int AQ8 = FBM * FBK / 8;   // 1024 -> 2/thread
    constexpr int KT  = HH / FBK;        // 16

    auto load_A = [&](int st, int kt, const __half* hprev) {
#pragma unroll
        for (int q = tid; q < AQ8; q += 512) {
            int r = q >> 3, c = (q & 7) * 8;
            cp16(&As[st*AS_SZH + r*FASTH + c],
                 hprev + (size_t)(row0 + r)*HH + kt*FBK + c);
        }
    };

    const int a_m = (lane & 7) + ((lane >> 3) & 1) * 8;
    const int a_k = (lane >> 4) * 8;
    const int b_k = (lane & 15);

#pragma unroll 1
    for (int t = 0; t < TT; t++) {
        // prefetch gate inputs into registers (independent of GEMM)
        float zxr[4][4];
#pragma unroll
        for (int s = 0; s < 4; s++) {
            const int b = row0 + s*32 + mrow;
            const size_t zr = ((size_t)b*TT + t) * (4*HH);
#pragma unroll
            for (int g = 0; g < 4; g++)
                zxr[s][g] = Zx[zr + g*HH + jg];
        }

        float acc[4][4];
#pragma unroll
        for (int ni = 0; ni < 4; ni++)
#pragma unroll
            for (int r = 0; r < 4; r++) acc[ni][r] = 0.0f;

        if (t > 0) {
            const __half* hprev = ((t - 1) & 1) ? ht1 : ht0;
            load_A(0, 0, hprev);
            CP_COMMIT;

#pragma unroll 1
            for (int kt = 0; kt < KT; kt++) {
                const int cur = kt & 1;
                if (kt + 1 < KT) {
                    load_A(cur ^ 1, kt + 1, hprev);
                    CP_COMMIT;
                    CP_WAITN(1);
                } else {
                    CP_WAITN(0);
                }
                __syncthreads();

#pragma unroll
                for (int ks = 0; ks < FBK/16; ks++) {
                    uint32_t afr[4], bfr[4][2];
                    {
                        uint32_t addr = As_u + (uint32_t)((cur*AS_SZH
                                          + (wm + a_m)*FASTH + ks*16 + a_k) * 2);
                        ldsm_x4(afr[0], afr[1], afr[2], afr[3], addr);
                    }
                    const int krow = kt*FBK + ks*16 + b_k;
#pragma unroll
                    for (int ni = 0; ni < 4; ni++) {
                        uint32_t addr = Bs_u + (uint32_t)((krow*FBSTH
                                          + wn + ni*8) * 2);
                        ldsm_x2t(bfr[ni][0], bfr[ni][1], addr);
                    }
#pragma unroll
                    for (int ni = 0; ni < 4; ni++)
                        mma_f16(acc[ni], afr, bfr[ni]);
                }
                __syncthreads();
            }
        } else {
            __syncthreads();
        }

        // ---- dump accumulators to ep (aliases A stages; all A reads done) ----
#pragma unroll
        for (int ni = 0; ni < 4; ni++) {
            const int r0 = wm + (lane >> 2);
            const int c0 = wn + ni*8 + 2*(lane & 3);
#pragma unroll
            for (int half = 0; half < 2; half++) {
                ep[(r0 + half*8)*FEPST + c0]     = acc[ni][half*2];
                ep[(r0 + half*8)*FEPST + c0 + 1] = acc[ni][half*2 + 1];
            }
        }
        __syncthreads();

        // ---- gates: each thread handles 4 (m, j) pairs ----
        float* hout   = hseq + (size_t)t*BB*HH;
        __half* htcur = (t & 1) ? ht1 : ht0;
#pragma unroll
        for (int s = 0; s < 4; s++) {
            const int m = s*32 + mrow;
            const int b = row0 + m;

            float zi = ep[m*FEPST +      j] + zxr[s][0];
            float zf = ep[m*FEPST + 16 + j] + zxr[s][1];
            float zc = ep[m*FEPST + 32 + j] + zxr[s][2];
            float zo = ep[m*FEPST + 48 + j] + zxr[s][3];

            float cc = csm[m*16 + j];
            float ig = 1.0f / (1.0f + expf(-(zi + cc*pij)));
            float fg = 1.0f / (1.0f + expf(-(zf + cc*pfj)));
            float cn = fg*cc + ig*tanhf(zc);
            float og = 1.0f / (1.0f + expf(-(zo + cn*poj)));
            float hn = og*tanhf(cn);

            csm[m*16 + j] = cn;
            hout[(size_t)b*HH + jg]  = hn;
            htcur[(size_t)b*HH + jg] = __float2half(hn);
        }

        // ---- grid barrier (also orders ep reuse vs next-step A loads) ----
        if (t + 1 < TT) {
            __threadfence();
            __syncthreads();
            if (tid == 0) {
                atomicAdd((unsigned*)&g_bar, 1u);
                const unsigned target = 128u * (unsigned)(t + 1);
                while (g_bar < target) __nanosleep(64);
                __threadfence();
            }
            __syncthreads();
        }
    }
}

// ---------------- final BN -> tanh -> Dense(H,10) ----------------------------
__global__ void logits_kernel(const float* __restrict__ hseq,
                              const float* __restrict__ g2, const float* __restrict__ b2,
                              const float* __restrict__ m2, const float* __restrict__ v2,
                              const float* __restrict__ Wout, float* __restrict__ out)
{
    int row = blockIdx.x;
    int t = row / BB, b = row % BB;
    int tid = threadIdx.x;

    float a[CC];
#pragma unroll
    for (int c2 = 0; c2 < CC; c2++) a[c2] = 0.0f;

    float4 hv = *(const float4*)(hseq + (size_t)row*HH + tid*4);
    float4 gv = *(const float4*)(g2 + tid*4);
    float4 bv = *(const float4*)(b2 + tid*4);
    float4 mv = *(const float4*)(m2 + tid*4);
    float4 vv = *(const float4*)(v2 + tid*4);

    float h4[4] = {hv.x, hv.y, hv.z, hv.w};
    float G4[4] = {gv.x, gv.y, gv.z, gv.w};
    float B4[4] = {bv.x, bv.y, bv.z, bv.w};
    float M4[4] = {mv.x, mv.y, mv.z, mv.w};
    float V4[4] = {vv.x, vv.y, vv.z, vv.w};

#pragma unroll
    for (int s = 0; s < 4; s++) {
        int k = tid*4 + s;
        float y = tanhf((h4[s] - M4[s]) * rsqrtf(V4[s] + BN_EPS) * G4[s] + B4[s]);
        const float* wr = Wout + (size_t)k*CC;
#pragma unroll
        for (int c2 = 0; c2 < CC; c2++)
            a[c2] = fmaf(y, wr[c2], a[c2]);
    }

#pragma unroll
    for (int off = 16; off > 0; off >>= 1)
#pragma unroll
        for (int c2 = 0; c2 < CC; c2++)
            a[c2] += __shfl_down_sync(0xffffffffu, a[c2], off);

    __shared__ float sacc[CC];
    if (tid < CC) sacc[tid] = 0.0f;
    __syncthreads();
    if ((tid & 31) == 0)
#pragma unroll
        for (int c2 = 0; c2 < CC; c2++) atomicAdd(&sacc[c2], a[c2]);
    __syncthreads();
    if (tid < CC)
        out[((size_t)b*TT + t)*CC + tid] = sacc[tid];
}

// ---------------- launcher ----------------------------------------------------
extern "C" void kernel_launch(void* const* d_in, const int* in_sizes, int n_in,
                              void* d_out, int out_size)
{
    const float* x      = (const float*)d_in[0];
    const float* W_fe   = (const float*)d_in[1];
    const float* b_fe   = (const float*)d_in[2];
    const float* gamma1 = (const float*)d_in[3];
    const float* beta1  = (const float*)d_in[4];
    const float* mean1  = (const float*)d_in[5];
    const float* var1   = (const float*)d_in[6];
    const float* Wg     = (const float*)d_in[7];
    const float* Wr     = (const float*)d_in[8];
    const float* bias   = (const float*)d_in[9];
    const float* pi     = (const float*)d_in[10];
    const float* pf     = (const float*)d_in[11];
    const float* po     = (const float*)d_in[12];
    const float* gamma2 = (const float*)d_in[13];
    const float* beta2  = (const float*)d_in[14];
    const float* mean2  = (const float*)d_in[15];
    const float* var2   = (const float*)d_in[16];
    const float* W_out  = (const float*)d_in[17];
    float* out = (float*)d_out;

    __half *feat, *wg, *wrt, *ht;
    float *zx, *hseq, *wfe;
    cudaGetSymbolAddress((void**)&feat, g_feat);
    cudaGetSymbolAddress((void**)&zx,   g_zx);
    cudaGetSymbolAddress((void**)&hseq, g_hseq);
    cudaGetSymbolAddress((void**)&wfe,  g_wfe);
    cudaGetSymbolAddress((void**)&wg,   g_wg);
    cudaGetSymbolAddress((void**)&wrt,  g_wrt);
    cudaGetSymbolAddress((void**)&ht,   g_ht);
    __half* ht0 = ht;
    __half* ht1 = ht + (size_t)BB * HH;

    constexpr int G1_SMEM = (2*256*20 + 2*16*136) * 4;            // 58368 B
    constexpr int G2_SMEM = (2*256*40 + 2*32*136) * 2;            // 58368 B
    cudaFuncSetAttribute(gemm1_tf32, cudaFuncAttributeMaxDynamicSharedMemorySize, G1_SMEM);
    cudaFuncSetAttribute(gemm2_f16,  cudaFuncAttributeMaxDynamicSharedMemorySize, G2_SMEM);
    cudaFuncSetAttribute(lstm_persistent,
                         cudaFuncAttributeMaxDynamicSharedMemorySize, PSMEM_BYTES);

    init_kernel<<<1, 32>>>();

    // preprocess weights
    {
        int n = FF*HH/4;
        round_tf32_kernel<<<(n+255)/256, 256>>>((const float4*)W_fe, (float4*)wfe, n);
        int n2 = HH*4*HH/2;
        f32_to_f16_kernel<<<(n2+255)/256, 256>>>((const float2*)Wg, (__half2*)wg, n2);
        f32_to_f16_kernel<<<(n2+255)/256, 256>>>((const float2*)Wr, (__half2*)wrt, n2);
    }

    // 1) feat (fp16) = tanh(BN(tanh(x @ W_fe + b_fe)))
    {
        dim3 grid(HH/128, M1/256);
        gemm1_tf32<<<grid, 512, G1_SMEM>>>(x, wfe, feat, M1, HH, FF,
                                           b_fe, gamma1, beta1, mean1, var1);
    }
    // 2) Zx = feat @ Wg + bias  (fp16 operands, fp32 out)
    {
        dim3 grid(4*HH/128, M1/256);
        gemm2_f16<<<grid, 512, G2_SMEM>>>(feat, wg, zx, M1, 4*HH, HH, bias);
    }
    // 3) recurrence (fp16 operands, B smem-resident)
    lstm_persistent<<<128, 512, PSMEM_BYTES>>>(wrt, zx, hseq, ht0, ht1, pi, pf, po);
    // 4) logits
    logits_kernel<<<M1, 256>>>(hseq, gamma2, beta2, mean2, var2, W_out, out);
}

// round 12
// speedup vs baseline: 1.7485x; 1.0454x over previous
#include <cuda_runtime.h>
#include <cuda_fp16.h>
#include <math.h>
#include <stdint.h>

// ---------------- problem constants ----------------
#define BB 256
#define TT 128
#define FF 784
#define HH 1024
#define CC 10
#define M1 (BB*TT)
#define BN_EPS 1e-3f

// ---------------- scratch (device globals) ----------------
__device__ __half g_feat[(size_t)M1 * HH];         // fp16 feat
__device__ float  g_zx  [(size_t)M1 * 4 * HH];     // fp32 Zx (+bias)
__device__ float  g_hseq[(size_t)M1 * HH];         // fp32 h (T,B,H)
__device__ __half g_ht  [2][(size_t)BB * HH];      // fp16 h ping-pong
__device__ float  g_wfe [(size_t)FF * HH];         // tf32-rounded W_fe
__device__ __half g_wg  [(size_t)HH * 4 * HH];     // fp16 kernel
__device__ __half g_wrt [(size_t)HH * 4 * HH];     // fp16 rec_kernel
__device__ volatile unsigned g_bar;

// ---------------- helpers ----------------
__device__ __forceinline__ uint32_t f2tf(float f) {
    uint32_t u;
    asm("cvt.rna.tf32.f32 %0, %1;" : "=r"(u) : "f"(f));
    return u;
}
__device__ __forceinline__ void cp16(void* dst, const void* src) {
    uint32_t d = (uint32_t)__cvta_generic_to_shared(dst);
    asm volatile("cp.async.cg.shared.global [%0], [%1], 16;" :: "r"(d), "l"(src));
}
#define CP_COMMIT asm volatile("cp.async.commit_group;")
#define CP_WAITN(n) asm volatile("cp.async.wait_group %0;" :: "n"(n))

__device__ __forceinline__ void mma_tf32(float* d, const uint32_t* a, const uint32_t* b) {
    asm volatile(
        "mma.sync.aligned.m16n8k8.row.col.f32.tf32.tf32.f32 "
        "{%0,%1,%2,%3}, {%4,%5,%6,%7}, {%8,%9}, {%0,%1,%2,%3};"
        : "+f"(d[0]), "+f"(d[1]), "+f"(d[2]), "+f"(d[3])
        : "r"(a[0]), "r"(a[1]), "r"(a[2]), "r"(a[3]),
          "r"(b[0]), "r"(b[1]));
}
__device__ __forceinline__ void mma_f16(float* d, const uint32_t* a, const uint32_t* b) {
    asm volatile(
        "mma.sync.aligned.m16n8k16.row.col.f32.f16.f16.f32 "
        "{%0,%1,%2,%3}, {%4,%5,%6,%7}, {%8,%9}, {%0,%1,%2,%3};"
        : "+f"(d[0]), "+f"(d[1]), "+f"(d[2]), "+f"(d[3])
        : "r"(a[0]), "r"(a[1]), "r"(a[2]), "r"(a[3]),
          "r"(b[0]), "r"(b[1]));
}
__device__ __forceinline__ void ldsm_x4(uint32_t& r0, uint32_t& r1, uint32_t& r2,
                                        uint32_t& r3, uint32_t addr) {
    asm volatile("ldmatrix.sync.aligned.m8n8.x4.shared.b16 {%0,%1,%2,%3}, [%4];"
        : "=r"(r0), "=r"(r1), "=r"(r2), "=r"(r3) : "r"(addr));
}
// x4 trans: loads a 16x16 fp16 tile transposed -> B fragments for TWO n8 tiles
__device__ __forceinline__ void ldsm_x4t(uint32_t& r0, uint32_t& r1, uint32_t& r2,
                                         uint32_t& r3, uint32_t addr) {
    asm volatile("ldmatrix.sync.aligned.m8n8.x4.trans.shared.b16 {%0,%1,%2,%3}, [%4];"
        : "=r"(r0), "=r"(r1), "=r"(r2), "=r"(r3) : "r"(addr));
}

__global__ void init_kernel() {
    if (threadIdx.x == 0 && blockIdx.x == 0) g_bar = 0u;
}
__global__ void round_tf32_kernel(const float4* __restrict__ in,
                                  float4* __restrict__ out, int n4) {
    int i = blockIdx.x * blockDim.x + threadIdx.x;
    if (i < n4) {
        float4 v = in[i];
        float4 o;
        o.x = __uint_as_float(f2tf(v.x));
        o.y = __uint_as_float(f2tf(v.y));
        o.z = __uint_as_float(f2tf(v.z));
        o.w = __uint_as_float(f2tf(v.w));
        out[i] = o;
    }
}
__global__ void f32_to_f16_kernel(const float2* __restrict__ in,
                                  __half2* __restrict__ out, int n2) {
    int i = blockIdx.x * blockDim.x + threadIdx.x;
    if (i < n2) {
        float2 v = in[i];
        out[i] = __floats2half2_rn(v.x, v.y);
    }
}

// ---------------- tf32 GEMM 1 (featurizer): x fp32 -> feat fp16 --------------
__global__ void __launch_bounds__(512)
gemm1_tf32(const float* __restrict__ A, const float* __restrict__ B,
           __half* __restrict__ C, int M, int N, int K,
           const float* __restrict__ p0, const float* __restrict__ p1,
           const float* __restrict__ p2, const float* __restrict__ p3,
           const float* __restrict__ p4)
{
    constexpr int BM = 256, BN = 128, BK = 16, WM = 64, WN = 32;
    constexpr int MI = WM/16, NI = WN/8, KS = BK/8;
    constexpr int AST = BK + 4, BST = BN + 8;
    constexpr int AQ = BM*BK/4, BQ = BK*BN/4;
    constexpr int ASZ = BM*AST, BSZ = BK*BST;

    extern __shared__ float sm[];
    float* As = sm;
    float* Bs = sm + 2*ASZ;

    const int tid = threadIdx.x, lane = tid & 31, warp = tid >> 5;
    const int wm = (warp / (BN/WN)) * WM, wn = (warp % (BN/WN)) * WN;
    const int row0 = blockIdx.y * BM, col0 = blockIdx.x * BN;

    float acc[MI][NI][4];
#pragma unroll
    for (int mi = 0; mi < MI; mi++)
#pragma unroll
        for (int ni = 0; ni < NI; ni++)
#pragma unroll
            for (int r = 0; r < 4; r++) acc[mi][ni][r] = 0.0f;

    const int KT = K / BK;
#pragma unroll
    for (int q = tid; q < AQ; q += 512) {
        int r = q / (BK/4), c = (q % (BK/4)) * 4;
        cp16(&As[r*AST + c], A + (size_t)(row0 + r)*K + c);
    }
#pragma unroll
    for (int q = tid; q < BQ; q += 512) {
        int r = q / (BN/4), c = (q % (BN/4)) * 4;
        cp16(&Bs[r*BST + c], B + (size_t)r*N + col0 + c);
    }
    CP_COMMIT;

#pragma unroll 1
    for (int kt = 0; kt < KT; kt++) {
        const int cur = kt & 1;
        if (kt + 1 < KT) {
            const int k0 = (kt + 1)*BK, nxt = cur ^ 1;
#pragma unroll
            for (int q = tid; q < AQ; q += 512) {
                int r = q / (BK/4), c = (q % (BK/4)) * 4;
                cp16(&As[nxt*ASZ + r*AST + c], A + (size_t)(row0 + r)*K + k0 + c);
            }
#pragma unroll
            for (int q = tid; q < BQ; q += 512) {
                int r = q / (BN/4), c = (q % (BN/4)) * 4;
                cp16(&Bs[nxt*BSZ + r*BST + c], B + (size_t)(k0 + r)*N + col0 + c);
            }
            CP_COMMIT;
            CP_WAITN(1);
        } else {
            CP_WAITN(0);
        }
        __syncthreads();

#pragma unroll
        for (int ks = 0; ks < KS; ks++) {
            uint32_t afr[MI][4], bfr[NI][2];
            const int ar = lane >> 2, ac = ks*8 + (lane & 3);
#pragma unroll
            for (int mi = 0; mi < MI; mi++) {
                const float* base = &As[cur*ASZ + (wm + mi*16 + ar)*AST + ac];
                afr[mi][0] = f2tf(base[0]);
                afr[mi][1] = f2tf(base[8*AST]);
                afr[mi][2] = f2tf(base[4]);
                afr[mi][3] = f2tf(base[8*AST + 4]);
            }
            const int bk = ks*8 + (lane & 3), bn = lane >> 2;
#pragma unroll
            for (int ni = 0; ni < NI; ni++) {
                const float* base = &Bs[cur*BSZ + bk*BST + wn + ni*8 + bn];
                bfr[ni][0] = __float_as_uint(base[0]);
                bfr[ni][1] = __float_as_uint(base[4*BST]);
            }
#pragma unroll
            for (int mi = 0; mi < MI; mi++)
#pragma unroll
                for (int ni = 0; ni < NI; ni++)
                    mma_tf32(acc[mi][ni], afr[mi], bfr[ni]);
        }
        __syncthreads();
    }

#pragma unroll
    for (int mi = 0; mi < MI; mi++)
#pragma unroll
        for (int ni = 0; ni < NI; ni++) {
            const int r0 = row0 + wm + mi*16 + (lane >> 2);
            const int c0 = col0 + wn + ni*8 + 2*(lane & 3);
#pragma unroll
            for (int half = 0; half < 2; half++) {
                const int rr = r0 + half*8;
#pragma unroll
                for (int e = 0; e < 2; e++) {
                    const int nn = c0 + e;
                    float v = acc[mi][ni][half*2 + e];
                    v = tanhf(v + p0[nn]);
                    v = (v - p3[nn]) * rsqrtf(p4[nn] + BN_EPS) * p1[nn] + p2[nn];
                    v = tanhf(v);
                    C[(size_t)rr*N + nn] = __float2half(v);
                }
            }
        }
}

// ---------------- fp16 GEMM 2: Zx = feat @ Wg + bias -------------------------
// BK=64 (16 K-iterations), x4-trans B loads.
__global__ void __launch_bounds__(512)
gemm2_f16(const __half* __restrict__ A, const __half* __restrict__ B,
          float* __restrict__ C, int M, int N, int K,
          const float* __restrict__ bias)
{
    constexpr int BM = 256, BN = 128, BK = 64, WM = 64, WN = 32;
    constexpr int MI = WM/16, NI = WN/8, KS = BK/16;
    constexpr int ASTH = BK + 8;     // 72
    constexpr int BSTH = BN + 8;     // 136
    constexpr int ASZH = BM*ASTH, BSZH = BK*BSTH;
    constexpr int AQ8 = BM*BK/8, BQ8 = BK*BN/8;

    extern __shared__ __half smh[];
    __half* As = smh;
    __half* Bs = smh + 2*ASZH;
    const uint32_t As_u = (uint32_t)__cvta_generic_to_shared(As);
    const uint32_t Bs_u = (uint32_t)__cvta_generic_to_shared(Bs);

    const int tid = threadIdx.x, lane = tid & 31, warp = tid >> 5;
    const int wm = (warp / (BN/WN)) * WM, wn = (warp % (BN/WN)) * WN;
    const int row0 = blockIdx.y * BM, col0 = blockIdx.x * BN;

    float acc[MI][NI][4];
#pragma unroll
    for (int mi = 0; mi < MI; mi++)
#pragma unroll
        for (int ni = 0; ni < NI; ni++)
#pragma unroll
            for (int r = 0; r < 4; r++) acc[mi][ni][r] = 0.0f;

    const int KT = K / BK;
#pragma unroll
    for (int q = tid; q < AQ8; q += 512) {
        int r = q >> 3, c = (q & 7) * 8;
        cp16(&As[r*ASTH + c], A + (size_t)(row0 + r)*K + c);
    }
#pragma unroll
    for (int q = tid; q < BQ8; q += 512) {
        int r = q >> 4, c = (q & 15) * 8;
        cp16(&Bs[r*BSTH + c], B + (size_t)r*N + col0 + c);
    }
    CP_COMMIT;

    const int a_m = (lane & 7) + ((lane >> 3) & 1) * 8;
    const int a_k = (lane >> 4) * 8;
    const int b_k = lane & 15;            // row within k16
    const int b_c = (lane >> 4) * 8;      // col half within n16

#pragma unroll 1
    for (int kt = 0; kt < KT; kt++) {
        const int cur = kt & 1;
        if (kt + 1 < KT) {
            const int k0 = (kt + 1)*BK, nxt = cur ^ 1;
#pragma unroll
            for (int q = tid; q < AQ8; q += 512) {
                int r = q >> 3, c = (q & 7) * 8;
                cp16(&As[nxt*ASZH + r*ASTH + c], A + (size_t)(row0 + r)*K + k0 + c);
            }
#pragma unroll
            for (int q = tid; q < BQ8; q += 512) {
                int r = q >> 4, c = (q & 15) * 8;
                cp16(&Bs[nxt*BSZH + r*BSTH + c], B + (size_t)(k0 + r)*N + col0 + c);
            }
            CP_COMMIT;
            CP_WAITN(1);
        } else {
            CP_WAITN(0);
        }
        __syncthreads();

#pragma unroll
        for (int ks = 0; ks < KS; ks++) {
            uint32_t afr[MI][4], bfr[NI][2];
#pragma unroll
            for (int mi = 0; mi < MI; mi++) {
                uint32_t addr = As_u + (uint32_t)((cur*ASZH + (wm + mi*16 + a_m)*ASTH
                                                   + ks*16 + a_k) * 2);
                ldsm_x4(afr[mi][0], afr[mi][1], afr[mi][2], afr[mi][3], addr);
            }
#pragma unroll
            for (int n2 = 0; n2 < NI/2; n2++) {
                uint32_t addr = Bs_u + (uint32_t)((cur*BSZH + (ks*16 + b_k)*BSTH
                                                   + wn + n2*16 + b_c) * 2);
                ldsm_x4t(bfr[2*n2][0], bfr[2*n2][1], bfr[2*n2+1][0], bfr[2*n2+1][1], addr);
            }
#pragma unroll
            for (int mi = 0; mi < MI; mi++)
#pragma unroll
                for (int ni = 0; ni < NI; ni++)
                    mma_f16(acc[mi][ni], afr[mi], bfr[ni]);
        }
        __syncthreads();
    }

#pragma unroll
    for (int mi = 0; mi < MI; mi++)
#pragma unroll
        for (int ni = 0; ni < NI; ni++) {
            const int r0 = row0 + wm + mi*16 + (lane >> 2);
            const int c0 = col0 + wn + ni*8 + 2*(lane & 3);
#pragma unroll
            for (int half = 0; half < 2; half++) {
                const int rr = r0 + half*8;
#pragma unroll
                for (int e = 0; e < 2; e++) {
                    const int nn = c0 + e;
                    C[(size_t)rr*N + nn] = acc[mi][ni][half*2 + e] + bias[nn];
                }
            }
        }
}

// ---------------- persistent fp16 LSTM recurrence, weights smem-resident -----
// 128 CTAs x 512 threads. B slab resident; 3-stage A ring, one sync per kt;
// x4-trans B fragment loads.
#define FBM 128
#define FBK 64
#define FCOLS 64
#define FASTH (FBK + 8)      // 72
#define FBSTH (FCOLS + 8)    // 72
#define FEPST (FCOLS + 4)    // 68 floats
#define AS_SZH (FBM * FASTH)          // 9216 halves/stage
#define B_SZH  (HH * FBSTH)           // 73728 halves (147456 B)
#define EP_SZ  (FBM * FEPST)          // 8704 floats (34816 B) aliases A stages
#define C_SZ   (FBM * 16)
#define PSMEM_BYTES (3*AS_SZH*2 + B_SZH*2 + C_SZ*4)   // 55296+147456+8192 = 210944

__global__ void __launch_bounds__(512)
lstm_persistent(const __half* __restrict__ Wr,
                const float* __restrict__ Zx,
                float* __restrict__ hseq,
                __half* __restrict__ ht0, __half* __restrict__ ht1,
                const float* __restrict__ pi, const float* __restrict__ pf,
                const float* __restrict__ po)
{
    extern __shared__ __half dsh[];
    __half* As   = dsh;                        // [3][AS_SZH]
    __half* Bres = dsh + 3*AS_SZH;             // [B_SZH] persistent
    float*  csm  = (float*)(dsh + 3*AS_SZH + B_SZH);
    float*  ep   = (float*)dsh;                // aliases A stages
    const uint32_t As_u = (uint32_t)__cvta_generic_to_shared(As);
    const uint32_t Bs_u = (uint32_t)__cvta_generic_to_shared(Bres);

    const int tid = threadIdx.x, lane = tid & 31, warp = tid >> 5;
    const int wm = (warp >> 1) * 16;
    const int wn = (warp & 1) * 32;
    const int row0 = (blockIdx.x & 1) * FBM;
    const int j0   = (blockIdx.x >> 1) * 16;

    const int j = tid & 15, jg = j0 + j;
    const int mrow = tid >> 4;
    const float pij = pi[jg], pfj = pf[jg], poj = po[jg];

    for (int i = tid; i < C_SZ; i += 512) csm[i] = 0.0f;
    {
        constexpr int BQ8 = HH * FCOLS / 8;
#pragma unroll
        for (int q = tid; q < BQ8; q += 512) {
            int k = q >> 3, ci = q & 7;
            int g = ci >> 1, jj8 = (ci & 1) * 8;
            cp16(&Bres[k*FBSTH + g*16 + jj8],
                 Wr + (size_t)k*(4*HH) + g*HH + j0 + jj8);
        }
        CP_COMMIT;
        CP_WAITN(0);
    }
    __syncthreads();

    constexpr int AQ8 = FBM * FBK / 8;
    constexpr int KT  = HH / FBK;        // 16

    auto load_A = [&](int st, int kt, const __half* hprev) {
#pragma unroll
        for (int q = tid; q < AQ8; q += 512) {
            int r = q >> 3, c = (q & 7) * 8;
            cp16(&As[st*AS_SZH + r*FASTH + c],
                 hprev + (size_t)(row0 + r)*HH + kt*FBK + c);
        }
    };

    const int a_m = (lane & 7) + ((lane >> 3) & 1) * 8;
    const int a_k = (lane >> 4) * 8;
    const int b_k = lane & 15;
    const int b_c = (lane >> 4) * 8;

#pragma unroll 1
    for (int t = 0; t < TT; t++) {
        float zxr[4][4];
#pragma unroll
        for (int s = 0; s < 4; s++) {
            const int b = row0 + s*32 + mrow;
            const size_t zr = ((size_t)b*TT + t) * (4*HH);
#pragma unroll
            for (int g = 0; g < 4; g++)
                zxr[s][g] = Zx[zr + g*HH + jg];
        }

        float acc[4][4];
#pragma unroll
        for (int ni = 0; ni < 4; ni++)
#pragma unroll
            for (int r = 0; r < 4; r++) acc[ni][r] = 0.0f;

        if (t > 0) {
            const __half* hprev = ((t - 1) & 1) ? ht1 : ht0;
            load_A(0, 0, hprev);
            CP_COMMIT;
            load_A(1, 1, hprev);
            CP_COMMIT;

#pragma unroll 1
            for (int kt = 0; kt < KT; kt++) {
                const int cur = kt % 3;
                if (kt + 1 < KT) { CP_WAITN(1); } else { CP_WAITN(0); }
                __syncthreads();   // visibility of A[kt] + protects slot (kt+2)%3

                if (kt + 2 < KT) {
                    load_A((kt + 2) % 3, kt + 2, hprev);
                    CP_COMMIT;
                }

#pragma unroll
                for (int ks = 0; ks < FBK/16; ks++) {
                    uint32_t afr[4], bfr[4][2];
                    {
                        uint32_t addr = As_u + (uint32_t)((cur*AS_SZH
                                          + (wm + a_m)*FASTH + ks*16 + a_k) * 2);
                        ldsm_x4(afr[0], afr[1], afr[2], afr[3], addr);
                    }
                    const int krow = kt*FBK + ks*16 + b_k;
#pragma unroll
                    for (int n2 = 0; n2 < 2; n2++) {
                        uint32_t addr = Bs_u + (uint32_t)((krow*FBSTH
                                          + wn + n2*16 + b_c) * 2);
                        ldsm_x4t(bfr[2*n2][0], bfr[2*n2][1],
                                 bfr[2*n2+1][0], bfr[2*n2+1][1], addr);
                    }
#pragma unroll
                    for (int ni = 0; ni < 4; ni++)
                        mma_f16(acc[ni], afr, bfr[ni]);
                }
            }
        }
        __syncthreads();   // all MMA smem reads done; ep (alias of As) safe

        // ---- dump accumulators to ep ----
#pragma unroll
        for (int ni = 0; ni < 4; ni++) {
            const int r0 = wm + (lane >> 2);
            const int c0 = wn + ni*8 + 2*(lane & 3);
#pragma unroll
            for (int half = 0; half < 2; half++) {
                ep[(r0 + half*8)*FEPST + c0]     = acc[ni][half*2];
                ep[(r0 + half*8)*FEPST + c0 + 1] = acc[ni][half*2 + 1];
            }
        }
        __syncthreads();

        // ---- gates ----
        float* hout   = hseq + (size_t)t*BB*HH;
        __half* htcur = (t & 1) ? ht1 : ht0;
#pragma unroll
        for (int s = 0; s < 4; s++) {
            const int m = s*32 + mrow;
            const int b = row0 + m;

            float zi = ep[m*FEPST +      j] + zxr[s][0];
            float zf = ep[m*FEPST + 16 + j] + zxr[s][1];
            float zc = ep[m*FEPST + 32 + j] + zxr[s][2];
            float zo = ep[m*FEPST + 48 + j] + zxr[s][3];

            float cc = csm[m*16 + j];
            float ig = 1.0f / (1.0f + expf(-(zi + cc*pij)));
            float fg = 1.0f / (1.0f + expf(-(zf + cc*pfj)));
            float cn = fg*cc + ig*tanhf(zc);
            float og = 1.0f / (1.0f + expf(-(zo + cn*poj)));
            float hn = og*tanhf(cn);

            csm[m*16 + j] = cn;
            hout[(size_t)b*HH + jg]  = hn;
            htcur[(size_t)b*HH + jg] = __float2half(hn);
        }

        // ---- grid barrier ----
        if (t + 1 < TT) {
            __threadfence();
            __syncthreads();
            if (tid == 0) {
                atomicAdd((unsigned*)&g_bar, 1u);
                const unsigned target = 128u * (unsigned)(t + 1);
                while (g_bar < target) { }
                __threadfence();
            }
            __syncthreads();
        }
    }
}

// ---------------- final BN -> tanh -> Dense(H,10) ----------------------------
__global__ void logits_kernel(const float* __restrict__ hseq,
                              const float* __restrict__ g2, const float* __restrict__ b2,
                              const float* __restrict__ m2, const float* __restrict__ v2,
                              const float* __restrict__ Wout, float* __restrict__ out)
{
    int row = blockIdx.x;
    int t = row / BB, b = row % BB;
    int tid = threadIdx.x;

    float a[CC];
#pragma unroll
    for (int c2 = 0; c2 < CC; c2++) a[c2] = 0.0f;

    float4 hv = *(const float4*)(hseq + (size_t)row*HH + tid*4);
    float4 gv = *(const float4*)(g2 + tid*4);
    float4 bv = *(const float4*)(b2 + tid*4);
    float4 mv = *(const float4*)(m2 + tid*4);
    float4 vv = *(const float4*)(v2 + tid*4);

    float h4[4] = {hv.x, hv.y, hv.z, hv.w};
    float G4[4] = {gv.x, gv.y, gv.z, gv.w};
    float B4[4] = {bv.x, bv.y, bv.z, bv.w};
    float M4[4] = {mv.x, mv.y, mv.z, mv.w};
    float V4[4] = {vv.x, vv.y, vv.z, vv.w};

#pragma unroll
    for (int s = 0; s < 4; s++) {
        int k = tid*4 + s;
        float y = tanhf((h4[s] - M4[s]) * rsqrtf(V4[s] + BN_EPS) * G4[s] + B4[s]);
        const float* wr = Wout + (size_t)k*CC;
#pragma unroll
        for (int c2 = 0; c2 < CC; c2++)
            a[c2] = fmaf(y, wr[c2], a[c2]);
    }

#pragma unroll
    for (int off = 16; off > 0; off >>= 1)
#pragma unroll
        for (int c2 = 0; c2 < CC; c2++)
            a[c2] += __shfl_down_sync(0xffffffffu, a[c2], off);

    __shared__ float sacc[CC];
    if (tid < CC) sacc[tid] = 0.0f;
    __syncthreads();
    if ((tid & 31) == 0)
#pragma unroll
        for (int c2 = 0; c2 < CC; c2++) atomicAdd(&sacc[c2], a[c2]);
    __syncthreads();
    if (tid < CC)
        out[((size_t)b*TT + t)*CC + tid] = sacc[tid];
}

// ---------------- launcher ----------------------------------------------------
extern "C" void kernel_launch(void* const* d_in, const int* in_sizes, int n_in,
                              void* d_out, int out_size)
{
    const float* x      = (const float*)d_in[0];
    const float* W_fe   = (const float*)d_in[1];
    const float* b_fe   = (const float*)d_in[2];
    const float* gamma1 = (const float*)d_in[3];
    const float* beta1  = (const float*)d_in[4];
    const float* mean1  = (const float*)d_in[5];
    const float* var1   = (const float*)d_in[6];
    const float* Wg     = (const float*)d_in[7];
    const float* Wr     = (const float*)d_in[8];
    const float* bias   = (const float*)d_in[9];
    const float* pi     = (const float*)d_in[10];
    const float* pf     = (const float*)d_in[11];
    const float* po     = (const float*)d_in[12];
    const float* gamma2 = (const float*)d_in[13];
    const float* beta2  = (const float*)d_in[14];
    const float* mean2  = (const float*)d_in[15];
    const float* var2   = (const float*)d_in[16];
    const float* W_out  = (const float*)d_in[17];
    float* out = (float*)d_out;

    __half *feat, *wg, *wrt, *ht;
    float *zx, *hseq, *wfe;
    cudaGetSymbolAddress((void**)&feat, g_feat);
    cudaGetSymbolAddress((void**)&zx,   g_zx);
    cudaGetSymbolAddress((void**)&hseq, g_hseq);
    cudaGetSymbolAddress((void**)&wfe,  g_wfe);
    cudaGetSymbolAddress((void**)&wg,   g_wg);
    cudaGetSymbolAddress((void**)&wrt,  g_wrt);
    cudaGetSymbolAddress((void**)&ht,   g_ht);
    __half* ht0 = ht;
    __half* ht1 = ht + (size_t)BB * HH;

    constexpr int G1_SMEM = (2*256*20 + 2*16*136) * 4;            // 58368 B
    constexpr int G2_SMEM = (2*256*72 + 2*64*136) * 2;            // 108544 B
    cudaFuncSetAttribute(gemm1_tf32, cudaFuncAttributeMaxDynamicSharedMemorySize, G1_SMEM);
    cudaFuncSetAttribute(gemm2_f16,  cudaFuncAttributeMaxDynamicSharedMemorySize, G2_SMEM);
    cudaFuncSetAttribute(lstm_persistent,
                         cudaFuncAttributeMaxDynamicSharedMemorySize, PSMEM_BYTES);

    init_kernel<<<1, 32>>>();

    // preprocess weights
    {
        int n = FF*HH/4;
        round_tf32_kernel<<<(n+255)/256, 256>>>((const float4*)W_fe, (float4*)wfe, n);
        int n2 = HH*4*HH/2;
        f32_to_f16_kernel<<<(n2+255)/256, 256>>>((const float2*)Wg, (__half2*)wg, n2);
        f32_to_f16_kernel<<<(n2+255)/256, 256>>>((const float2*)Wr, (__half2*)wrt, n2);
    }

    // 1) feat (fp16) = tanh(BN(tanh(x @ W_fe + b_fe)))
    {
        dim3 grid(HH/128, M1/256);
        gemm1_tf32<<<grid, 512, G1_SMEM>>>(x, wfe, feat, M1, HH, FF,
                                           b_fe, gamma1, beta1, mean1, var1);
    }
    // 2) Zx = feat @ Wg + bias
    {
        dim3 grid(4*HH/128, M1/256);
        gemm2_f16<<<grid, 512, G2_SMEM>>>(feat, wg, zx, M1, 4*HH, HH, bias);
    }
    // 3) recurrence (fp16, B smem-resident, 3-stage A)
    lstm_persistent<<<128, 512, PSMEM_BYTES>>>(wrt, zx, hseq, ht0, ht1, pi, pf, po);
    // 4) logits
    logits_kernel<<<M1, 256>>>(hseq, gamma2, beta2, mean2, var2, W_out, out);
}

// round 13
// speedup vs baseline: 1.8614x; 1.0646x over previous
#include <cuda_runtime.h>
#include <cuda_fp16.h>
#include <math.h>
#include <stdint.h>

// ---------------- problem constants ----------------
#define BB 256
#define TT 128
#define FF 784
#define FFP 832              // FF padded to multiple of 64
#define HH 1024
#define CC 10
#define M1 (BB*TT)
#define BN_EPS 1e-3f

// ---------------- scratch (device globals) ----------------
__device__ __half g_xh  [(size_t)M1 * FFP];        // fp16 x, K-padded
__device__ __half g_wfe [(size_t)FFP * HH];        // fp16 W_fe, K-padded
__device__ __half g_feat[(size_t)M1 * HH];         // fp16 feat
__device__ float  g_zx  [(size_t)M1 * 4 * HH];     // fp32 Zx (+bias)
__device__ __half g_hseq[(size_t)M1 * HH];         // fp16 h (T,B,H)
__device__ __half g_wg  [(size_t)HH * 4 * HH];     // fp16 kernel
__device__ __half g_wrt [(size_t)HH * 4 * HH];     // fp16 rec_kernel
__device__ volatile unsigned g_bar;

// ---------------- helpers ----------------
__device__ __forceinline__ void cp16(void* dst, const void* src) {
    uint32_t d = (uint32_t)__cvta_generic_to_shared(dst);
    asm volatile("cp.async.cg.shared.global [%0], [%1], 16;" :: "r"(d), "l"(src));
}
#define CP_COMMIT asm volatile("cp.async.commit_group;")
#define CP_WAITN(n) asm volatile("cp.async.wait_group %0;" :: "n"(n))

__device__ __forceinline__ void mma_f16(float* d, const uint32_t* a, const uint32_t* b) {
    asm volatile(
        "mma.sync.aligned.m16n8k16.row.col.f32.f16.f16.f32 "
        "{%0,%1,%2,%3}, {%4,%5,%6,%7}, {%8,%9}, {%0,%1,%2,%3};"
        : "+f"(d[0]), "+f"(d[1]), "+f"(d[2]), "+f"(d[3])
        : "r"(a[0]), "r"(a[1]), "r"(a[2]), "r"(a[3]),
          "r"(b[0]), "r"(b[1]));
}
__device__ __forceinline__ void ldsm_x4(uint32_t& r0, uint32_t& r1, uint32_t& r2,
                                        uint32_t& r3, uint32_t addr) {
    asm volatile("ldmatrix.sync.aligned.m8n8.x4.shared.b16 {%0,%1,%2,%3}, [%4];"
        : "=r"(r0), "=r"(r1), "=r"(r2), "=r"(r3) : "r"(addr));
}
__device__ __forceinline__ void ldsm_x4t(uint32_t& r0, uint32_t& r1, uint32_t& r2,
                                         uint32_t& r3, uint32_t addr) {
    asm volatile("ldmatrix.sync.aligned.m8n8.x4.trans.shared.b16 {%0,%1,%2,%3}, [%4];"
        : "=r"(r0), "=r"(r1), "=r"(r2), "=r"(r3) : "r"(addr));
}

__global__ void init_kernel() {
    if (threadIdx.x == 0 && blockIdx.x == 0) g_bar = 0u;
}
__global__ void f32_to_f16_kernel(const float2* __restrict__ in,
                                  __half2* __restrict__ out, int n2) {
    int i = blockIdx.x * blockDim.x + threadIdx.x;
    if (i < n2) {
        float2 v = in[i];
        out[i] = __floats2half2_rn(v.x, v.y);
    }
}
// pad-convert: out[r, 0..FFP) = (c < K_src) ? fp16(in[r*K_src + c]) : 0
__global__ void pad_f16_kernel(const float* __restrict__ in,
                               __half* __restrict__ out, int rows, int ksrc) {
    int idx = blockIdx.x * blockDim.x + threadIdx.x;
    int total = rows * FFP;
    if (idx < total) {
        int r = idx / FFP, c = idx % FFP;
        out[idx] = (c < ksrc) ? __float2half(in[(size_t)r * ksrc + c]) : __half(0.0f);
    }
}

// ---------------- fp16 GEMM (both time-parallel GEMMs) -----------------------
// BM=256 BN=128 BK=64, 512 threads (WM=64, WN=32), ldmatrix + m16n8k16.
// EPI 1: feat epilogue tanh,BN,tanh -> __half C (p0=b_fe,p1=g1,p2=beta1,p3=m1,p4=v1)
// EPI 2: +bias -> float C (p0=bias)
template<int EPI>
__global__ void __launch_bounds__(512)
gemm_f16(const __half* __restrict__ A, const __half* __restrict__ B,
         void* __restrict__ Cv, int M, int N, int K,
         const float* __restrict__ p0, const float* __restrict__ p1,
         const float* __restrict__ p2, const float* __restrict__ p3,
         const float* __restrict__ p4)
{
    constexpr int BM = 256, BN = 128, BK = 64, WM = 64, WN = 32;
    constexpr int MI = WM/16, NI = WN/8, KS = BK/16;
    constexpr int ASTH = BK + 8;     // 72
    constexpr int BSTH = BN + 8;     // 136
    constexpr int ASZH = BM*ASTH, BSZH = BK*BSTH;
    constexpr int AQ8 = BM*BK/8, BQ8 = BK*BN/8;

    extern __shared__ __half smh[];
    __half* As = smh;
    __half* Bs = smh + 2*ASZH;
    const uint32_t As_u = (uint32_t)__cvta_generic_to_shared(As);
    const uint32_t Bs_u = (uint32_t)__cvta_generic_to_shared(Bs);

    const int tid = threadIdx.x, lane = tid & 31, warp = tid >> 5;
    const int wm = (warp / (BN/WN)) * WM, wn = (warp % (BN/WN)) * WN;
    const int row0 = blockIdx.y * BM, col0 = blockIdx.x * BN;

    float acc[MI][NI][4];
#pragma unroll
    for (int mi = 0; mi < MI; mi++)
#pragma unroll
        for (int ni = 0; ni < NI; ni++)
#pragma unroll
            for (int r = 0; r < 4; r++) acc[mi][ni][r] = 0.0f;

    const int KT = K / BK;
#pragma unroll
    for (int q = tid; q < AQ8; q += 512) {
        int r = q >> 3, c = (q & 7) * 8;
        cp16(&As[r*ASTH + c], A + (size_t)(row0 + r)*K + c);
    }
#pragma unroll
    for (int q = tid; q < BQ8; q += 512) {
        int r = q >> 4, c = (q & 15) * 8;
        cp16(&Bs[r*BSTH + c], B + (size_t)r*N + col0 + c);
    }
    CP_COMMIT;

    const int a_m = (lane & 7) + ((lane >> 3) & 1) * 8;
    const int a_k = (lane >> 4) * 8;
    const int b_k = lane & 15;
    const int b_c = (lane >> 4) * 8;

#pragma unroll 1
    for (int kt = 0; kt < KT; kt++) {
        const int cur = kt & 1;
        if (kt + 1 < KT) {
            const int k0 = (kt + 1)*BK, nxt = cur ^ 1;
#pragma unroll
            for (int q = tid; q < AQ8; q += 512) {
                int r = q >> 3, c = (q & 7) * 8;
                cp16(&As[nxt*ASZH + r*ASTH + c], A + (size_t)(row0 + r)*K + k0 + c);
            }
#pragma unroll
            for (int q = tid; q < BQ8; q += 512) {
                int r = q >> 4, c = (q & 15) * 8;
                cp16(&Bs[nxt*BSZH + r*BSTH + c], B + (size_t)(k0 + r)*N + col0 + c);
            }
            CP_COMMIT;
            CP_WAITN(1);
        } else {
            CP_WAITN(0);
        }
        __syncthreads();

#pragma unroll
        for (int ks = 0; ks < KS; ks++) {
            uint32_t afr[MI][4], bfr[NI][2];
#pragma unroll
            for (int mi = 0; mi < MI; mi++) {
                uint32_t addr = As_u + (uint32_t)((cur*ASZH + (wm + mi*16 + a_m)*ASTH
                                                   + ks*16 + a_k) * 2);
                ldsm_x4(afr[mi][0], afr[mi][1], afr[mi][2], afr[mi][3], addr);
            }
#pragma unroll
            for (int n2 = 0; n2 < NI/2; n2++) {
                uint32_t addr = Bs_u + (uint32_t)((cur*BSZH + (ks*16 + b_k)*BSTH
                                                   + wn + n2*16 + b_c) * 2);
                ldsm_x4t(bfr[2*n2][0], bfr[2*n2][1], bfr[2*n2+1][0], bfr[2*n2+1][1], addr);
            }
#pragma unroll
            for (int mi = 0; mi < MI; mi++)
#pragma unroll
                for (int ni = 0; ni < NI; ni++)
                    mma_f16(acc[mi][ni], afr[mi], bfr[ni]);
        }
        __syncthreads();
    }

#pragma unroll
    for (int mi = 0; mi < MI; mi++)
#pragma unroll
        for (int ni = 0; ni < NI; ni++) {
            const int r0 = row0 + wm + mi*16 + (lane >> 2);
            const int c0 = col0 + wn + ni*8 + 2*(lane & 3);
#pragma unroll
            for (int half = 0; half < 2; half++) {
                const int rr = r0 + half*8;
#pragma unroll
                for (int e = 0; e < 2; e++) {
                    const int nn = c0 + e;
                    float v = acc[mi][ni][half*2 + e];
                    if (EPI == 1) {
                        v = tanhf(v + p0[nn]);
                        v = (v - p3[nn]) * rsqrtf(p4[nn] + BN_EPS) * p1[nn] + p2[nn];
                        v = tanhf(v);
                        ((__half*)Cv)[(size_t)rr*N + nn] = __float2half(v);
                    } else {
                        ((float*)Cv)[(size_t)rr*N + nn] = v + p0[nn];
                    }
                }
            }
        }
}

// ---------------- persistent fp16 LSTM recurrence, weights smem-resident -----
#define FBM 128
#define FBK 64
#define FCOLS 64
#define FASTH (FBK + 8)      // 72
#define FBSTH (FCOLS + 8)    // 72
#define FEPST (FCOLS + 4)    // 68 floats
#define AS_SZH (FBM * FASTH)          // 9216 halves/stage
#define B_SZH  (HH * FBSTH)           // 73728 halves (147456 B)
#define EP_SZ  (FBM * FEPST)          // aliases A stages
#define C_SZ   (FBM * 16)
#define PSMEM_BYTES (3*AS_SZH*2 + B_SZH*2 + C_SZ*4)   // 210944

__global__ void __launch_bounds__(512)
lstm_persistent(const __half* __restrict__ Wr,
                const float* __restrict__ Zx,
                __half* __restrict__ hseq,        // (TT, BB, HH) fp16
                const float* __restrict__ pi, const float* __restrict__ pf,
                const float* __restrict__ po)
{
    extern __shared__ __half dsh[];
    __half* As   = dsh;                        // [3][AS_SZH]
    __half* Bres = dsh + 3*AS_SZH;             // [B_SZH] persistent
    float*  csm  = (float*)(dsh + 3*AS_SZH + B_SZH);
    float*  ep   = (float*)dsh;                // aliases A stages
    const uint32_t As_u = (uint32_t)__cvta_generic_to_shared(As);
    const uint32_t Bs_u = (uint32_t)__cvta_generic_to_shared(Bres);

    const int tid = threadIdx.x, lane = tid & 31, warp = tid >> 5;
    const int wm = (warp >> 1) * 16;
    const int wn = (warp & 1) * 32;
    const int row0 = (blockIdx.x & 1) * FBM;
    const int j0   = (blockIdx.x >> 1) * 16;

    const int j = tid & 15, jg = j0 + j;
    const int mrow = tid >> 4;
    const float pij = pi[jg], pfj = pf[jg], poj = po[jg];

    for (int i = tid; i < C_SZ; i += 512) csm[i] = 0.0f;
    {
        constexpr int BQ8 = HH * FCOLS / 8;
#pragma unroll
        for (int q = tid; q < BQ8; q += 512) {
            int k = q >> 3, ci = q & 7;
            int g = ci >> 1, jj8 = (ci & 1) * 8;
            cp16(&Bres[k*FBSTH + g*16 + jj8],
                 Wr + (size_t)k*(4*HH) + g*HH + j0 + jj8);
        }
        CP_COMMIT;
        CP_WAITN(0);
    }
    __syncthreads();

    constexpr int AQ8 = FBM * FBK / 8;
    constexpr int KT  = HH / FBK;        // 16

    auto load_A = [&](int st, int kt, const __half* hprev) {
#pragma unroll
        for (int q = tid; q < AQ8; q += 512) {
            int r = q >> 3, c = (q & 7) * 8;
            cp16(&As[st*AS_SZH + r*FASTH + c],
                 hprev + (size_t)(row0 + r)*HH + kt*FBK + c);
        }
    };

    const int a_m = (lane & 7) + ((lane >> 3) & 1) * 8;
    const int a_k = (lane >> 4) * 8;
    const int b_k = lane & 15;
    const int b_c = (lane >> 4) * 8;

    // gate-input registers for the CURRENT step (prefetched at previous tail)
    float zxr[4][4];
#pragma unroll
    for (int s = 0; s < 4; s++) {
        const int b = row0 + s*32 + mrow;
        const size_t zr = (size_t)b*TT * (4*HH);
#pragma unroll
        for (int g = 0; g < 4; g++)
            zxr[s][g] = Zx[zr + g*HH + jg];
    }

#pragma unroll 1
    for (int t = 0; t < TT; t++) {
        float acc[4][4];
#pragma unroll
        for (int ni = 0; ni < 4; ni++)
#pragma unroll
            for (int r = 0; r < 4; r++) acc[ni][r] = 0.0f;

        if (t > 0) {
            const __half* hprev = hseq + (size_t)(t - 1)*BB*HH;
            load_A(0, 0, hprev);
            CP_COMMIT;
            load_A(1, 1, hprev);
            CP_COMMIT;

#pragma unroll 1
            for (int kt = 0; kt < KT; kt++) {
                const int cur = kt % 3;
                if (kt + 1 < KT) { CP_WAITN(1); } else { CP_WAITN(0); }
                __syncthreads();

                if (kt + 2 < KT) {
                    load_A((kt + 2) % 3, kt + 2, hprev);
                    CP_COMMIT;
                }

#pragma unroll
                for (int ks = 0; ks < FBK/16; ks++) {
                    uint32_t afr[4], bfr[4][2];
                    {
                        uint32_t addr = As_u + (uint32_t)((cur*AS_SZH
                                          + (wm + a_m)*FASTH + ks*16 + a_k) * 2);
                        ldsm_x4(afr[0], afr[1], afr[2], afr[3], addr);
                    }
                    const int krow = kt*FBK + ks*16 + b_k;
#pragma unroll
                    for (int n2 = 0; n2 < 2; n2++) {
                        uint32_t addr = Bs_u + (uint32_t)((krow*FBSTH
                                          + wn + n2*16 + b_c) * 2);
                        ldsm_x4t(bfr[2*n2][0], bfr[2*n2][1],
                                 bfr[2*n2+1][0], bfr[2*n2+1][1], addr);
                    }
#pragma unroll
                    for (int ni = 0; ni < 4; ni++)
                        mma_f16(acc[ni], afr, bfr[ni]);
                }
            }
        }
        __syncthreads();   // all MMA smem reads done; ep (alias of As) safe

        // ---- dump accumulators to ep ----
#pragma unroll
        for (int ni = 0; ni < 4; ni++) {
            const int r0 = wm + (lane >> 2);
            const int c0 = wn + ni*8 + 2*(lane & 3);
#pragma unroll
            for (int half = 0; half < 2; half++) {
                ep[(r0 + half*8)*FEPST + c0]     = acc[ni][half*2];
                ep[(r0 + half*8)*FEPST + c0 + 1] = acc[ni][half*2 + 1];
            }
        }
        __syncthreads();

        // ---- gates (uses zxr prefetched for this t) ----
        __half* hout = hseq + (size_t)t*BB*HH;
#pragma unroll
        for (int s = 0; s < 4; s++) {
            const int m = s*32 + mrow;
            const int b = row0 + m;

            float zi = ep[m*FEPST +      j] + zxr[s][0];
            float zf = ep[m*FEPST + 16 + j] + zxr[s][1];
            float zc = ep[m*FEPST + 32 + j] + zxr[s][2];
            float zo = ep[m*FEPST + 48 + j] + zxr[s][3];

            float cc = csm[m*16 + j];
            float ig = 1.0f / (1.0f + expf(-(zi + cc*pij)));
            float fg = 1.0f / (1.0f + expf(-(zf + cc*pfj)));
            float cn = fg*cc + ig*tanhf(zc);
            float og = 1.0f / (1.0f + expf(-(zo + cn*poj)));
            float hn = og*tanhf(cn);

            csm[m*16 + j] = cn;
            hout[(size_t)b*HH + jg] = __float2half(hn);
        }

        // ---- step boundary: arrive, prefetch next Zx, wait ----
        if (t + 1 < TT) {
            __threadfence();
            __syncthreads();            // all threads' h stores fenced
            if (tid == 0)
                asm volatile("red.release.gpu.global.add.u32 [%0], %1;"
                             :: "l"((unsigned*)&g_bar), "r"(1u) : "memory");
            // prefetch next step's gate inputs while the barrier settles
#pragma unroll
            for (int s = 0; s < 4; s++) {
                const int b = row0 + s*32 + mrow;
                const size_t zr = ((size_t)b*TT + (t + 1)) * (4*HH);
#pragma unroll
                for (int g = 0; g < 4; g++)
                    zxr[s][g] = Zx[zr + g*HH + jg];
            }
            if (tid == 0) {
                const unsigned target = 128u * (unsigned)(t + 1);
                unsigned v;
                do {
                    asm volatile("ld.acquire.gpu.global.u32 %0, [%1];"
                                 : "=r"(v) : "l"((unsigned*)&g_bar) : "memory");
                } while (v < target);
            }
            __syncthreads();
        }
    }
}

// ---------------- final BN -> tanh -> Dense(H,10), fp16 h --------------------
__global__ void logits_kernel(const __half* __restrict__ hseq,
                              const float* __restrict__ g2, const float* __restrict__ b2,
                              const float* __restrict__ m2, const float* __restrict__ v2,
                              const float* __restrict__ Wout, float* __restrict__ out)
{
    int row = blockIdx.x;
    int t = row / BB, b = row % BB;
    int tid = threadIdx.x;

    float a[CC];
#pragma unroll
    for (int c2 = 0; c2 < CC; c2++) a[c2] = 0.0f;

    const __half2* hp = (const __half2*)(hseq + (size_t)row*HH) + tid*2;
    __half2 h01 = hp[0], h23 = hp[1];
    float h4[4] = {__low2float(h01), __high2float(h01),
                   __low2float(h23), __high2float(h23)};

    float4 gv = *(const float4*)(g2 + tid*4);
    float4 bv = *(const float4*)(b2 + tid*4);
    float4 mv = *(const float4*)(m2 + tid*4);
    float4 vv = *(const float4*)(v2 + tid*4);
    float G4[4] = {gv.x, gv.y, gv.z, gv.w};
    float B4[4] = {bv.x, bv.y, bv.z, bv.w};
    float M4[4] = {mv.x, mv.y, mv.z, mv.w};
    float V4[4] = {vv.x, vv.y, vv.z, vv.w};

#pragma unroll
    for (int s = 0; s < 4; s++) {
        int k = tid*4 + s;
        float y = tanhf((h4[s] - M4[s]) * rsqrtf(V4[s] + BN_EPS) * G4[s] + B4[s]);
        const float* wr = Wout + (size_t)k*CC;
#pragma unroll
        for (int c2 = 0; c2 < CC; c2++)
            a[c2] = fmaf(y, wr[c2], a[c2]);
    }

#pragma unroll
    for (int off = 16; off > 0; off >>= 1)
#pragma unroll
        for (int c2 = 0; c2 < CC; c2++)
            a[c2] += __shfl_down_sync(0xffffffffu, a[c2], off);

    __shared__ float sacc[CC];
    if (tid < CC) sacc[tid] = 0.0f;
    __syncthreads();
    if ((tid & 31) == 0)
#pragma unroll
        for (int c2 = 0; c2 < CC; c2++) atomicAdd(&sacc[c2], a[c2]);
    __syncthreads();
    if (tid < CC)
        out[((size_t)b*TT + t)*CC + tid] = sacc[tid];
}

// ---------------- launcher ----------------------------------------------------
extern "C" void kernel_launch(void* const* d_in, const int* in_sizes, int n_in,
                              void* d_out, int out_size)
{
    const float* x      = (const float*)d_in[0];
    const float* W_fe   = (const float*)d_in[1];
    const float* b_fe   = (const float*)d_in[2];
    const float* gamma1 = (const float*)d_in[3];
    const float* beta1  = (const float*)d_in[4];
    const float* mean1  = (const float*)d_in[5];
    const float* var1   = (const float*)d_in[6];
    const float* Wg     = (const float*)d_in[7];
    const float* Wr     = (const float*)d_in[8];
    const float* bias   = (const float*)d_in[9];
    const float* pi     = (const float*)d_in[10];
    const float* pf     = (const float*)d_in[11];
    const float* po     = (const float*)d_in[12];
    const float* gamma2 = (const float*)d_in[13];
    const float* beta2  = (const float*)d_in[14];
    const float* mean2  = (const float*)d_in[15];
    const float* var2   = (const float*)d_in[16];
    const float* W_out  = (const float*)d_in[17];
    float* out = (float*)d_out;

    __half *xh, *wfe, *feat, *wg, *wrt, *hseq;
    float *zx;
    cudaGetSymbolAddress((void**)&xh,   g_xh);
    cudaGetSymbolAddress((void**)&wfe,  g_wfe);
    cudaGetSymbolAddress((void**)&feat, g_feat);
    cudaGetSymbolAddress((void**)&zx,   g_zx);
    cudaGetSymbolAddress((void**)&hseq, g_hseq);
    cudaGetSymbolAddress((void**)&wg,   g_wg);
    cudaGetSymbolAddress((void**)&wrt,  g_wrt);

    constexpr int G_SMEM = (2*256*72 + 2*64*136) * 2;   // 108544 B
    cudaFuncSetAttribute((const void*)gemm_f16<1>,
                         cudaFuncAttributeMaxDynamicSharedMemorySize, G_SMEM);
    cudaFuncSetAttribute((const void*)gemm_f16<2>,
                         cudaFuncAttributeMaxDynamicSharedMemorySize, G_SMEM);
    cudaFuncSetAttribute(lstm_persistent,
                         cudaFuncAttributeMaxDynamicSharedMemorySize, PSMEM_BYTES);

    init_kernel<<<1, 32>>>();

    // preprocess: pad/convert x and W_fe; convert Wg, Wr
    {
        int n = M1 * FFP;
        pad_f16_kernel<<<(n + 255)/256, 256>>>(x, xh, M1, FF);
        n = FFP * HH;   // W_fe is (784,1024); pad rows 784..831 with zeros
        pad_f16_kernel<<<(n + 255)/256, 256>>>(nullptr, nullptr, 0, 0); // no-op guard
    }
    // W_fe pad: rows = HH? No — W_fe layout (FF, HH) row-major: pad K rows.
    // Use a dedicated small kernel call: treat as rows=HH? Simpler elementwise:
    {
        // wfe[r*HH + c] for r in [0,FFP): r<FF ? W_fe[r*HH+c] : 0
        // reuse f32_to_f16 for the real part, then zero the tail.
        int n2 = FF * HH / 2;
        f32_to_f16_kernel<<<(n2 + 255)/256, 256>>>((const float2*)W_fe, (__half2*)wfe, n2);
        int tail = (FFP - FF) * HH;   // 48*1024 halves to zero
        cudaMemsetAsync(wfe + (size_t)FF * HH, 0, (size_t)tail * sizeof(__half));
        int n3 = HH * 4 * HH / 2;
        f32_to_f16_kernel<<<(n3 + 255)/256, 256>>>((const float2*)Wg, (__half2*)wg, n3);
        f32_to_f16_kernel<<<(n3 + 255)/256, 256>>>((const float2*)Wr, (__half2*)wrt, n3);
    }

    // 1) feat (fp16) = tanh(BN(tanh(x @ W_fe + b_fe)))   K=832 padded
    {
        dim3 grid(HH/128, M1/256);
        gemm_f16<1><<<grid, 512, G_SMEM>>>(xh, wfe, feat, M1, HH, FFP,
                                           b_fe, gamma1, beta1, mean1, var1);
    }
    // 2) Zx = feat @ Wg + bias
    {
        dim3 grid(4*HH/128, M1/256);
        gemm_f16<2><<<grid, 512, G_SMEM>>>(feat, wg, zx, M1, 4*HH, HH,
                                           bias, nullptr, nullptr, nullptr, nullptr);
    }
    // 3) recurrence (fp16, B smem-resident, unified fp16 hseq)
    lstm_persistent<<<128, 512, PSMEM_BYTES>>>(wrt, zx, hseq, pi, pf, po);
    // 4) logits
    logits_kernel<<<M1, 256>>>(hseq, gamma2, beta2, mean2, var2, W_out, out);
}

// round 14
// speedup vs baseline: 1.8998x; 1.0206x over previous
#include <cuda_runtime.h>
#include <cuda_fp16.h>
#include <math.h>
#include <stdint.h>

// ---------------- problem constants ----------------
#define BB 256
#define TT 128
#define FF 784
#define FFP 832              // FF padded to multiple of 64
#define HH 1024
#define CC 10
#define M1 (BB*TT)
#define BN_EPS 1e-3f

// ---------------- scratch (device globals) ----------------
__device__ __half g_xh  [(size_t)M1 * FFP];        // fp16 x, K-padded
__device__ __half g_wfe [(size_t)FFP * HH];        // fp16 W_fe, K-padded
__device__ __half g_feat[(size_t)M1 * HH];         // fp16 feat
__device__ float  g_zx  [(size_t)M1 * 4 * HH];     // fp32 Zx (+bias)
__device__ __half g_hseq[(size_t)M1 * HH];         // fp16 h (T,B,H)
__device__ __half g_wg  [(size_t)HH * 4 * HH];     // fp16 kernel
__device__ __half g_wrt [(size_t)HH * 4 * HH];     // fp16 rec_kernel
__device__ volatile unsigned g_bar;

// ---------------- helpers ----------------
__device__ __forceinline__ void cp16(void* dst, const void* src) {
    uint32_t d = (uint32_t)__cvta_generic_to_shared(dst);
    asm volatile("cp.async.cg.shared.global [%0], [%1], 16;" :: "r"(d), "l"(src));
}
#define CP_COMMIT asm volatile("cp.async.commit_group;")
#define CP_WAITN(n) asm volatile("cp.async.wait_group %0;" :: "n"(n))

__device__ __forceinline__ void mma_f16(float* d, const uint32_t* a, const uint32_t* b) {
    asm volatile(
        "mma.sync.aligned.m16n8k16.row.col.f32.f16.f16.f32 "
        "{%0,%1,%2,%3}, {%4,%5,%6,%7}, {%8,%9}, {%0,%1,%2,%3};"
        : "+f"(d[0]), "+f"(d[1]), "+f"(d[2]), "+f"(d[3])
        : "r"(a[0]), "r"(a[1]), "r"(a[2]), "r"(a[3]),
          "r"(b[0]), "r"(b[1]));
}
__device__ __forceinline__ void ldsm_x4(uint32_t& r0, uint32_t& r1, uint32_t& r2,
                                        uint32_t& r3, uint32_t addr) {
    asm volatile("ldmatrix.sync.aligned.m8n8.x4.shared.b16 {%0,%1,%2,%3}, [%4];"
        : "=r"(r0), "=r"(r1), "=r"(r2), "=r"(r3) : "r"(addr));
}
__device__ __forceinline__ void ldsm_x4t(uint32_t& r0, uint32_t& r1, uint32_t& r2,
                                         uint32_t& r3, uint32_t addr) {
    asm volatile("ldmatrix.sync.aligned.m8n8.x4.trans.shared.b16 {%0,%1,%2,%3}, [%4];"
        : "=r"(r0), "=r"(r1), "=r"(r2), "=r"(r3) : "r"(addr));
}

// ---- fast transcendentals: 2 MUFU each, ~1e-6 relative error ----
#define LOG2E 1.4426950408889634f
__device__ __forceinline__ float ex2f(float x) {
    float y; asm("ex2.approx.f32 %0, %1;" : "=f"(y) : "f"(x)); return y;
}
__device__ __forceinline__ float rcpf(float x) {
    float y; asm("rcp.approx.f32 %0, %1;" : "=f"(y) : "f"(x)); return y;
}
__device__ __forceinline__ float fsig(float x) {          // 1/(1+e^-x)
    return rcpf(1.0f + ex2f(-x * LOG2E));
}
__device__ __forceinline__ float ftanh(float x) {         // 2*sig(2x)-1
    return fmaf(2.0f, fsig(2.0f * x), -1.0f);
}

__global__ void init_kernel() {
    if (threadIdx.x == 0 && blockIdx.x == 0) g_bar = 0u;
}
__global__ void f32_to_f16_kernel(const float2* __restrict__ in,
                                  __half2* __restrict__ out, int n2) {
    int i = blockIdx.x * blockDim.x + threadIdx.x;
    if (i < n2) {
        float2 v = in[i];
        out[i] = __floats2half2_rn(v.x, v.y);
    }
}
// pad-convert x: out[r, 0..FFP) = (c < ksrc) ? fp16(in[r*ksrc + c]) : 0
__global__ void pad_f16_kernel(const float* __restrict__ in,
                               __half* __restrict__ out, int rows, int ksrc) {
    int idx = blockIdx.x * blockDim.x + threadIdx.x;
    int total = rows * FFP;
    if (idx < total) {
        int r = idx / FFP, c = idx % FFP;
        out[idx] = (c < ksrc) ? __float2half(in[(size_t)r * ksrc + c]) : __half(0.0f);
    }
}

// ---------------- fp16 GEMM (both time-parallel GEMMs) -----------------------
// EPI 1: feat epilogue tanh,BN,tanh -> __half C.  EPI 2: +bias -> float C.
template<int EPI>
__global__ void __launch_bounds__(512)
gemm_f16(const __half* __restrict__ A, const __half* __restrict__ B,
         void* __restrict__ Cv, int M, int N, int K,
         const float* __restrict__ p0, const float* __restrict__ p1,
         const float* __restrict__ p2, const float* __restrict__ p3,
         const float* __restrict__ p4)
{
    constexpr int BM = 256, BN = 128, BK = 64, WM = 64, WN = 32;
    constexpr int MI = WM/16, NI = WN/8, KS = BK/16;
    constexpr int ASTH = BK + 8;     // 72
    constexpr int BSTH = BN + 8;     // 136
    constexpr int ASZH = BM*ASTH, BSZH = BK*BSTH;
    constexpr int AQ8 = BM*BK/8, BQ8 = BK*BN/8;

    extern __shared__ __half smh[];
    __half* As = smh;
    __half* Bs = smh + 2*ASZH;
    const uint32_t As_u = (uint32_t)__cvta_generic_to_shared(As);
    const uint32_t Bs_u = (uint32_t)__cvta_generic_to_shared(Bs);

    const int tid = threadIdx.x, lane = tid & 31, warp = tid >> 5;
    const int wm = (warp / (BN/WN)) * WM, wn = (warp % (BN/WN)) * WN;
    const int row0 = blockIdx.y * BM, col0 = blockIdx.x * BN;

    float acc[MI][NI][4];
#pragma unroll
    for (int mi = 0; mi < MI; mi++)
#pragma unroll
        for (int ni = 0; ni < NI; ni++)
#pragma unroll
            for (int r = 0; r < 4; r++) acc[mi][ni][r] = 0.0f;

    const int KT = K / BK;
#pragma unroll
    for (int q = tid; q < AQ8; q += 512) {
        int r = q >> 3, c = (q & 7) * 8;
        cp16(&As[r*ASTH + c], A + (size_t)(row0 + r)*K + c);
    }
#pragma unroll
    for (int q = tid; q < BQ8; q += 512) {
        int r = q >> 4, c = (q & 15) * 8;
        cp16(&Bs[r*BSTH + c], B + (size_t)r*N + col0 + c);
    }
    CP_COMMIT;

    const int a_m = (lane & 7) + ((lane >> 3) & 1) * 8;
    const int a_k = (lane >> 4) * 8;
    const int b_k = lane & 15;
    const int b_c = (lane >> 4) * 8;

#pragma unroll 1
    for (int kt = 0; kt < KT; kt++) {
        const int cur = kt & 1;
        if (kt + 1 < KT) {
            const int k0 = (kt + 1)*BK, nxt = cur ^ 1;
#pragma unroll
            for (int q = tid; q < AQ8; q += 512) {
                int r = q >> 3, c = (q & 7) * 8;
                cp16(&As[nxt*ASZH + r*ASTH + c], A + (size_t)(row0 + r)*K + k0 + c);
            }
#pragma unroll
            for (int q = tid; q < BQ8; q += 512) {
                int r = q >> 4, c = (q & 15) * 8;
                cp16(&Bs[nxt*BSZH + r*BSTH + c], B + (size_t)(k0 + r)*N + col0 + c);
            }
            CP_COMMIT;
            CP_WAITN(1);
        } else {
            CP_WAITN(0);
        }
        __syncthreads();

#pragma unroll
        for (int ks = 0; ks < KS; ks++) {
            uint32_t afr[MI][4], bfr[NI][2];
#pragma unroll
            for (int mi = 0; mi < MI; mi++) {
                uint32_t addr = As_u + (uint32_t)((cur*ASZH + (wm + mi*16 + a_m)*ASTH
                                                   + ks*16 + a_k) * 2);
                ldsm_x4(afr[mi][0], afr[mi][1], afr[mi][2], afr[mi][3], addr);
            }
#pragma unroll
            for (int n2 = 0; n2 < NI/2; n2++) {
                uint32_t addr = Bs_u + (uint32_t)((cur*BSZH + (ks*16 + b_k)*BSTH
                                                   + wn + n2*16 + b_c) * 2);
                ldsm_x4t(bfr[2*n2][0], bfr[2*n2][1], bfr[2*n2+1][0], bfr[2*n2+1][1], addr);
            }
#pragma unroll
            for (int mi = 0; mi < MI; mi++)
#pragma unroll
                for (int ni = 0; ni < NI; ni++)
                    mma_f16(acc[mi][ni], afr[mi], bfr[ni]);
        }
        __syncthreads();
    }

#pragma unroll
    for (int mi = 0; mi < MI; mi++)
#pragma unroll
        for (int ni = 0; ni < NI; ni++) {
            const int r0 = row0 + wm + mi*16 + (lane >> 2);
            const int c0 = col0 + wn + ni*8 + 2*(lane & 3);
#pragma unroll
            for (int half = 0; half < 2; half++) {
                const int rr = r0 + half*8;
#pragma unroll
                for (int e = 0; e < 2; e++) {
                    const int nn = c0 + e;
                    float v = acc[mi][ni][half*2 + e];
                    if (EPI == 1) {
                        v = ftanh(v + p0[nn]);
                        v = (v - p3[nn]) * rsqrtf(p4[nn] + BN_EPS) * p1[nn] + p2[nn];
                        v = ftanh(v);
                        ((__half*)Cv)[(size_t)rr*N + nn] = __float2half(v);
                    } else {
                        ((float*)Cv)[(size_t)rr*N + nn] = v + p0[nn];
                    }
                }
            }
        }
}

// ---------------- persistent fp16 LSTM recurrence, weights smem-resident -----
#define FBM 128
#define FBK 64
#define FCOLS 64
#define FASTH (FBK + 8)      // 72
#define FBSTH (FCOLS + 8)    // 72
#define FEPST (FCOLS + 4)    // 68 floats
#define AS_SZH (FBM * FASTH)          // 9216 halves/stage
#define B_SZH  (HH * FBSTH)           // 73728 halves (147456 B)
#define EP_SZ  (FBM * FEPST)          // aliases A stages
#define C_SZ   (FBM * 16)
#define PSMEM_BYTES (3*AS_SZH*2 + B_SZH*2 + C_SZ*4)   // 210944

__global__ void __launch_bounds__(512)
lstm_persistent(const __half* __restrict__ Wr,
                const float* __restrict__ Zx,
                __half* __restrict__ hseq,        // (TT, BB, HH) fp16
                const float* __restrict__ pi, const float* __restrict__ pf,
                const float* __restrict__ po)
{
    extern __shared__ __half dsh[];
    __half* As   = dsh;                        // [3][AS_SZH]
    __half* Bres = dsh + 3*AS_SZH;             // [B_SZH] persistent
    float*  csm  = (float*)(dsh + 3*AS_SZH + B_SZH);
    float*  ep   = (float*)dsh;                // aliases A stages
    const uint32_t As_u = (uint32_t)__cvta_generic_to_shared(As);
    const uint32_t Bs_u = (uint32_t)__cvta_generic_to_shared(Bres);

    const int tid = threadIdx.x, lane = tid & 31, warp = tid >> 5;
    const int wm = (warp >> 1) * 16;
    const int wn = (warp & 1) * 32;
    const int row0 = (blockIdx.x & 1) * FBM;
    const int j0   = (blockIdx.x >> 1) * 16;

    const int j = tid & 15, jg = j0 + j;
    const int mrow = tid >> 4;
    const float pij = pi[jg], pfj = pf[jg], poj = po[jg];

    for (int i = tid; i < C_SZ; i += 512) csm[i] = 0.0f;
    {
        constexpr int BQ8 = HH * FCOLS / 8;
#pragma unroll
        for (int q = tid; q < BQ8; q += 512) {
            int k = q >> 3, ci = q & 7;
            int g = ci >> 1, jj8 = (ci & 1) * 8;
            cp16(&Bres[k*FBSTH + g*16 + jj8],
                 Wr + (size_t)k*(4*HH) + g*HH + j0 + jj8);
        }
        CP_COMMIT;
        CP_WAITN(0);
    }
    __syncthreads();

    constexpr int AQ8 = FBM * FBK / 8;
    constexpr int KT  = HH / FBK;        // 16

    auto load_A = [&](int st, int kt, const __half* hprev) {
#pragma unroll
        for (int q = tid; q < AQ8; q += 512) {
            int r = q >> 3, c = (q & 7) * 8;
            cp16(&As[st*AS_SZH + r*FASTH + c],
                 hprev + (size_t)(row0 + r)*HH + kt*FBK + c);
        }
    };

    const int a_m = (lane & 7) + ((lane >> 3) & 1) * 8;
    const int a_k = (lane >> 4) * 8;
    const int b_k = lane & 15;
    const int b_c = (lane >> 4) * 8;

    // gate-input registers for the CURRENT step (prefetched at previous tail)
    float zxr[4][4];
#pragma unroll
    for (int s = 0; s < 4; s++) {
        const int b = row0 + s*32 + mrow;
        const size_t zr = (size_t)b*TT * (4*HH);
#pragma unroll
        for (int g = 0; g < 4; g++)
            zxr[s][g] = Zx[zr + g*HH + jg];
    }

#pragma unroll 1
    for (int t = 0; t < TT; t++) {
        float acc[4][4];
#pragma unroll
        for (int ni = 0; ni < 4; ni++)
#pragma unroll
            for (int r = 0; r < 4; r++) acc[ni][r] = 0.0f;

        if (t > 0) {
            const __half* hprev = hseq + (size_t)(t - 1)*BB*HH;
            load_A(0, 0, hprev);
            CP_COMMIT;
            load_A(1, 1, hprev);
            CP_COMMIT;

#pragma unroll 1
            for (int kt = 0; kt < KT; kt++) {
                const int cur = kt % 3;
                if (kt + 1 < KT) { CP_WAITN(1); } else { CP_WAITN(0); }
                __syncthreads();

                if (kt + 2 < KT) {
                    load_A((kt + 2) % 3, kt + 2, hprev);
                    CP_COMMIT;
                }

#pragma unroll
                for (int ks = 0; ks < FBK/16; ks++) {
                    uint32_t afr[4], bfr[4][2];
                    {
                        uint32_t addr = As_u + (uint32_t)((cur*AS_SZH
                                          + (wm + a_m)*FASTH + ks*16 + a_k) * 2);
                        ldsm_x4(afr[0], afr[1], afr[2], afr[3], addr);
                    }
                    const int krow = kt*FBK + ks*16 + b_k;
#pragma unroll
                    for (int n2 = 0; n2 < 2; n2++) {
                        uint32_t addr = Bs_u + (uint32_t)((krow*FBSTH
                                          + wn + n2*16 + b_c) * 2);
                        ldsm_x4t(bfr[2*n2][0], bfr[2*n2][1],
                                 bfr[2*n2+1][0], bfr[2*n2+1][1], addr);
                    }
#pragma unroll
                    for (int ni = 0; ni < 4; ni++)
                        mma_f16(acc[ni], afr, bfr[ni]);
                }
            }
        }
        __syncthreads();   // all MMA smem reads done; ep (alias of As) safe

        // ---- dump accumulators to ep ----
#pragma unroll
        for (int ni = 0; ni < 4; ni++) {
            const int r0 = wm + (lane >> 2);
            const int c0 = wn + ni*8 + 2*(lane & 3);
#pragma unroll
            for (int half = 0; half < 2; half++) {
                ep[(r0 + half*8)*FEPST + c0]     = acc[ni][half*2];
                ep[(r0 + half*8)*FEPST + c0 + 1] = acc[ni][half*2 + 1];
            }
        }
        __syncthreads();

        // ---- gates (fast sigmoid/tanh: 2 MUFU each) ----
        __half* hout = hseq + (size_t)t*BB*HH;
#pragma unroll
        for (int s = 0; s < 4; s++) {
            const int m = s*32 + mrow;
            const int b = row0 + m;

            float zi = ep[m*FEPST +      j] + zxr[s][0];
            float zf = ep[m*FEPST + 16 + j] + zxr[s][1];
            float zc = ep[m*FEPST + 32 + j] + zxr[s][2];
            float zo = ep[m*FEPST + 48 + j] + zxr[s][3];

            float cc = csm[m*16 + j];
            float ig = fsig(zi + cc*pij);
            float fg = fsig(zf + cc*pfj);
            float cn = fg*cc + ig*ftanh(zc);
            float og = fsig(zo + cn*poj);
            float hn = og*ftanh(cn);

            csm[m*16 + j] = cn;
            hout[(size_t)b*HH + jg] = __float2half(hn);
        }

        // ---- step boundary: arrive, prefetch next Zx, wait ----
        if (t + 1 < TT) {
            __threadfence();
            __syncthreads();            // all threads' h stores fenced
            if (tid == 0)
                asm volatile("red.release.gpu.global.add.u32 [%0], %1;"
                             :: "l"((unsigned*)&g_bar), "r"(1u) : "memory");
            // prefetch next step's gate inputs while the barrier settles
#pragma unroll
            for (int s = 0; s < 4; s++) {
                const int b = row0 + s*32 + mrow;
                const size_t zr = ((size_t)b*TT + (t + 1)) * (4*HH);
#pragma unroll
                for (int g = 0; g < 4; g++)
                    zxr[s][g] = Zx[zr + g*HH + jg];
            }
            if (tid == 0) {
                const unsigned target = 128u * (unsigned)(t + 1);
                unsigned v;
                do {
                    asm volatile("ld.acquire.gpu.global.u32 %0, [%1];"
                                 : "=r"(v) : "l"((unsigned*)&g_bar) : "memory");
                } while (v < target);
            }
            __syncthreads();
        }
    }
}

// ---------------- final BN -> tanh -> Dense(H,10), fp16 h --------------------
__global__ void logits_kernel(const __half* __restrict__ hseq,
                              const float* __restrict__ g2, const float* __restrict__ b2,
                              const float* __restrict__ m2, const float* __restrict__ v2,
                              const float* __restrict__ Wout, float* __restrict__ out)
{
    int row = blockIdx.x;
    int t = row / BB, b = row % BB;
    int tid = threadIdx.x;

    float a[CC];
#pragma unroll
    for (int c2 = 0; c2 < CC; c2++) a[c2] = 0.0f;

    const __half2* hp = (const __half2*)(hseq + (size_t)row*HH) + tid*2;
    __half2 h01 = hp[0], h23 = hp[1];
    float h4[4] = {__low2float(h01), __high2float(h01),
                   __low2float(h23), __high2float(h23)};

    float4 gv = *(const float4*)(g2 + tid*4);
    float4 bv = *(const float4*)(b2 + tid*4);
    float4 mv = *(const float4*)(m2 + tid*4);
    float4 vv = *(const float4*)(v2 + tid*4);
    float G4[4] = {gv.x, gv.y, gv.z, gv.w};
    float B4[4] = {bv.x, bv.y, bv.z, bv.w};
    float M4[4] = {mv.x, mv.y, mv.z, mv.w};
    float V4[4] = {vv.x, vv.y, vv.z, vv.w};

#pragma unroll
    for (int s = 0; s < 4; s++) {
        int k = tid*4 + s;
        float y = ftanh((h4[s] - M4[s]) * rsqrtf(V4[s] + BN_EPS) * G4[s] + B4[s]);
        const float* wr = Wout + (size_t)k*CC;
#pragma unroll
        for (int c2 = 0; c2 < CC; c2++)
            a[c2] = fmaf(y, wr[c2], a[c2]);
    }

#pragma unroll
    for (int off = 16; off > 0; off >>= 1)
#pragma unroll
        for (int c2 = 0; c2 < CC; c2++)
            a[c2] += __shfl_down_sync(0xffffffffu, a[c2], off);

    __shared__ float sacc[CC];
    if (tid < CC) sacc[tid] = 0.0f;
    __syncthreads();
    if ((tid & 31) == 0)
#pragma unroll
        for (int c2 = 0; c2 < CC; c2++) atomicAdd(&sacc[c2], a[c2]);
    __syncthreads();
    if (tid < CC)
        out[((size_t)b*TT + t)*CC + tid] = sacc[tid];
}

// ---------------- launcher ----------------------------------------------------
extern "C" void kernel_launch(void* const* d_in, const int* in_sizes, int n_in,
                              void* d_out, int out_size)
{
    const float* x      = (const float*)d_in[0];
    const float* W_fe   = (const float*)d_in[1];
    const float* b_fe   = (const float*)d_in[2];
    const float* gamma1 = (const float*)d_in[3];
    const float* beta1  = (const float*)d_in[4];
    const float* mean1  = (const float*)d_in[5];
    const float* var1   = (const float*)d_in[6];
    const float* Wg     = (const float*)d_in[7];
    const float* Wr     = (const float*)d_in[8];
    const float* bias   = (const float*)d_in[9];
    const float* pi     = (const float*)d_in[10];
    const float* pf     = (const float*)d_in[11];
    const float* po     = (const float*)d_in[12];
    const float* gamma2 = (const float*)d_in[13];
    const float* beta2  = (const float*)d_in[14];
    const float* mean2  = (const float*)d_in[15];
    const float* var2   = (const float*)d_in[16];
    const float* W_out  = (const float*)d_in[17];
    float* out = (float*)d_out;

    __half *xh, *wfe, *feat, *wg, *wrt, *hseq;
    float *zx;
    cudaGetSymbolAddress((void**)&xh,   g_xh);
    cudaGetSymbolAddress((void**)&wfe,  g_wfe);
    cudaGetSymbolAddress((void**)&feat, g_feat);
    cudaGetSymbolAddress((void**)&zx,   g_zx);
    cudaGetSymbolAddress((void**)&hseq, g_hseq);
    cudaGetSymbolAddress((void**)&wg,   g_wg);
    cudaGetSymbolAddress((void**)&wrt,  g_wrt);

    constexpr int G_SMEM = (2*256*72 + 2*64*136) * 2;   // 108544 B
    cudaFuncSetAttribute((const void*)gemm_f16<1>,
                         cudaFuncAttributeMaxDynamicSharedMemorySize, G_SMEM);
    cudaFuncSetAttribute((const void*)gemm_f16<2>,
                         cudaFuncAttributeMaxDynamicSharedMemorySize, G_SMEM);
    cudaFuncSetAttribute(lstm_persistent,
                         cudaFuncAttributeMaxDynamicSharedMemorySize, PSMEM_BYTES);

    init_kernel<<<1, 32>>>();

    // preprocess: pad/convert x; convert W_fe (+zero tail), Wg, Wr
    {
        int n = M1 * FFP;
        pad_f16_kernel<<<(n + 255)/256, 256>>>(x, xh, M1, FF);

        int n2 = FF * HH / 2;
        f32_to_f16_kernel<<<(n2 + 255)/256, 256>>>((const float2*)W_fe, (__half2*)wfe, n2);
        int tail = (FFP - FF) * HH;
        cudaMemsetAsync(wfe + (size_t)FF * HH, 0, (size_t)tail * sizeof(__half));

        int n3 = HH * 4 * HH / 2;
        f32_to_f16_kernel<<<(n3 + 255)/256, 256>>>((const float2*)Wg, (__half2*)wg, n3);
        f32_to_f16_kernel<<<(n3 + 255)/256, 256>>>((const float2*)Wr, (__half2*)wrt, n3);
    }

    // 1) feat (fp16) = tanh(BN(tanh(x @ W_fe + b_fe)))   K=832 padded
    {
        dim3 grid(HH/128, M1/256);
        gemm_f16<1><<<grid, 512, G_SMEM>>>(xh, wfe, feat, M1, HH, FFP,
                                           b_fe, gamma1, beta1, mean1, var1);
    }
    // 2) Zx = feat @ Wg + bias
    {
        dim3 grid(4*HH/128, M1/256);
        gemm_f16<2><<<grid, 512, G_SMEM>>>(feat, wg, zx, M1, 4*HH, HH,
                                           bias, nullptr, nullptr, nullptr, nullptr);
    }
    // 3) recurrence (fp16, B smem-resident, fast gate math)
    lstm_persistent<<<128, 512, PSMEM_BYTES>>>(wrt, zx, hseq, pi, pf, po);
    // 4) logits
    logits_kernel<<<M1, 256>>>(hseq, gamma2, beta2, mean2, var2, W_out, out);
}

// round 15
// speedup vs baseline: 1.9576x; 1.0304x over previous
#include <cuda_runtime.h>
#include <cuda_fp16.h>
#include <math.h>
#include <stdint.h>

// ---------------- problem constants ----------------
#define BB 256
#define TT 128
#define FF 784
#define FFP 832              // FF padded to multiple of 64
#define HH 1024
#define CC 10
#define M1 (BB*TT)
#define BN_EPS 1e-3f

// ---------------- scratch (device globals) ----------------
__device__ __half g_xh  [(size_t)M1 * FFP];        // fp16 x, K-padded
__device__ __half g_wfe [(size_t)FFP * HH];        // fp16 W_fe, K-padded
__device__ __half g_feat[(size_t)M1 * HH];         // fp16 feat, T-MAJOR rows (t*BB+b)
__device__ float  g_zx  [(size_t)M1 * 4 * HH];     // fp32 Zx (+bias), T-MAJOR
__device__ __half g_hseq[(size_t)M1 * HH];         // fp16 h (T,B,H)
__device__ __half g_wg  [(size_t)HH * 4 * HH];     // fp16 kernel
__device__ __half g_wrt [(size_t)HH * 4 * HH];     // fp16 rec_kernel
__device__ volatile unsigned g_bar;

// ---------------- helpers ----------------
__device__ __forceinline__ void cp16(void* dst, const void* src) {
    uint32_t d = (uint32_t)__cvta_generic_to_shared(dst);
    asm volatile("cp.async.cg.shared.global [%0], [%1], 16;" :: "r"(d), "l"(src));
}
#define CP_COMMIT asm volatile("cp.async.commit_group;")
#define CP_WAITN(n) asm volatile("cp.async.wait_group %0;" :: "n"(n))

__device__ __forceinline__ void mma_f16(float* d, const uint32_t* a, const uint32_t* b) {
    asm volatile(
        "mma.sync.aligned.m16n8k16.row.col.f32.f16.f16.f32 "
        "{%0,%1,%2,%3}, {%4,%5,%6,%7}, {%8,%9}, {%0,%1,%2,%3};"
        : "+f"(d[0]), "+f"(d[1]), "+f"(d[2]), "+f"(d[3])
        : "r"(a[0]), "r"(a[1]), "r"(a[2]), "r"(a[3]),
          "r"(b[0]), "r"(b[1]));
}
__device__ __forceinline__ void ldsm_x4(uint32_t& r0, uint32_t& r1, uint32_t& r2,
                                        uint32_t& r3, uint32_t addr) {
    asm volatile("ldmatrix.sync.aligned.m8n8.x4.shared.b16 {%0,%1,%2,%3}, [%4];"
        : "=r"(r0), "=r"(r1), "=r"(r2), "=r"(r3) : "r"(addr));
}
__device__ __forceinline__ void ldsm_x4t(uint32_t& r0, uint32_t& r1, uint32_t& r2,
                                         uint32_t& r3, uint32_t addr) {
    asm volatile("ldmatrix.sync.aligned.m8n8.x4.trans.shared.b16 {%0,%1,%2,%3}, [%4];"
        : "=r"(r0), "=r"(r1), "=r"(r2), "=r"(r3) : "r"(addr));
}

// ---- fast transcendentals: 2 MUFU each, ~1e-6 relative error ----
#define LOG2E 1.4426950408889634f
__device__ __forceinline__ float ex2f(float x) {
    float y; asm("ex2.approx.f32 %0, %1;" : "=f"(y) : "f"(x)); return y;
}
__device__ __forceinline__ float rcpf(float x) {
    float y; asm("rcp.approx.f32 %0, %1;" : "=f"(y) : "f"(x)); return y;
}
__device__ __forceinline__ float fsig(float x) {
    return rcpf(1.0f + ex2f(-x * LOG2E));
}
__device__ __forceinline__ float ftanh(float x) {
    return fmaf(2.0f, fsig(2.0f * x), -1.0f);
}

__global__ void init_kernel() {
    if (threadIdx.x == 0 && blockIdx.x == 0) g_bar = 0u;
}
__global__ void f32_to_f16_kernel(const float2* __restrict__ in,
                                  __half2* __restrict__ out, int n2) {
    int i = blockIdx.x * blockDim.x + threadIdx.x;
    if (i < n2) {
        float2 v = in[i];
        out[i] = __floats2half2_rn(v.x, v.y);
    }
}
__global__ void pad_f16_kernel(const float* __restrict__ in,
                               __half* __restrict__ out, int rows, int ksrc) {
    int idx = blockIdx.x * blockDim.x + threadIdx.x;
    int total = rows * FFP;
    if (idx < total) {
        int r = idx / FFP, c = idx % FFP;
        out[idx] = (c < ksrc) ? __float2half(in[(size_t)r * ksrc + c]) : __half(0.0f);
    }
}

// ---------------- fp16 GEMM (both time-parallel GEMMs) -----------------------
// EPI 1: feat epilogue tanh,BN,tanh -> __half C, stored T-MAJOR:
//        input row rr = b*TT+t  ->  C row (t*BB + b).
// EPI 2: +bias -> float C (rows unchanged; A already t-major).
template<int EPI>
__global__ void __launch_bounds__(512)
gemm_f16(const __half* __restrict__ A, const __half* __restrict__ B,
         void* __restrict__ Cv, int M, int N, int K,
         const float* __restrict__ p0, const float* __restrict__ p1,
         const float* __restrict__ p2, const float* __restrict__ p3,
         const float* __restrict__ p4)
{
    constexpr int BM = 256, BN = 128, BK = 64, WM = 64, WN = 32;
    constexpr int MI = WM/16, NI = WN/8, KS = BK/16;
    constexpr int ASTH = BK + 8;     // 72
    constexpr int BSTH = BN + 8;     // 136
    constexpr int ASZH = BM*ASTH, BSZH = BK*BSTH;
    constexpr int AQ8 = BM*BK/8, BQ8 = BK*BN/8;

    extern __shared__ __half smh[];
    __half* As = smh;
    __half* Bs = smh + 2*ASZH;
    const uint32_t As_u = (uint32_t)__cvta_generic_to_shared(As);
    const uint32_t Bs_u = (uint32_t)__cvta_generic_to_shared(Bs);

    const int tid = threadIdx.x, lane = tid & 31, warp = tid >> 5;
    const int wm = (warp / (BN/WN)) * WM, wn = (warp % (BN/WN)) * WN;
    const int row0 = blockIdx.y * BM, col0 = blockIdx.x * BN;

    float acc[MI][NI][4];
#pragma unroll
    for (int mi = 0; mi < MI; mi++)
#pragma unroll
        for (int ni = 0; ni < NI; ni++)
#pragma unroll
            for (int r = 0; r < 4; r++) acc[mi][ni][r] = 0.0f;

    const int KT = K / BK;
#pragma unroll
    for (int q = tid; q < AQ8; q += 512) {
        int r = q >> 3, c = (q & 7) * 8;
        cp16(&As[r*ASTH + c], A + (size_t)(row0 + r)*K + c);
    }
#pragma unroll
    for (int q = tid; q < BQ8; q += 512) {
        int r = q >> 4, c = (q & 15) * 8;
        cp16(&Bs[r*BSTH + c], B + (size_t)r*N + col0 + c);
    }
    CP_COMMIT;

    const int a_m = (lane & 7) + ((lane >> 3) & 1) * 8;
    const int a_k = (lane >> 4) * 8;
    const int b_k = lane & 15;
    const int b_c = (lane >> 4) * 8;

#pragma unroll 1
    for (int kt = 0; kt < KT; kt++) {
        const int cur = kt & 1;
        if (kt + 1 < KT) {
            const int k0 = (kt + 1)*BK, nxt = cur ^ 1;
#pragma unroll
            for (int q = tid; q < AQ8; q += 512) {
                int r = q >> 3, c = (q & 7) * 8;
                cp16(&As[nxt*ASZH + r*ASTH + c], A + (size_t)(row0 + r)*K + k0 + c);
            }
#pragma unroll
            for (int q = tid; q < BQ8; q += 512) {
                int r = q >> 4, c = (q & 15) * 8;
                cp16(&Bs[nxt*BSZH + r*BSTH + c], B + (size_t)(k0 + r)*N + col0 + c);
            }
            CP_COMMIT;
            CP_WAITN(1);
        } else {
            CP_WAITN(0);
        }
        __syncthreads();

#pragma unroll
        for (int ks = 0; ks < KS; ks++) {
            uint32_t afr[MI][4], bfr[NI][2];
#pragma unroll
            for (int mi = 0; mi < MI; mi++) {
                uint32_t addr = As_u + (uint32_t)((cur*ASZH + (wm + mi*16 + a_m)*ASTH
                                                   + ks*16 + a_k) * 2);
                ldsm_x4(afr[mi][0], afr[mi][1], afr[mi][2], afr[mi][3], addr);
            }
#pragma unroll
            for (int n2 = 0; n2 < NI/2; n2++) {
                uint32_t addr = Bs_u + (uint32_t)((cur*BSZH + (ks*16 + b_k)*BSTH
                                                   + wn + n2*16 + b_c) * 2);
                ldsm_x4t(bfr[2*n2][0], bfr[2*n2][1], bfr[2*n2+1][0], bfr[2*n2+1][1], addr);
            }
#pragma unroll
            for (int mi = 0; mi < MI; mi++)
#pragma unroll
                for (int ni = 0; ni < NI; ni++)
                    mma_f16(acc[mi][ni], afr[mi], bfr[ni]);
        }
        __syncthreads();
    }

#pragma unroll
    for (int mi = 0; mi < MI; mi++)
#pragma unroll
        for (int ni = 0; ni < NI; ni++) {
            const int r0 = row0 + wm + mi*16 + (lane >> 2);
            const int c0 = col0 + wn + ni*8 + 2*(lane & 3);
#pragma unroll
            for (int half = 0; half < 2; half++) {
                const int rr = r0 + half*8;
#pragma unroll
                for (int e = 0; e < 2; e++) {
                    const int nn = c0 + e;
                    float v = acc[mi][ni][half*2 + e];
                    if (EPI == 1) {
                        v = ftanh(v + p0[nn]);
                        v = (v - p3[nn]) * rsqrtf(p4[nn] + BN_EPS) * p1[nn] + p2[nn];
                        v = ftanh(v);
                        // t-major store: rr = b*TT + t  ->  crow = t*BB + b
                        const int crow = ((rr & (TT - 1)) << 8) + (rr >> 7);
                        ((__half*)Cv)[(size_t)crow*N + nn] = __float2half(v);
                    } else {
                        ((float*)Cv)[(size_t)rr*N + nn] = v + p0[nn];
                    }
                }
            }
        }
}

// ---------------- persistent fp16 LSTM recurrence, weights smem-resident -----
#define FBM 128
#define FBK 64
#define FCOLS 64
#define FASTH (FBK + 8)      // 72
#define FBSTH (FCOLS + 8)    // 72
#define FEPST (FCOLS + 4)    // 68 floats
#define AS_SZH (FBM * FASTH)          // 9216 halves/stage
#define B_SZH  (HH * FBSTH)           // 73728 halves (147456 B)
#define EP_SZ  (FBM * FEPST)          // aliases A stages
#define C_SZ   (FBM * 16)
#define PSMEM_BYTES (3*AS_SZH*2 + B_SZH*2 + C_SZ*4)   // 210944

__global__ void __launch_bounds__(512)
lstm_persistent(const __half* __restrict__ Wr,
                const float* __restrict__ Zx,      // T-MAJOR: row t*BB+b
                __half* __restrict__ hseq,         // (TT, BB, HH) fp16
                const float* __restrict__ pi, const float* __restrict__ pf,
                const float* __restrict__ po)
{
    extern __shared__ __half dsh[];
    __half* As   = dsh;                        // [3][AS_SZH]
    __half* Bres = dsh + 3*AS_SZH;             // [B_SZH] persistent
    float*  csm  = (float*)(dsh + 3*AS_SZH + B_SZH);
    float*  ep   = (float*)dsh;                // aliases A stages
    const uint32_t As_u = (uint32_t)__cvta_generic_to_shared(As);
    const uint32_t Bs_u = (uint32_t)__cvta_generic_to_shared(Bres);

    const int tid = threadIdx.x, lane = tid & 31, warp = tid >> 5;
    const int wm = (warp >> 1) * 16;
    const int wn = (warp & 1) * 32;
    const int row0 = (blockIdx.x & 1) * FBM;
    const int j0   = (blockIdx.x >> 1) * 16;

    const int j = tid & 15, jg = j0 + j;
    const int mrow = tid >> 4;
    const float pij = pi[jg], pfj = pf[jg], poj = po[jg];

    for (int i = tid; i < C_SZ; i += 512) csm[i] = 0.0f;
    {
        constexpr int BQ8 = HH * FCOLS / 8;
#pragma unroll
        for (int q = tid; q < BQ8; q += 512) {
            int k = q >> 3, ci = q & 7;
            int g = ci >> 1, jj8 = (ci & 1) * 8;
            cp16(&Bres[k*FBSTH + g*16 + jj8],
                 Wr + (size_t)k*(4*HH) + g*HH + j0 + jj8);
        }
        CP_COMMIT;
        CP_WAITN(0);
    }
    __syncthreads();

    constexpr int AQ8 = FBM * FBK / 8;
    constexpr int KT  = HH / FBK;        // 16

    auto load_A = [&](int st, int kt, const __half* hprev) {
#pragma unroll
        for (int q = tid; q < AQ8; q += 512) {
            int r = q >> 3, c = (q & 7) * 8;
            cp16(&As[st*AS_SZH + r*FASTH + c],
                 hprev + (size_t)(row0 + r)*HH + kt*FBK + c);
        }
    };

    const int a_m = (lane & 7) + ((lane >> 3) & 1) * 8;
    const int a_k = (lane >> 4) * 8;
    const int b_k = lane & 15;
    const int b_c = (lane >> 4) * 8;

    // gate-input registers for the CURRENT step (t-major Zx: contiguous block)
    float zxr[4][4];
#pragma unroll
    for (int s = 0; s < 4; s++) {
        const int b = row0 + s*32 + mrow;
        const size_t zr = (size_t)b * (4*HH);            // t = 0
#pragma unroll
        for (int g = 0; g < 4; g++)
            zxr[s][g] = Zx[zr + g*HH + jg];
    }

#pragma unroll 1
    for (int t = 0; t < TT; t++) {
        float acc[4][4];
#pragma unroll
        for (int ni = 0; ni < 4; ni++)
#pragma unroll
            for (int r = 0; r < 4; r++) acc[ni][r] = 0.0f;

        if (t > 0) {
            const __half* hprev = hseq + (size_t)(t - 1)*BB*HH;
            load_A(0, 0, hprev);
            CP_COMMIT;
            load_A(1, 1, hprev);
            CP_COMMIT;

#pragma unroll 1
            for (int kt = 0; kt < KT; kt++) {
                const int cur = kt % 3;
                if (kt + 1 < KT) { CP_WAITN(1); } else { CP_WAITN(0); }
                __syncthreads();

                if (kt + 2 < KT) {
                    load_A((kt + 2) % 3, kt + 2, hprev);
                    CP_COMMIT;
                }

#pragma unroll
                for (int ks = 0; ks < FBK/16; ks++) {
                    uint32_t afr[4], bfr[4][2];
                    {
                        uint32_t addr = As_u + (uint32_t)((cur*AS_SZH
                                          + (wm + a_m)*FASTH + ks*16 + a_k) * 2);
                        ldsm_x4(afr[0], afr[1], afr[2], afr[3], addr);
                    }
                    const int krow = kt*FBK + ks*16 + b_k;
#pragma unroll
                    for (int n2 = 0; n2 < 2; n2++) {
                        uint32_t addr = Bs_u + (uint32_t)((krow*FBSTH
                                          + wn + n2*16 + b_c) * 2);
                        ldsm_x4t(bfr[2*n2][0], bfr[2*n2][1],
                                 bfr[2*n2+1][0], bfr[2*n2+1][1], addr);
                    }
#pragma unroll
                    for (int ni = 0; ni < 4; ni++)
                        mma_f16(acc[ni], afr, bfr[ni]);
                }
            }
        }
        __syncthreads();   // all MMA smem reads done; ep (alias of As) safe

        // ---- dump accumulators to ep ----
#pragma unroll
        for (int ni = 0; ni < 4; ni++) {
            const int r0 = wm + (lane >> 2);
            const int c0 = wn + ni*8 + 2*(lane & 3);
#pragma unroll
            for (int half = 0; half < 2; half++) {
                ep[(r0 + half*8)*FEPST + c0]     = acc[ni][half*2];
                ep[(r0 + half*8)*FEPST + c0 + 1] = acc[ni][half*2 + 1];
            }
        }
        __syncthreads();

        // ---- gates ----
        __half* hout = hseq + (size_t)t*BB*HH;
#pragma unroll
        for (int s = 0; s < 4; s++) {
            const int m = s*32 + mrow;
            const int b = row0 + m;

            float zi = ep[m*FEPST +      j] + zxr[s][0];
            float zf = ep[m*FEPST + 16 + j] + zxr[s][1];
            float zc = ep[m*FEPST + 32 + j] + zxr[s][2];
            float zo = ep[m*FEPST + 48 + j] + zxr[s][3];

            float cc = csm[m*16 + j];
            float ig = fsig(zi + cc*pij);
            float fg = fsig(zf + cc*pfj);
            float cn = fg*cc + ig*ftanh(zc);
            float og = fsig(zo + cn*poj);
            float hn = og*ftanh(cn);

            csm[m*16 + j] = cn;
            hout[(size_t)b*HH + jg] = __float2half(hn);
        }

        // ---- step boundary: cumulative release barrier + Zx prefetch ----
        if (t + 1 < TT) {
            __syncthreads();            // CTA-scope fence over all h stores
            if (tid == 0)               // cumulative release (grid.sync pattern)
                asm volatile("red.release.gpu.global.add.u32 [%0], %1;"
                             :: "l"((unsigned*)&g_bar), "r"(1u) : "memory");
            // prefetch next step's gate inputs (contiguous t-major block)
#pragma unroll
            for (int s = 0; s < 4; s++) {
                const int b = row0 + s*32 + mrow;
                const size_t zr = ((size_t)(t + 1)*BB + b) * (4*HH);
#pragma unroll
                for (int g = 0; g < 4; g++)
                    zxr[s][g] = Zx[zr + g*HH + jg];
            }
            if (tid == 0) {
                const unsigned target = 128u * (unsigned)(t + 1);
                unsigned v;
                do {
                    asm volatile("ld.acquire.gpu.global.u32 %0, [%1];"
                                 : "=r"(v) : "l"((unsigned*)&g_bar) : "memory");
                } while (v < target);
            }
            __syncthreads();
        }
    }
}

// ---------------- final BN -> tanh -> Dense(H,10), fp16 h --------------------
__global__ void logits_kernel(const __half* __restrict__ hseq,
                              const float* __restrict__ g2, const float* __restrict__ b2,
                              const float* __restrict__ m2, const float* __restrict__ v2,
                              const float* __restrict__ Wout, float* __restrict__ out)
{
    int row = blockIdx.x;            // = t*BB + b
    int t = row / BB, b = row % BB;
    int tid = threadIdx.x;

    float a[CC];
#pragma unroll
    for (int c2 = 0; c2 < CC; c2++) a[c2] = 0.0f;

    const __half2* hp = (const __half2*)(hseq + (size_t)row*HH) + tid*2;
    __half2 h01 = hp[0], h23 = hp[1];
    float h4[4] = {__low2float(h01), __high2float(h01),
                   __low2float(h23), __high2float(h23)};

    float4 gv = *(const float4*)(g2 + tid*4);
    float4 bv = *(const float4*)(b2 + tid*4);
    float4 mv = *(const float4*)(m2 + tid*4);
    float4 vv = *(const float4*)(v2 + tid*4);
    float G4[4] = {gv.x, gv.y, gv.z, gv.w};
    float B4[4] = {bv.x, bv.y, bv.z, bv.w};
    float M4[4] = {mv.x, mv.y, mv.z, mv.w};
    float V4[4] = {vv.x, vv.y, vv.z, vv.w};

#pragma unroll
    for (int s = 0; s < 4; s++) {
        int k = tid*4 + s;
        float y = ftanh((h4[s] - M4[s]) * rsqrtf(V4[s] + BN_EPS) * G4[s] + B4[s]);
        const float* wr = Wout + (size_t)k*CC;
#pragma unroll
        for (int c2 = 0; c2 < CC; c2++)
            a[c2] = fmaf(y, wr[c2], a[c2]);
    }

#pragma unroll
    for (int off = 16; off > 0; off >>= 1)
#pragma unroll
        for (int c2 = 0; c2 < CC; c2++)
            a[c2] += __shfl_down_sync(0xffffffffu, a[c2], off);

    __shared__ float sacc[CC];
    if (tid < CC) sacc[tid] = 0.0f;
    __syncthreads();
    if ((tid & 31) == 0)
#pragma unroll
        for (int c2 = 0; c2 < CC; c2++) atomicAdd(&sacc[c2], a[c2]);
    __syncthreads();
    if (tid < CC)
        out[((size_t)b*TT + t)*CC + tid] = sacc[tid];
}

// ---------------- launcher ----------------------------------------------------
extern "C" void kernel_launch(void* const* d_in, const int* in_sizes, int n_in,
                              void* d_out, int out_size)
{
    const float* x      = (const float*)d_in[0];
    const float* W_fe   = (const float*)d_in[1];
    const float* b_fe   = (const float*)d_in[2];
    const float* gamma1 = (const float*)d_in[3];
    const float* beta1  = (const float*)d_in[4];
    const float* mean1  = (const float*)d_in[5];
    const float* var1   = (const float*)d_in[6];
    const float* Wg     = (const float*)d_in[7];
    const float* Wr     = (const float*)d_in[8];
    const float* bias   = (const float*)d_in[9];
    const float* pi     = (const float*)d_in[10];
    const float* pf     = (const float*)d_in[11];
    const float* po     = (const float*)d_in[12];
    const float* gamma2 = (const float*)d_in[13];
    const float* beta2  = (const float*)d_in[14];
    const float* mean2  = (const float*)d_in[15];
    const float* var2   = (const float*)d_in[16];
    const float* W_out  = (const float*)d_in[17];
    float* out = (float*)d_out;

    __half *xh, *wfe, *feat, *wg, *wrt, *hseq;
    float *zx;
    cudaGetSymbolAddress((void**)&xh,   g_xh);
    cudaGetSymbolAddress((void**)&wfe,  g_wfe);
    cudaGetSymbolAddress((void**)&feat, g_feat);
    cudaGetSymbolAddress((void**)&zx,   g_zx);
    cudaGetSymbolAddress((void**)&hseq, g_hseq);
    cudaGetSymbolAddress((void**)&wg,   g_wg);
    cudaGetSymbolAddress((void**)&wrt,  g_wrt);

    constexpr int G_SMEM = (2*256*72 + 2*64*136) * 2;   // 108544 B
    cudaFuncSetAttribute((const void*)gemm_f16<1>,
                         cudaFuncAttributeMaxDynamicSharedMemorySize, G_SMEM);
    cudaFuncSetAttribute((const void*)gemm_f16<2>,
                         cudaFuncAttributeMaxDynamicSharedMemorySize, G_SMEM);
    cudaFuncSetAttribute(lstm_persistent,
                         cudaFuncAttributeMaxDynamicSharedMemorySize, PSMEM_BYTES);

    init_kernel<<<1, 32>>>();

    // preprocess: pad/convert x; convert W_fe (+zero tail), Wg, Wr
    {
        int n = M1 * FFP;
        pad_f16_kernel<<<(n + 255)/256, 256>>>(x, xh, M1, FF);

        int n2 = FF * HH / 2;
        f32_to_f16_kernel<<<(n2 + 255)/256, 256>>>((const float2*)W_fe, (__half2*)wfe, n2);
        int tail = (FFP - FF) * HH;
        cudaMemsetAsync(wfe + (size_t)FF * HH, 0, (size_t)tail * sizeof(__half));

        int n3 = HH * 4 * HH / 2;
        f32_to_f16_kernel<<<(n3 + 255)/256, 256>>>((const float2*)Wg, (__half2*)wg, n3);
        f32_to_f16_kernel<<<(n3 + 255)/256, 256>>>((const float2*)Wr, (__half2*)wrt, n3);
    }

    // 1) feat (fp16, T-MAJOR) = tanh(BN(tanh(x @ W_fe + b_fe)))
    {
        dim3 grid(HH/128, M1/256);
        gemm_f16<1><<<grid, 512, G_SMEM>>>(xh, wfe, feat, M1, HH, FFP,
                                           b_fe, gamma1, beta1, mean1, var1);
    }
    // 2) Zx = feat @ Wg + bias  (rows inherit t-major order)
    {
        dim3 grid(4*HH/128, M1/256);
        gemm_f16<2><<<grid, 512, G_SMEM>>>(feat, wg, zx, M1, 4*HH, HH,
                                           bias, nullptr, nullptr, nullptr, nullptr);
    }
    // 3) recurrence (fp16, B smem-resident, t-major Zx)
    lstm_persistent<<<128, 512, PSMEM_BYTES>>>(wrt, zx, hseq, pi, pf, po);
    // 4) logits
    logits_kernel<<<M1, 256>>>(hseq, gamma2, beta2, mean2, var2, W_out, out);
}